// round 3
// baseline (speedup 1.0000x reference)
#include <cuda_runtime.h>
#include <math.h>

#define LDIM 384
#define NPIX (384*384)
#define CH 64
#define D1 788
#define D2 210

// ---------------- device scratch (static, no allocation) ----------------
__device__ float  g_a1[D1], g_b1[D1];        // x_1d norm: scale, shift
__device__ float  g_a2[D2], g_b2[D2];        // x_2d norm
__device__ float  g_row[CH*LDIM], g_col[CH*LDIM];
__device__ float  g_row2[CH*LDIM], g_col2[CH*LDIM];
__device__ float  g_s2[CH], g_t2[CH];        // pair2 inorm
__device__ float  g_sP[CH], g_tP[CH];        // pair inorm
__device__ float  g_sC[CH], g_tC[CH];        // per-conv inorm (reused)
__device__ double g_acc[2*CH];               // per-channel {sum, sumsq}
__device__ float  g_bufA[CH*NPIX];
__device__ float  g_bufB[CH*NPIX];
__device__ float  g_bufX[CH*NPIX];
__device__ float  g_wT[10*9*64*64];          // weights re-laid [lk*9+tap][cin][cout]

__device__ __forceinline__ float leaky(float v){ return v > 0.f ? v : 0.01f*v; }

__device__ float blockReduceSum(float v, float* sm){
    int tid = threadIdx.x;
    int lane = tid & 31;
    int wid  = tid >> 5;
    #pragma unroll
    for (int o = 16; o > 0; o >>= 1) v += __shfl_down_sync(0xffffffffu, v, o);
    __syncthreads();                       // protect sm reuse across calls
    if (lane == 0) sm[wid] = v;
    __syncthreads();
    int nw = (blockDim.x + 31) >> 5;
    v = 0.f;
    if (tid < nw) v = sm[tid];
    if (tid < 32) {
        #pragma unroll
        for (int o = 16; o > 0; o >>= 1) v += __shfl_down_sync(0xffffffffu, v, o);
    }
    return v;  // valid at tid 0
}

// ---------------- small kernels ----------------
__global__ void k_reset(){
    if (threadIdx.x < 2*CH) g_acc[threadIdx.x] = 0.0;
}

__global__ void k_stats1d(const float* __restrict__ x){
    __shared__ float sm[32];
    int c = blockIdx.x;
    float s = 0.f, q = 0.f;
    for (int i = threadIdx.x; i < LDIM; i += blockDim.x){
        float v = x[c*LDIM + i]; s += v; q += v*v;
    }
    s = blockReduceSum(s, sm);
    q = blockReduceSum(q, sm);
    if (threadIdx.x == 0){
        float mu = s / LDIM;
        float var = q / LDIM - mu*mu;
        float a = rsqrtf(var + 1e-5f);
        g_a1[c] = a; g_b1[c] = -mu*a;
    }
}

__global__ void k_stats2d(const float* __restrict__ x){
    __shared__ float sm[32];
    int c = blockIdx.x;
    const float* p = x + c*NPIX;
    float s = 0.f, q = 0.f;
    for (int i = threadIdx.x; i < NPIX; i += blockDim.x){
        float v = p[i]; s += v; q += v*v;
    }
    s = blockReduceSum(s, sm);
    q = blockReduceSum(q, sm);
    if (threadIdx.x == 0){
        float mu = s / (float)NPIX;
        float var = q / (float)NPIX - mu*mu;
        float a = rsqrtf(var + 1e-5f);
        g_a2[c] = a; g_b2[c] = -mu*a;
    }
}

__global__ void k_wprep(const float* __restrict__ rw){
    int o = blockIdx.x*blockDim.x + threadIdx.x;
    if (o >= 10*9*64*64) return;
    int co  = o & 63;
    int ci  = (o >> 6) & 63;
    int lt  = o >> 12;           // lk*9 + tap
    int tap = lt % 9;
    int lk  = lt / 9;
    g_wT[o] = rw[((lk*64 + co)*64 + ci)*9 + tap];
}

// row/col = W1a/W1b @ normalized x1  (64 blocks, 384 threads)
__global__ void k_rowcol(const float* __restrict__ x1, const float* __restrict__ W1){
    __shared__ float sa[D1], sb[D1];
    int c = blockIdx.x, i = threadIdx.x;
    for (int d = threadIdx.x; d < D1; d += blockDim.x){ sa[d] = g_a1[d]; sb[d] = g_b1[d]; }
    __syncthreads();
    float r = 0.f, cl = 0.f;
    for (int d = 0; d < D1; d++){
        float v = x1[d*LDIM + i]*sa[d] + sb[d];
        r  += W1[c*(2*D1) + d]      * v;
        cl += W1[c*(2*D1) + D1 + d] * v;
    }
    g_row[c*LDIM + i] = r;
    g_col[c*LDIM + i] = cl;
}

// analytic pair1 inorm stats + build row2/col2  (64 blocks, 384 threads)
__global__ void k_pair1(const float* __restrict__ g1, const float* __restrict__ b1){
    __shared__ float sm[32];
    __shared__ float sS, sT;
    int c = blockIdx.x, t = threadIdx.x;
    float r  = g_row[c*LDIM + t];
    float co = g_col[c*LDIM + t];
    float sr  = blockReduceSum(r, sm);
    float sr2 = blockReduceSum(r*r, sm);
    float sc  = blockReduceSum(co, sm);
    float sc2 = blockReduceSum(co*co, sm);
    if (t == 0){
        float mr = sr / LDIM, mc = sc / LDIM;
        float var = (sr2/LDIM - mr*mr) + (sc2/LDIM - mc*mc);
        float s = g1[c]*rsqrtf(var + 1e-5f);
        sS = s; sT = b1[c] - (mr + mc)*s;
    }
    __syncthreads();
    g_row2[c*LDIM + t] = r*sS + sT;
    g_col2[c*LDIM + t] = co*sS;
}

__global__ void k_finalize(const float* __restrict__ gamma, const float* __restrict__ beta,
                           float* __restrict__ sOut, float* __restrict__ tOut, double invN){
    int c = threadIdx.x;
    double sum = g_acc[2*c], sq = g_acc[2*c+1];
    double mu  = sum*invN;
    double var = sq*invN - mu*mu;
    float s = gamma[c]*rsqrtf((float)var + 1e-5f);
    float t = beta[c] - (float)mu*s;
    sOut[c] = s; tOut[c] = t;
    g_acc[2*c] = 0.0; g_acc[2*c+1] = 0.0;
}

// elementwise: out = leaky(in*s+t) [+ res]
__global__ void k_ew(const float* __restrict__ in, const float* __restrict__ s,
                     const float* __restrict__ t, const float* __restrict__ res,
                     float* __restrict__ out){
    int idx = blockIdx.x*blockDim.x + threadIdx.x;
    int p = idx*4;
    int c = p / NPIX;
    float4 v = *(const float4*)(in + p);
    float ss = s[c], tt = t[c];
    v.x = leaky(v.x*ss + tt);
    v.y = leaky(v.y*ss + tt);
    v.z = leaky(v.z*ss + tt);
    v.w = leaky(v.w*ss + tt);
    if (res){
        float4 rr = *(const float4*)(res + p);
        v.x += rr.x; v.y += rr.y; v.z += rr.z; v.w += rr.w;
    }
    *(float4*)(out + p) = v;
}

// ---------------- pair2 GEMM: out[64][NPIX] = W2 @ norm(x2) ----------------
#define KC 30
__global__ __launch_bounds__(256) void k_pair2(const float* __restrict__ x2,
                                               const float* __restrict__ W2){
    __shared__ float sA[KC*64];
    __shared__ float sB[KC*128];
    __shared__ float rs[64], rq[64];
    int pix0 = blockIdx.x*128;
    int tid = threadIdx.x;
    int tm = tid >> 4, tn = tid & 15;
    float acc[4][8];
    #pragma unroll
    for (int m = 0; m < 4; m++)
        #pragma unroll
        for (int j = 0; j < 8; j++) acc[m][j] = 0.f;

    for (int c0 = 0; c0 < D2; c0 += KC){
        __syncthreads();
        for (int idx = tid; idx < KC*128; idx += 256){
            int k = idx >> 7, n = idx & 127;
            int d = c0 + k;
            sB[idx] = x2[d*NPIX + pix0 + n]*g_a2[d] + g_b2[d];
        }
        for (int idx = tid; idx < KC*64; idx += 256){
            int k = idx >> 6, m = idx & 63;
            sA[idx] = W2[m*D2 + c0 + k];
        }
        __syncthreads();
        #pragma unroll 2
        for (int k = 0; k < KC; k++){
            float4 a = *(const float4*)&sA[k*64 + tm*4];
            float b[8];
            #pragma unroll
            for (int j = 0; j < 8; j++) b[j] = sB[k*128 + tn + j*16];
            #pragma unroll
            for (int j = 0; j < 8; j++){
                acc[0][j] = fmaf(a.x, b[j], acc[0][j]);
                acc[1][j] = fmaf(a.y, b[j], acc[1][j]);
                acc[2][j] = fmaf(a.z, b[j], acc[2][j]);
                acc[3][j] = fmaf(a.w, b[j], acc[3][j]);
            }
        }
    }
    __syncthreads();
    if (tid < 64){ rs[tid] = 0.f; rq[tid] = 0.f; }
    __syncthreads();
    #pragma unroll
    for (int mm = 0; mm < 4; mm++){
        int c = tm*4 + mm;
        float s = 0.f, q = 0.f;
        #pragma unroll
        for (int j = 0; j < 8; j++){
            float v = acc[mm][j];
            g_bufB[c*NPIX + pix0 + tn + j*16] = v;
            s += v; q += v*v;
        }
        atomicAdd(&rs[c], s); atomicAdd(&rq[c], q);
    }
    __syncthreads();
    if (tid < 64){
        atomicAdd(&g_acc[2*tid],   (double)rs[tid]);
        atomicAdd(&g_acc[2*tid+1], (double)rq[tid]);
    }
}

// ---------------- pair combine: bufA = W3a@p1n + W3b@p2n ----------------
__global__ __launch_bounds__(256) void k_combine(const float* __restrict__ W3){
    extern __shared__ float sm[];
    float* sB1 = sm;            // 64*128
    float* sB2 = sm + 8192;     // 64*128
    float* sA  = sm + 16384;    // 128*64
    int pix0 = blockIdx.x*128;
    int i  = pix0 / LDIM;
    int j0 = pix0 - i*LDIM;
    int tid = threadIdx.x;
    int tm = tid >> 4, tn = tid & 15;

    for (int idx = tid; idx < 8192; idx += 256){
        int e = idx >> 7, n = idx & 127;
        sB1[idx] = leaky(g_row2[e*LDIM + i] + g_col2[e*LDIM + j0 + n]);
        sB2[idx] = leaky(g_bufB[e*NPIX + pix0 + n]*g_s2[e] + g_t2[e]);
    }
    for (int idx = tid; idx < 8192; idx += 256){
        int k = idx >> 6, m = idx & 63;
        sA[idx] = W3[m*128 + k];
    }
    __syncthreads();

    float acc[4][8];
    #pragma unroll
    for (int m = 0; m < 4; m++)
        #pragma unroll
        for (int j = 0; j < 8; j++) acc[m][j] = 0.f;

    #pragma unroll 2
    for (int k = 0; k < 64; k++){
        float4 a = *(const float4*)&sA[k*64 + tm*4];
        float b[8];
        #pragma unroll
        for (int j = 0; j < 8; j++) b[j] = sB1[k*128 + tn + j*16];
        #pragma unroll
        for (int j = 0; j < 8; j++){
            acc[0][j] = fmaf(a.x, b[j], acc[0][j]);
            acc[1][j] = fmaf(a.y, b[j], acc[1][j]);
            acc[2][j] = fmaf(a.z, b[j], acc[2][j]);
            acc[3][j] = fmaf(a.w, b[j], acc[3][j]);
        }
    }
    #pragma unroll 2
    for (int k = 0; k < 64; k++){
        float4 a = *(const float4*)&sA[(64+k)*64 + tm*4];
        float b[8];
        #pragma unroll
        for (int j = 0; j < 8; j++) b[j] = sB2[k*128 + tn + j*16];
        #pragma unroll
        for (int j = 0; j < 8; j++){
            acc[0][j] = fmaf(a.x, b[j], acc[0][j]);
            acc[1][j] = fmaf(a.y, b[j], acc[1][j]);
            acc[2][j] = fmaf(a.z, b[j], acc[2][j]);
            acc[3][j] = fmaf(a.w, b[j], acc[3][j]);
        }
    }
    __syncthreads();
    float* rs = sA; float* rq = sA + 64;
    if (tid < 64){ rs[tid] = 0.f; rq[tid] = 0.f; }
    __syncthreads();
    #pragma unroll
    for (int mm = 0; mm < 4; mm++){
        int c = tm*4 + mm;
        float s = 0.f, q = 0.f;
        #pragma unroll
        for (int j = 0; j < 8; j++){
            float v = acc[mm][j];
            g_bufA[c*NPIX + pix0 + tn + j*16] = v;
            s += v; q += v*v;
        }
        atomicAdd(&rs[c], s); atomicAdd(&rq[c], q);
    }
    __syncthreads();
    if (tid < 64){
        atomicAdd(&g_acc[2*tid],   (double)rs[tid]);
        atomicAdd(&g_acc[2*tid+1], (double)rq[tid]);
    }
}

// ---------------- dilated 3x3 conv, implicit GEMM ----------------
// block: 256 threads, output tile 64ch x 128px (one row segment)
#define SIN_STRIDE 136
#define CONV_SMEM ((64*3*SIN_STRIDE + 64*64)*4)
__global__ __launch_bounds__(256) void k_conv(const float* __restrict__ in, int wbase,
                                              const float* __restrict__ bias,
                                              int useTf, int dil,
                                              float* __restrict__ out){
    extern __shared__ float sm[];
    float* sIn = sm;                     // 64 * 3 * 136
    float* sW  = sm + 64*3*SIN_STRIDE;   // 64 * 64 (also reduction scratch)
    int tile = blockIdx.x;
    int ty  = tile / 3;
    int tx0 = (tile - ty*3)*128;
    int tid = threadIdx.x;
    int WIN = 128 + 2*dil;

    for (int idx = tid; idx < 64*3*WIN; idx += 256){
        int c   = idx / (3*WIN);
        int rem = idx - c*3*WIN;
        int r   = rem / WIN;
        int x   = rem - r*WIN;
        int gy  = ty + (r-1)*dil;
        int gx  = tx0 - dil + x;
        float v = 0.f;
        if (gy >= 0 && gy < LDIM && gx >= 0 && gx < LDIM){
            v = in[(c*LDIM + gy)*LDIM + gx];
            if (useTf) v = leaky(v*g_sC[c] + g_tC[c]);
        }
        sIn[(c*3 + r)*SIN_STRIDE + x] = v;
    }

    int tm = tid >> 4, tn = tid & 15;
    float acc[4][8];
    #pragma unroll
    for (int m = 0; m < 4; m++)
        #pragma unroll
        for (int j = 0; j < 8; j++) acc[m][j] = 0.f;

    for (int r = 0; r < 3; r++){
        for (int tp = 0; tp < 3; tp++){
            int tap = r*3 + tp;
            __syncthreads();
            const float* wp = g_wT + (wbase + tap)*4096;
            for (int idx = tid; idx < 4096; idx += 256) sW[idx] = wp[idx];
            __syncthreads();
            int xoff = tn + tp*dil;
            #pragma unroll 4
            for (int k = 0; k < 64; k++){
                float4 a = *(const float4*)&sW[k*64 + tm*4];
                const float* bp = &sIn[(k*3 + r)*SIN_STRIDE + xoff];
                float b[8];
                #pragma unroll
                for (int j = 0; j < 8; j++) b[j] = bp[j*16];
                #pragma unroll
                for (int j = 0; j < 8; j++){
                    acc[0][j] = fmaf(a.x, b[j], acc[0][j]);
                    acc[1][j] = fmaf(a.y, b[j], acc[1][j]);
                    acc[2][j] = fmaf(a.z, b[j], acc[2][j]);
                    acc[3][j] = fmaf(a.w, b[j], acc[3][j]);
                }
            }
        }
    }
    __syncthreads();
    float* rs = sW; float* rq = sW + 64;
    if (tid < 64){ rs[tid] = 0.f; rq[tid] = 0.f; }
    __syncthreads();
    int pbase = ty*LDIM + tx0;
    #pragma unroll
    for (int mm = 0; mm < 4; mm++){
        int c = tm*4 + mm;
        float bb = bias[c];
        float s = 0.f, q = 0.f;
        #pragma unroll
        for (int j = 0; j < 8; j++){
            float v = acc[mm][j] + bb;
            out[c*NPIX + pbase + tn + j*16] = v;
            s += v; q += v*v;
        }
        atomicAdd(&rs[c], s); atomicAdd(&rq[c], q);
    }
    __syncthreads();
    if (tid < 64){
        atomicAdd(&g_acc[2*tid],   (double)rs[tid]);
        atomicAdd(&g_acc[2*tid+1], (double)rq[tid]);
    }
}

// ---------------- host ----------------
extern "C" void kernel_launch(void* const* d_in, const int* in_sizes, int n_in,
                              void* d_out, int out_size){
    const float* x1    = (const float*)d_in[0];
    const float* x2    = (const float*)d_in[1];
    const float* W1    = (const float*)d_in[2];
    const float* g1    = (const float*)d_in[3];
    const float* b1    = (const float*)d_in[4];
    const float* W2    = (const float*)d_in[5];
    const float* g2    = (const float*)d_in[6];
    const float* b2    = (const float*)d_in[7];
    const float* W3    = (const float*)d_in[8];
    const float* g3    = (const float*)d_in[9];
    const float* b3    = (const float*)d_in[10];
    const float* rw    = (const float*)d_in[11];
    const float* rb    = (const float*)d_in[12];
    const float* rg    = (const float*)d_in[13];
    const float* rbeta = (const float*)d_in[14];
    float* out = (float*)d_out;

    float *bufA, *bufB, *bufX, *s2, *t2, *sP, *tP, *sC, *tC;
    cudaGetSymbolAddress((void**)&bufA, g_bufA);
    cudaGetSymbolAddress((void**)&bufB, g_bufB);
    cudaGetSymbolAddress((void**)&bufX, g_bufX);
    cudaGetSymbolAddress((void**)&s2, g_s2);
    cudaGetSymbolAddress((void**)&t2, g_t2);
    cudaGetSymbolAddress((void**)&sP, g_sP);
    cudaGetSymbolAddress((void**)&tP, g_tP);
    cudaGetSymbolAddress((void**)&sC, g_sC);
    cudaGetSymbolAddress((void**)&tC, g_tC);

    cudaFuncSetAttribute(k_conv,    cudaFuncAttributeMaxDynamicSharedMemorySize, CONV_SMEM);
    cudaFuncSetAttribute(k_combine, cudaFuncAttributeMaxDynamicSharedMemorySize, 98304);

    const double invN = 1.0 / (double)NPIX;

    k_reset  <<<1, 128>>>();
    k_stats1d<<<D1, 128>>>(x1);
    k_stats2d<<<D2, 256>>>(x2);
    k_wprep  <<<1440, 256>>>(rw);
    k_rowcol <<<CH, LDIM>>>(x1, W1);
    k_pair1  <<<CH, LDIM>>>(g1, b1);
    k_pair2  <<<1152, 256>>>(x2, W2);
    k_finalize<<<1, 64>>>(g2, b2, s2, t2, invN);
    k_combine<<<1152, 256, 98304>>>(W3);
    k_finalize<<<1, 64>>>(g3, b3, sP, tP, invN);
    k_ew     <<<9216, 256>>>(bufA, sP, tP, nullptr, bufX);

    const int dil[5] = {1, 2, 4, 2, 1};
    for (int l = 0; l < 5; l++){
        int d = dil[l];
        k_conv<<<1152, 256, CONV_SMEM>>>(bufX, (l*2)*9, rb + (l*2)*64, 0, d, bufA);
        k_finalize<<<1, 64>>>(rg + (l*2)*64, rbeta + (l*2)*64, sC, tC, invN);
        k_conv<<<1152, 256, CONV_SMEM>>>(bufA, (l*2+1)*9, rb + (l*2+1)*64, 1, d, bufB);
        k_finalize<<<1, 64>>>(rg + (l*2+1)*64, rbeta + (l*2+1)*64, sC, tC, invN);
        k_ew<<<9216, 256>>>(bufB, sC, tC, bufX, (l == 4) ? out : bufX);
    }
}

// round 10
// speedup vs baseline: 1.1032x; 1.1032x over previous
#include <cuda_runtime.h>
#include <cuda_bf16.h>
#include <math.h>
#include <stdint.h>

#define LDIM 384
#define NPIX (384*384)
#define CH 64
#define D1 788
#define D2 210

// ---------------- device scratch (static, no allocation) ----------------
__device__ float  g_a1[D1], g_b1[D1];
__device__ float  g_a2[D2], g_b2[D2];
__device__ float  g_row[CH*LDIM], g_col[CH*LDIM];
__device__ float  g_row2[CH*LDIM], g_col2[CH*LDIM];
__device__ float  g_s2[CH], g_t2[CH];
__device__ float  g_sP[CH], g_tP[CH];
__device__ float  g_sC[CH], g_tC[CH];
__device__ double g_acc[2*CH];
__device__ float  g_bufA[CH*NPIX];
__device__ float  g_bufB[CH*NPIX];
__device__ float  g_bufX[CH*NPIX];
// bf16 split weights: [conv(10)][r(3)][m(128: 0-63 hi, 64-127 lo)][k(192 = tx*64+cin)]
#define ATILE 24576
__device__ __nv_bfloat16 g_wA[30*ATILE];

__device__ __forceinline__ float leaky(float v){ return v > 0.f ? v : 0.01f*v; }

__device__ float blockReduceSum(float v, float* sm){
    int tid = threadIdx.x;
    int lane = tid & 31;
    int wid  = tid >> 5;
    #pragma unroll
    for (int o = 16; o > 0; o >>= 1) v += __shfl_down_sync(0xffffffffu, v, o);
    __syncthreads();
    if (lane == 0) sm[wid] = v;
    __syncthreads();
    int nw = (blockDim.x + 31) >> 5;
    v = 0.f;
    if (tid < nw) v = sm[tid];
    if (tid < 32) {
        #pragma unroll
        for (int o = 16; o > 0; o >>= 1) v += __shfl_down_sync(0xffffffffu, v, o);
    }
    return v;
}

// ---------------- mma.sync helpers (sm_80-class; valid on compute_103) ----------------
__device__ __forceinline__ uint32_t smem_u32(const void* p){
    uint32_t a;
    asm("{ .reg .u64 t; cvta.to.shared.u64 t, %1; cvt.u32.u64 %0, t; }" : "=r"(a) : "l"(p));
    return a;
}
__device__ __forceinline__ void ldm4(uint32_t r[4], uint32_t addr){
    asm volatile("ldmatrix.sync.aligned.m8n8.x4.shared.b16 {%0,%1,%2,%3}, [%4];"
                 : "=r"(r[0]), "=r"(r[1]), "=r"(r[2]), "=r"(r[3]) : "r"(addr));
}
__device__ __forceinline__ void mma16816(float c[4], const uint32_t a[4], uint32_t b0, uint32_t b1){
    asm volatile("mma.sync.aligned.m16n8k16.row.col.f32.bf16.bf16.f32 "
                 "{%0,%1,%2,%3}, {%4,%5,%6,%7}, {%8,%9}, {%0,%1,%2,%3};"
                 : "+f"(c[0]), "+f"(c[1]), "+f"(c[2]), "+f"(c[3])
                 : "r"(a[0]), "r"(a[1]), "r"(a[2]), "r"(a[3]), "r"(b0), "r"(b1));
}

// ---------------- small kernels ----------------
__global__ void k_reset(){
    if (threadIdx.x < 2*CH) g_acc[threadIdx.x] = 0.0;
}

__global__ void k_stats1d(const float* __restrict__ x){
    __shared__ float sm[32];
    int c = blockIdx.x;
    float s = 0.f, q = 0.f;
    for (int i = threadIdx.x; i < LDIM; i += blockDim.x){
        float v = x[c*LDIM + i]; s += v; q += v*v;
    }
    s = blockReduceSum(s, sm);
    q = blockReduceSum(q, sm);
    if (threadIdx.x == 0){
        float mu = s / LDIM;
        float var = q / LDIM - mu*mu;
        float a = rsqrtf(var + 1e-5f);
        g_a1[c] = a; g_b1[c] = -mu*a;
    }
}

__global__ void k_stats2d(const float* __restrict__ x){
    __shared__ float sm[32];
    int c = blockIdx.x;
    const float* p = x + c*NPIX;
    float s = 0.f, q = 0.f;
    for (int i = threadIdx.x; i < NPIX; i += blockDim.x){
        float v = p[i]; s += v; q += v*v;
    }
    s = blockReduceSum(s, sm);
    q = blockReduceSum(q, sm);
    if (threadIdx.x == 0){
        float mu = s / (float)NPIX;
        float var = q / (float)NPIX - mu*mu;
        float a = rsqrtf(var + 1e-5f);
        g_a2[c] = a; g_b2[c] = -mu*a;
    }
}

// build bf16 hi/lo split weights, linear [lkr][m][k]
__global__ void k_aprep(const float* __restrict__ rw){
    int idx = blockIdx.x*blockDim.x + threadIdx.x;
    if (idx >= 30*128*192) return;
    int lkr = idx / (128*192);
    int rem = idx - lkr*(128*192);
    int m = rem / 192;
    int k = rem - m*192;
    int cout = m & 63, part = m >> 6;
    int cin = k & 63, tx = k >> 6;
    int lk = lkr / 3, r = lkr - lk*3;
    float w = rw[((lk*64 + cout)*64 + cin)*9 + r*3 + tx];
    __nv_bfloat16 hi = __float2bfloat16(w);
    __nv_bfloat16 val = part ? __float2bfloat16(w - __bfloat162float(hi)) : hi;
    g_wA[lkr*ATILE + m*192 + k] = val;
}

__global__ void k_rowcol(const float* __restrict__ x1, const float* __restrict__ W1){
    __shared__ float sa[D1], sb[D1];
    int c = blockIdx.x, i = threadIdx.x;
    for (int d = threadIdx.x; d < D1; d += blockDim.x){ sa[d] = g_a1[d]; sb[d] = g_b1[d]; }
    __syncthreads();
    float r = 0.f, cl = 0.f;
    for (int d = 0; d < D1; d++){
        float v = x1[d*LDIM + i]*sa[d] + sb[d];
        r  += W1[c*(2*D1) + d]      * v;
        cl += W1[c*(2*D1) + D1 + d] * v;
    }
    g_row[c*LDIM + i] = r;
    g_col[c*LDIM + i] = cl;
}

__global__ void k_pair1(const float* __restrict__ g1, const float* __restrict__ b1){
    __shared__ float sm[32];
    __shared__ float sS, sT;
    int c = blockIdx.x, t = threadIdx.x;
    float r  = g_row[c*LDIM + t];
    float co = g_col[c*LDIM + t];
    float sr  = blockReduceSum(r, sm);
    float sr2 = blockReduceSum(r*r, sm);
    float sc  = blockReduceSum(co, sm);
    float sc2 = blockReduceSum(co*co, sm);
    if (t == 0){
        float mr = sr / LDIM, mc = sc / LDIM;
        float var = (sr2/LDIM - mr*mr) + (sc2/LDIM - mc*mc);
        float s = g1[c]*rsqrtf(var + 1e-5f);
        sS = s; sT = b1[c] - (mr + mc)*s;
    }
    __syncthreads();
    g_row2[c*LDIM + t] = r*sS + sT;
    g_col2[c*LDIM + t] = co*sS;
}

__global__ void k_finalize(const float* __restrict__ gamma, const float* __restrict__ beta,
                           float* __restrict__ sOut, float* __restrict__ tOut, double invN){
    int c = threadIdx.x;
    double sum = g_acc[2*c], sq = g_acc[2*c+1];
    double mu  = sum*invN;
    double var = sq*invN - mu*mu;
    float s = gamma[c]*rsqrtf((float)var + 1e-5f);
    float t = beta[c] - (float)mu*s;
    sOut[c] = s; tOut[c] = t;
    g_acc[2*c] = 0.0; g_acc[2*c+1] = 0.0;
}

__global__ void k_ew(const float* __restrict__ in, const float* __restrict__ s,
                     const float* __restrict__ t, const float* __restrict__ res,
                     float* __restrict__ out){
    int idx = blockIdx.x*blockDim.x + threadIdx.x;
    int p = idx*4;
    int c = p / NPIX;
    float4 v = *(const float4*)(in + p);
    float ss = s[c], tt = t[c];
    v.x = leaky(v.x*ss + tt);
    v.y = leaky(v.y*ss + tt);
    v.z = leaky(v.z*ss + tt);
    v.w = leaky(v.w*ss + tt);
    if (res){
        float4 rr = *(const float4*)(res + p);
        v.x += rr.x; v.y += rr.y; v.z += rr.z; v.w += rr.w;
    }
    *(float4*)(out + p) = v;
}

// ---------------- pair2 GEMM (fp32 FFMA; small) ----------------
#define KC 30
__global__ __launch_bounds__(256) void k_pair2(const float* __restrict__ x2,
                                               const float* __restrict__ W2){
    __shared__ float sA[KC*64];
    __shared__ float sB[KC*128];
    __shared__ float rs[64], rq[64];
    int pix0 = blockIdx.x*128;
    int tid = threadIdx.x;
    int tm = tid >> 4, tn = tid & 15;
    float acc[4][8];
    #pragma unroll
    for (int m = 0; m < 4; m++)
        #pragma unroll
        for (int j = 0; j < 8; j++) acc[m][j] = 0.f;

    for (int c0 = 0; c0 < D2; c0 += KC){
        __syncthreads();
        for (int idx = tid; idx < KC*128; idx += 256){
            int k = idx >> 7, n = idx & 127;
            int d = c0 + k;
            sB[idx] = x2[d*NPIX + pix0 + n]*g_a2[d] + g_b2[d];
        }
        for (int idx = tid; idx < KC*64; idx += 256){
            int k = idx >> 6, m = idx & 63;
            sA[idx] = W2[m*D2 + c0 + k];
        }
        __syncthreads();
        #pragma unroll 2
        for (int k = 0; k < KC; k++){
            float4 a = *(const float4*)&sA[k*64 + tm*4];
            float b[8];
            #pragma unroll
            for (int j = 0; j < 8; j++) b[j] = sB[k*128 + tn + j*16];
            #pragma unroll
            for (int j = 0; j < 8; j++){
                acc[0][j] = fmaf(a.x, b[j], acc[0][j]);
                acc[1][j] = fmaf(a.y, b[j], acc[1][j]);
                acc[2][j] = fmaf(a.z, b[j], acc[2][j]);
                acc[3][j] = fmaf(a.w, b[j], acc[3][j]);
            }
        }
    }
    __syncthreads();
    if (tid < 64){ rs[tid] = 0.f; rq[tid] = 0.f; }
    __syncthreads();
    #pragma unroll
    for (int mm = 0; mm < 4; mm++){
        int c = tm*4 + mm;
        float s = 0.f, q = 0.f;
        #pragma unroll
        for (int j = 0; j < 8; j++){
            float v = acc[mm][j];
            g_bufB[c*NPIX + pix0 + tn + j*16] = v;
            s += v; q += v*v;
        }
        atomicAdd(&rs[c], s); atomicAdd(&rq[c], q);
    }
    __syncthreads();
    if (tid < 64){
        atomicAdd(&g_acc[2*tid],   (double)rs[tid]);
        atomicAdd(&g_acc[2*tid+1], (double)rq[tid]);
    }
}

// ---------------- pair combine (fp32 FFMA; small) ----------------
__global__ __launch_bounds__(256) void k_combine(const float* __restrict__ W3){
    extern __shared__ float sm[];
    float* sB1 = sm;
    float* sB2 = sm + 8192;
    float* sA  = sm + 16384;
    int pix0 = blockIdx.x*128;
    int i  = pix0 / LDIM;
    int j0 = pix0 - i*LDIM;
    int tid = threadIdx.x;
    int tm = tid >> 4, tn = tid & 15;

    for (int idx = tid; idx < 8192; idx += 256){
        int e = idx >> 7, n = idx & 127;
        sB1[idx] = leaky(g_row2[e*LDIM + i] + g_col2[e*LDIM + j0 + n]);
        sB2[idx] = leaky(g_bufB[e*NPIX + pix0 + n]*g_s2[e] + g_t2[e]);
    }
    for (int idx = tid; idx < 8192; idx += 256){
        int k = idx >> 6, m = idx & 63;
        sA[idx] = W3[m*128 + k];
    }
    __syncthreads();

    float acc[4][8];
    #pragma unroll
    for (int m = 0; m < 4; m++)
        #pragma unroll
        for (int j = 0; j < 8; j++) acc[m][j] = 0.f;

    #pragma unroll 2
    for (int k = 0; k < 64; k++){
        float4 a = *(const float4*)&sA[k*64 + tm*4];
        float b[8];
        #pragma unroll
        for (int j = 0; j < 8; j++) b[j] = sB1[k*128 + tn + j*16];
        #pragma unroll
        for (int j = 0; j < 8; j++){
            acc[0][j] = fmaf(a.x, b[j], acc[0][j]);
            acc[1][j] = fmaf(a.y, b[j], acc[1][j]);
            acc[2][j] = fmaf(a.z, b[j], acc[2][j]);
            acc[3][j] = fmaf(a.w, b[j], acc[3][j]);
        }
    }
    #pragma unroll 2
    for (int k = 0; k < 64; k++){
        float4 a = *(const float4*)&sA[(64+k)*64 + tm*4];
        float b[8];
        #pragma unroll
        for (int j = 0; j < 8; j++) b[j] = sB2[k*128 + tn + j*16];
        #pragma unroll
        for (int j = 0; j < 8; j++){
            acc[0][j] = fmaf(a.x, b[j], acc[0][j]);
            acc[1][j] = fmaf(a.y, b[j], acc[1][j]);
            acc[2][j] = fmaf(a.z, b[j], acc[2][j]);
            acc[3][j] = fmaf(a.w, b[j], acc[3][j]);
        }
    }
    __syncthreads();
    float* rs = sA; float* rq = sA + 64;
    if (tid < 64){ rs[tid] = 0.f; rq[tid] = 0.f; }
    __syncthreads();
    #pragma unroll
    for (int mm = 0; mm < 4; mm++){
        int c = tm*4 + mm;
        float s = 0.f, q = 0.f;
        #pragma unroll
        for (int j = 0; j < 8; j++){
            float v = acc[mm][j];
            g_bufA[c*NPIX + pix0 + tn + j*16] = v;
            s += v; q += v*v;
        }
        atomicAdd(&rs[c], s); atomicAdd(&rq[c], q);
    }
    __syncthreads();
    if (tid < 64){
        atomicAdd(&g_acc[2*tid],   (double)rs[tid]);
        atomicAdd(&g_acc[2*tid+1], (double)rq[tid]);
    }
}

// ---------------- dilated 3x3 conv via mma.sync bf16-split ----------------
// C[128m][128n]: rows 0-63 = W_hi@(Bh+Bl), 64-127 = W_lo@(Bh+Bl); out = top+bottom.
// smem: A [128][200 bf16] (400B rows), B_hi/B_lo same shape, raw f32 band 64x137.
#define RAWS 137
#define SM_A   0
#define SM_BH  51200
#define SM_BL  102400
#define SM_RAW 153600
#define SM_RED (SM_RAW + 64*RAWS*4)
#define CONV_SMEM (SM_RED + 512)
#define EPI_STRIDE 132

__global__ __launch_bounds__(256)
void k_conv(const float* __restrict__ in, int abase, const float* __restrict__ bias,
            int useTf, int dil, float* __restrict__ out){
    extern __shared__ char smem[];
    float* sRaw = (float*)(smem + SM_RAW);
    uint32_t sbase = smem_u32(smem);
    int tid = threadIdx.x, wid = tid >> 5, lane = tid & 31;
    int tile = blockIdx.x;
    int ty = tile/3, tx0 = (tile - ty*3)*128;
    int WIN = 128 + 2*dil;
    int wm = wid & 3, wn = wid >> 2;

    uint32_t lrow = lane & 15;
    uint32_t lk   = (lane >> 4) << 4;     // 0 or 16 bytes (k 0-7 vs 8-15)
    uint32_t aAddr  = sbase + SM_A  + (wm*32 + lrow)*400 + lk;
    uint32_t bAddrH = sbase + SM_BH + (wn*64 + lrow)*400 + lk;
    uint32_t bAddrL = sbase + SM_BL + (wn*64 + lrow)*400 + lk;

    float acc[2][8][4];
    #pragma unroll
    for (int i = 0; i < 2; i++)
        #pragma unroll
        for (int j = 0; j < 8; j++)
            #pragma unroll
            for (int q = 0; q < 4; q++) acc[i][j][q] = 0.f;

    for (int r = 0; r < 3; r++){
        int gy = ty + (r-1)*dil;
        bool rowOK = (gy >= 0 && gy < LDIM);
        for (int idx = tid; idx < 64*WIN; idx += 256){
            int c = idx / WIN, x = idx - c*WIN;
            int gx = tx0 - dil + x;
            float v = 0.f;
            if (rowOK && gx >= 0 && gx < LDIM){
                v = in[(c*LDIM + gy)*LDIM + gx];
                if (useTf) v = leaky(v*g_sC[c] + g_tC[c]);
            }
            sRaw[c*RAWS + x] = v;
        }
        // stage A (128x192 bf16) into 400B-padded rows
        const float4* asrc = (const float4*)(g_wA + abase + r*ATILE);
        #pragma unroll 4
        for (int j = tid; j < 3072; j += 256){
            int m = j/24, q = j - m*24;
            *(float4*)(smem + SM_A + m*400 + q*16) = asrc[j];
        }
        __syncthreads();
        // build B_hi/B_lo [n][k], k = tx*64+cin, with tap shift baked in
        #pragma unroll 4
        for (int idx = tid; idx < 12288; idx += 256){
            int n  = idx/96, k2 = idx - n*96;
            int tx = k2 >> 5, cin = (k2 & 31) << 1;
            int x = n + tx*dil;
            float v0 = sRaw[cin*RAWS + x];
            float v1 = sRaw[(cin+1)*RAWS + x];
            __nv_bfloat16 h0 = __float2bfloat16(v0);
            __nv_bfloat16 h1 = __float2bfloat16(v1);
            __nv_bfloat162 hh; hh.x = h0; hh.y = h1;
            __nv_bfloat162 ll;
            ll.x = __float2bfloat16(v0 - __bfloat162float(h0));
            ll.y = __float2bfloat16(v1 - __bfloat162float(h1));
            int off = n*400 + (tx*64 + cin)*2;
            *(__nv_bfloat162*)(smem + SM_BH + off) = hh;
            *(__nv_bfloat162*)(smem + SM_BL + off) = ll;
        }
        __syncthreads();

        #pragma unroll 2
        for (int kb = 0; kb < 12; kb++){
            #pragma unroll
            for (int part = 0; part < 2; part++){
                uint32_t ko = kb*32;
                uint32_t ba = (part ? bAddrL : bAddrH) + ko;
                uint32_t a0[4], a1[4], bb[4][4];
                ldm4(a0, aAddr + ko);
                ldm4(a1, aAddr + ko + 16*400);
                #pragma unroll
                for (int q = 0; q < 4; q++) ldm4(bb[q], ba + q*16*400);
                #pragma unroll
                for (int nf = 0; nf < 8; nf++){
                    uint32_t b0 = bb[nf>>1][nf&1];
                    uint32_t b1 = bb[nf>>1][(nf&1)+2];
                    mma16816(acc[0][nf], a0, b0, b1);
                    mma16816(acc[1][nf], a1, b0, b1);
                }
            }
        }
        __syncthreads();
    }

    // fragments -> smem C (reuse B area)
    float* sC = (float*)(smem + SM_BH);
    #pragma unroll
    for (int mf = 0; mf < 2; mf++){
        int r0 = wm*32 + mf*16 + (lane >> 2);
        #pragma unroll
        for (int nf = 0; nf < 8; nf++){
            int c0 = wn*64 + nf*8 + (lane & 3)*2;
            *(float2*)&sC[r0*EPI_STRIDE + c0]       = make_float2(acc[mf][nf][0], acc[mf][nf][1]);
            *(float2*)&sC[(r0+8)*EPI_STRIDE + c0]   = make_float2(acc[mf][nf][2], acc[mf][nf][3]);
        }
    }
    __syncthreads();

    float* rs = (float*)(smem + SM_RED);
    float* rq = rs + 64;
    if (tid < 64){ rs[tid] = 0.f; rq[tid] = 0.f; }
    __syncthreads();
    int pbase = ty*LDIM + tx0;
    for (int i = 0; i < 32; i++){
        int idx = i*256 + tid;
        int row = idx >> 7, col = idx & 127;
        float v = sC[row*EPI_STRIDE + col] + sC[(row+64)*EPI_STRIDE + col] + bias[row];
        out[row*NPIX + pbase + col] = v;
        float s = v, q = v*v;
        #pragma unroll
        for (int o = 16; o > 0; o >>= 1){
            s += __shfl_down_sync(0xffffffffu, s, o);
            q += __shfl_down_sync(0xffffffffu, q, o);
        }
        if (lane == 0){ atomicAdd(&rs[row], s); atomicAdd(&rq[row], q); }
    }
    __syncthreads();
    if (tid < 64){
        atomicAdd(&g_acc[2*tid],   (double)rs[tid]);
        atomicAdd(&g_acc[2*tid+1], (double)rq[tid]);
    }
}

// ---------------- host ----------------
extern "C" void kernel_launch(void* const* d_in, const int* in_sizes, int n_in,
                              void* d_out, int out_size){
    const float* x1    = (const float*)d_in[0];
    const float* x2    = (const float*)d_in[1];
    const float* W1    = (const float*)d_in[2];
    const float* g1    = (const float*)d_in[3];
    const float* b1    = (const float*)d_in[4];
    const float* W2    = (const float*)d_in[5];
    const float* g2    = (const float*)d_in[6];
    const float* b2    = (const float*)d_in[7];
    const float* W3    = (const float*)d_in[8];
    const float* g3    = (const float*)d_in[9];
    const float* b3    = (const float*)d_in[10];
    const float* rw    = (const float*)d_in[11];
    const float* rb    = (const float*)d_in[12];
    const float* rg    = (const float*)d_in[13];
    const float* rbeta = (const float*)d_in[14];
    float* out = (float*)d_out;

    float *bufA, *bufB, *bufX, *s2, *t2, *sP, *tP, *sC, *tC;
    cudaGetSymbolAddress((void**)&bufA, g_bufA);
    cudaGetSymbolAddress((void**)&bufB, g_bufB);
    cudaGetSymbolAddress((void**)&bufX, g_bufX);
    cudaGetSymbolAddress((void**)&s2, g_s2);
    cudaGetSymbolAddress((void**)&t2, g_t2);
    cudaGetSymbolAddress((void**)&sP, g_sP);
    cudaGetSymbolAddress((void**)&tP, g_tP);
    cudaGetSymbolAddress((void**)&sC, g_sC);
    cudaGetSymbolAddress((void**)&tC, g_tC);

    cudaFuncSetAttribute(k_conv,    cudaFuncAttributeMaxDynamicSharedMemorySize, CONV_SMEM);
    cudaFuncSetAttribute(k_combine, cudaFuncAttributeMaxDynamicSharedMemorySize, 98304);

    const double invN = 1.0 / (double)NPIX;

    k_reset  <<<1, 128>>>();
    k_stats1d<<<D1, 128>>>(x1);
    k_stats2d<<<D2, 256>>>(x2);
    k_aprep  <<<2880, 256>>>(rw);
    k_rowcol <<<CH, LDIM>>>(x1, W1);
    k_pair1  <<<CH, LDIM>>>(g1, b1);
    k_pair2  <<<1152, 256>>>(x2, W2);
    k_finalize<<<1, 64>>>(g2, b2, s2, t2, invN);
    k_combine<<<1152, 256, 98304>>>(W3);
    k_finalize<<<1, 64>>>(g3, b3, sP, tP, invN);
    k_ew     <<<9216, 256>>>(bufA, sP, tP, nullptr, bufX);

    const int dil[5] = {1, 2, 4, 2, 1};
    for (int l = 0; l < 5; l++){
        int d = dil[l];
        k_conv<<<1152, 256, CONV_SMEM>>>(bufX, (l*2)*3*ATILE,   rb + (l*2)*64,   0, d, bufA);
        k_finalize<<<1, 64>>>(rg + (l*2)*64, rbeta + (l*2)*64, sC, tC, invN);
        k_conv<<<1152, 256, CONV_SMEM>>>(bufA, (l*2+1)*3*ATILE, rb + (l*2+1)*64, 1, d, bufB);
        k_finalize<<<1, 64>>>(rg + (l*2+1)*64, rbeta + (l*2+1)*64, sC, tC, invN);
        k_ew<<<9216, 256>>>(bufB, sC, tC, bufX, (l == 4) ? out : bufX);
    }
}

// round 11
// speedup vs baseline: 1.9453x; 1.7634x over previous
#include <cuda_runtime.h>
#include <cuda_bf16.h>
#include <math.h>
#include <stdint.h>

#define LDIM 384
#define NPIX (384*384)
#define CH 64
#define D1 788
#define D2 210

// ---------------- device scratch (static, no allocation) ----------------
__device__ float  g_a1[D1], g_b1[D1];
__device__ float  g_a2[D2], g_b2[D2];
__device__ float  g_row[CH*LDIM], g_col[CH*LDIM];
__device__ float  g_row2[CH*LDIM], g_col2[CH*LDIM];
__device__ float  g_s2[CH], g_t2[CH];
__device__ float  g_sP[CH], g_tP[CH];
__device__ float  g_sC[CH], g_tC[CH];
__device__ double g_acc[2*CH];
__device__ float  g_bufA[CH*NPIX];
__device__ float  g_bufB[CH*NPIX];
__device__ float  g_bufX[CH*NPIX];
__device__ float  g_bufY[CH*NPIX];
// bf16 split weights: [conv(10)][r(3)][m(128: 0-63 hi, 64-127 lo)][k(192 = tx*64+cin)]
#define ATILE 24576
__device__ __nv_bfloat16 g_wA[30*ATILE];

__device__ __forceinline__ float leaky(float v){ return v > 0.f ? v : 0.01f*v; }

__device__ float blockReduceSum(float v, float* sm){
    int tid = threadIdx.x;
    int lane = tid & 31;
    int wid  = tid >> 5;
    #pragma unroll
    for (int o = 16; o > 0; o >>= 1) v += __shfl_down_sync(0xffffffffu, v, o);
    __syncthreads();
    if (lane == 0) sm[wid] = v;
    __syncthreads();
    int nw = (blockDim.x + 31) >> 5;
    v = 0.f;
    if (tid < nw) v = sm[tid];
    if (tid < 32) {
        #pragma unroll
        for (int o = 16; o > 0; o >>= 1) v += __shfl_down_sync(0xffffffffu, v, o);
    }
    return v;
}

// ---------------- mma.sync helpers ----------------
__device__ __forceinline__ uint32_t smem_u32(const void* p){
    uint32_t a;
    asm("{ .reg .u64 t; cvta.to.shared.u64 t, %1; cvt.u32.u64 %0, t; }" : "=r"(a) : "l"(p));
    return a;
}
__device__ __forceinline__ void ldm4(uint32_t r[4], uint32_t addr){
    asm volatile("ldmatrix.sync.aligned.m8n8.x4.shared.b16 {%0,%1,%2,%3}, [%4];"
                 : "=r"(r[0]), "=r"(r[1]), "=r"(r[2]), "=r"(r[3]) : "r"(addr));
}
__device__ __forceinline__ void ldm4t(uint32_t r[4], uint32_t addr){
    asm volatile("ldmatrix.sync.aligned.m8n8.x4.trans.shared.b16 {%0,%1,%2,%3}, [%4];"
                 : "=r"(r[0]), "=r"(r[1]), "=r"(r[2]), "=r"(r[3]) : "r"(addr));
}
__device__ __forceinline__ void mma16816(float c[4], const uint32_t a[4], uint32_t b0, uint32_t b1){
    asm volatile("mma.sync.aligned.m16n8k16.row.col.f32.bf16.bf16.f32 "
                 "{%0,%1,%2,%3}, {%4,%5,%6,%7}, {%8,%9}, {%0,%1,%2,%3};"
                 : "+f"(c[0]), "+f"(c[1]), "+f"(c[2]), "+f"(c[3])
                 : "r"(a[0]), "r"(a[1]), "r"(a[2]), "r"(a[3]), "r"(b0), "r"(b1));
}
__device__ __forceinline__ uint32_t cvt_bf16x2(float hi, float lo){
    uint32_t r;
    asm("cvt.rn.bf16x2.f32 %0, %1, %2;" : "=r"(r) : "f"(hi), "f"(lo));
    return r;
}

// ---------------- small kernels ----------------
__global__ void k_reset(){
    if (threadIdx.x < 2*CH) g_acc[threadIdx.x] = 0.0;
}

__global__ void k_stats1d(const float* __restrict__ x){
    __shared__ float sm[32];
    int c = blockIdx.x;
    float s = 0.f, q = 0.f;
    for (int i = threadIdx.x; i < LDIM; i += blockDim.x){
        float v = x[c*LDIM + i]; s += v; q += v*v;
    }
    s = blockReduceSum(s, sm);
    q = blockReduceSum(q, sm);
    if (threadIdx.x == 0){
        float mu = s / LDIM;
        float var = q / LDIM - mu*mu;
        float a = rsqrtf(var + 1e-5f);
        g_a1[c] = a; g_b1[c] = -mu*a;
    }
}

__global__ void k_stats2d(const float* __restrict__ x){
    __shared__ float sm[32];
    int c = blockIdx.x;
    const float* p = x + c*NPIX;
    float s = 0.f, q = 0.f;
    for (int i = threadIdx.x; i < NPIX; i += blockDim.x){
        float v = p[i]; s += v; q += v*v;
    }
    s = blockReduceSum(s, sm);
    q = blockReduceSum(q, sm);
    if (threadIdx.x == 0){
        float mu = s / (float)NPIX;
        float var = q / (float)NPIX - mu*mu;
        float a = rsqrtf(var + 1e-5f);
        g_a2[c] = a; g_b2[c] = -mu*a;
    }
}

// build bf16 hi/lo split weights, linear [lkr][m][k]
__global__ void k_aprep(const float* __restrict__ rw){
    int idx = blockIdx.x*blockDim.x + threadIdx.x;
    if (idx >= 30*128*192) return;
    int lkr = idx / (128*192);
    int rem = idx - lkr*(128*192);
    int m = rem / 192;
    int k = rem - m*192;
    int cout = m & 63, part = m >> 6;
    int cin = k & 63, tx = k >> 6;
    int lk = lkr / 3, r = lkr - lk*3;
    float w = rw[((lk*64 + cout)*64 + cin)*9 + r*3 + tx];
    __nv_bfloat16 hi = __float2bfloat16(w);
    __nv_bfloat16 val = part ? __float2bfloat16(w - __bfloat162float(hi)) : hi;
    g_wA[lkr*ATILE + m*192 + k] = val;
}

__global__ void k_rowcol(const float* __restrict__ x1, const float* __restrict__ W1){
    __shared__ float sa[D1], sb[D1];
    int c = blockIdx.x, i = threadIdx.x;
    for (int d = threadIdx.x; d < D1; d += blockDim.x){ sa[d] = g_a1[d]; sb[d] = g_b1[d]; }
    __syncthreads();
    float r = 0.f, cl = 0.f;
    for (int d = 0; d < D1; d++){
        float v = x1[d*LDIM + i]*sa[d] + sb[d];
        r  += W1[c*(2*D1) + d]      * v;
        cl += W1[c*(2*D1) + D1 + d] * v;
    }
    g_row[c*LDIM + i] = r;
    g_col[c*LDIM + i] = cl;
}

__global__ void k_pair1(const float* __restrict__ g1, const float* __restrict__ b1){
    __shared__ float sm[32];
    __shared__ float sS, sT;
    int c = blockIdx.x, t = threadIdx.x;
    float r  = g_row[c*LDIM + t];
    float co = g_col[c*LDIM + t];
    float sr  = blockReduceSum(r, sm);
    float sr2 = blockReduceSum(r*r, sm);
    float sc  = blockReduceSum(co, sm);
    float sc2 = blockReduceSum(co*co, sm);
    if (t == 0){
        float mr = sr / LDIM, mc = sc / LDIM;
        float var = (sr2/LDIM - mr*mr) + (sc2/LDIM - mc*mc);
        float s = g1[c]*rsqrtf(var + 1e-5f);
        sS = s; sT = b1[c] - (mr + mc)*s;
    }
    __syncthreads();
    g_row2[c*LDIM + t] = r*sS + sT;
    g_col2[c*LDIM + t] = co*sS;
}

__global__ void k_finalize(const float* __restrict__ gamma, const float* __restrict__ beta,
                           float* __restrict__ sOut, float* __restrict__ tOut, double invN){
    int c = threadIdx.x;
    double sum = g_acc[2*c], sq = g_acc[2*c+1];
    double mu  = sum*invN;
    double var = sq*invN - mu*mu;
    float s = gamma[c]*rsqrtf((float)var + 1e-5f);
    float t = beta[c] - (float)mu*s;
    sOut[c] = s; tOut[c] = t;
    g_acc[2*c] = 0.0; g_acc[2*c+1] = 0.0;
}

__global__ void k_ew(const float* __restrict__ in, const float* __restrict__ s,
                     const float* __restrict__ t, const float* __restrict__ res,
                     float* __restrict__ out){
    int idx = blockIdx.x*blockDim.x + threadIdx.x;
    int p = idx*4;
    int c = p / NPIX;
    float4 v = *(const float4*)(in + p);
    float ss = s[c], tt = t[c];
    v.x = leaky(v.x*ss + tt);
    v.y = leaky(v.y*ss + tt);
    v.z = leaky(v.z*ss + tt);
    v.w = leaky(v.w*ss + tt);
    if (res){
        float4 rr = *(const float4*)(res + p);
        v.x += rr.x; v.y += rr.y; v.z += rr.z; v.w += rr.w;
    }
    *(float4*)(out + p) = v;
}

// ---------------- pair2 GEMM (fp32 FFMA; small) ----------------
#define KC 30
__global__ __launch_bounds__(256) void k_pair2(const float* __restrict__ x2,
                                               const float* __restrict__ W2){
    __shared__ float sA[KC*64];
    __shared__ float sB[KC*128];
    __shared__ float rs[64], rq[64];
    int pix0 = blockIdx.x*128;
    int tid = threadIdx.x;
    int tm = tid >> 4, tn = tid & 15;
    float acc[4][8];
    #pragma unroll
    for (int m = 0; m < 4; m++)
        #pragma unroll
        for (int j = 0; j < 8; j++) acc[m][j] = 0.f;

    for (int c0 = 0; c0 < D2; c0 += KC){
        __syncthreads();
        for (int idx = tid; idx < KC*128; idx += 256){
            int k = idx >> 7, n = idx & 127;
            int d = c0 + k;
            sB[idx] = x2[d*NPIX + pix0 + n]*g_a2[d] + g_b2[d];
        }
        for (int idx = tid; idx < KC*64; idx += 256){
            int k = idx >> 6, m = idx & 63;
            sA[idx] = W2[m*D2 + c0 + k];
        }
        __syncthreads();
        #pragma unroll 2
        for (int k = 0; k < KC; k++){
            float4 a = *(const float4*)&sA[k*64 + tm*4];
            float b[8];
            #pragma unroll
            for (int j = 0; j < 8; j++) b[j] = sB[k*128 + tn + j*16];
            #pragma unroll
            for (int j = 0; j < 8; j++){
                acc[0][j] = fmaf(a.x, b[j], acc[0][j]);
                acc[1][j] = fmaf(a.y, b[j], acc[1][j]);
                acc[2][j] = fmaf(a.z, b[j], acc[2][j]);
                acc[3][j] = fmaf(a.w, b[j], acc[3][j]);
            }
        }
    }
    __syncthreads();
    if (tid < 64){ rs[tid] = 0.f; rq[tid] = 0.f; }
    __syncthreads();
    #pragma unroll
    for (int mm = 0; mm < 4; mm++){
        int c = tm*4 + mm;
        float s = 0.f, q = 0.f;
        #pragma unroll
        for (int j = 0; j < 8; j++){
            float v = acc[mm][j];
            g_bufB[c*NPIX + pix0 + tn + j*16] = v;
            s += v; q += v*v;
        }
        atomicAdd(&rs[c], s); atomicAdd(&rq[c], q);
    }
    __syncthreads();
    if (tid < 64){
        atomicAdd(&g_acc[2*tid],   (double)rs[tid]);
        atomicAdd(&g_acc[2*tid+1], (double)rq[tid]);
    }
}

// ---------------- pair combine (fp32 FFMA; small) ----------------
__global__ __launch_bounds__(256) void k_combine(const float* __restrict__ W3){
    extern __shared__ float sm[];
    float* sB1 = sm;
    float* sB2 = sm + 8192;
    float* sA  = sm + 16384;
    int pix0 = blockIdx.x*128;
    int i  = pix0 / LDIM;
    int j0 = pix0 - i*LDIM;
    int tid = threadIdx.x;
    int tm = tid >> 4, tn = tid & 15;

    for (int idx = tid; idx < 8192; idx += 256){
        int e = idx >> 7, n = idx & 127;
        sB1[idx] = leaky(g_row2[e*LDIM + i] + g_col2[e*LDIM + j0 + n]);
        sB2[idx] = leaky(g_bufB[e*NPIX + pix0 + n]*g_s2[e] + g_t2[e]);
    }
    for (int idx = tid; idx < 8192; idx += 256){
        int k = idx >> 6, m = idx & 63;
        sA[idx] = W3[m*128 + k];
    }
    __syncthreads();

    float acc[4][8];
    #pragma unroll
    for (int m = 0; m < 4; m++)
        #pragma unroll
        for (int j = 0; j < 8; j++) acc[m][j] = 0.f;

    #pragma unroll 2
    for (int k = 0; k < 64; k++){
        float4 a = *(const float4*)&sA[k*64 + tm*4];
        float b[8];
        #pragma unroll
        for (int j = 0; j < 8; j++) b[j] = sB1[k*128 + tn + j*16];
        #pragma unroll
        for (int j = 0; j < 8; j++){
            acc[0][j] = fmaf(a.x, b[j], acc[0][j]);
            acc[1][j] = fmaf(a.y, b[j], acc[1][j]);
            acc[2][j] = fmaf(a.z, b[j], acc[2][j]);
            acc[3][j] = fmaf(a.w, b[j], acc[3][j]);
        }
    }
    #pragma unroll 2
    for (int k = 0; k < 64; k++){
        float4 a = *(const float4*)&sA[(64+k)*64 + tm*4];
        float b[8];
        #pragma unroll
        for (int j = 0; j < 8; j++) b[j] = sB2[k*128 + tn + j*16];
        #pragma unroll
        for (int j = 0; j < 8; j++){
            acc[0][j] = fmaf(a.x, b[j], acc[0][j]);
            acc[1][j] = fmaf(a.y, b[j], acc[1][j]);
            acc[2][j] = fmaf(a.z, b[j], acc[2][j]);
            acc[3][j] = fmaf(a.w, b[j], acc[3][j]);
        }
    }
    __syncthreads();
    float* rs = sA; float* rq = sA + 64;
    if (tid < 64){ rs[tid] = 0.f; rq[tid] = 0.f; }
    __syncthreads();
    #pragma unroll
    for (int mm = 0; mm < 4; mm++){
        int c = tm*4 + mm;
        float s = 0.f, q = 0.f;
        #pragma unroll
        for (int j = 0; j < 8; j++){
            float v = acc[mm][j];
            g_bufA[c*NPIX + pix0 + tn + j*16] = v;
            s += v; q += v*v;
        }
        atomicAdd(&rs[c], s); atomicAdd(&rq[c], q);
    }
    __syncthreads();
    if (tid < 64){
        atomicAdd(&g_acc[2*tid],   (double)rs[tid]);
        atomicAdd(&g_acc[2*tid+1], (double)rq[tid]);
    }
}

// ---------------- dilated 3x3 conv via mma.sync bf16-split, 2 CTA/SM ----------------
// Per (r, tx) phase: A panel 128m x 64k (144B rows), B [k][n] 128 rows (hi 0-63, lo 64-127)
// x 272B rows, ldmatrix.trans for B. Accumulate over 9 phases. out = C_top + C_bot.
#define RAWS 137
#define ASTR 144
#define BSTR 272
#define SM_A   0
#define SM_B   18432
#define SM_RAW 53248
#define SM_RED 88320
#define SM_ST  88832
#define CONV_SMEM (88832 + 768)
#define EPI_STRIDE 132

// MODE: 0 = plain load; 1 = leaky(v*s+t); 2 = mode1 + write transformed interior to xnew
template<int DIL, int MODE>
__global__ __launch_bounds__(256, 2)
void k_conv(const float* __restrict__ in, int abase, const float* __restrict__ bias,
            const float* __restrict__ tfs, const float* __restrict__ tft,
            float* __restrict__ xnew, float* __restrict__ out){
    constexpr int WIN = 128 + 2*DIL;
    extern __shared__ char smem[];
    float* sRaw = (float*)(smem + SM_RAW);
    float* sST  = (float*)(smem + SM_ST);       // s[64], t[64], bias[64]
    uint32_t sbase = smem_u32(smem);
    int tid = threadIdx.x, wid = tid >> 5, lane = tid & 31;
    int tile = blockIdx.x;
    int ty = tile/3, tx0 = (tile - ty*3)*128;
    int wm = wid & 3, wn = wid >> 2;

    if (tid < 64){
        if (MODE >= 1){ sST[tid] = tfs[tid]; sST[64 + tid] = tft[tid]; }
        sST[128 + tid] = bias[tid];
    }

    uint32_t aAddr = sbase + SM_A + (wm*32 + (lane & 15))*ASTR + ((lane >> 4) << 4);
    uint32_t bAddr = sbase + SM_B + ((lane & 7) + ((lane >> 3) & 1)*8)*BSTR
                   + (wn*64 + ((lane >> 4) << 3))*2;

    float acc[2][8][4];
    #pragma unroll
    for (int i = 0; i < 2; i++)
        #pragma unroll
        for (int j = 0; j < 8; j++)
            #pragma unroll
            for (int q = 0; q < 4; q++) acc[i][j][q] = 0.f;

    for (int r = 0; r < 3; r++){
        __syncthreads();   // prev mma done with SM_A/B; prev builds done with raw
        int gy = ty + (r-1)*DIL;
        bool rowOK = ((unsigned)gy < LDIM);
        for (int idx = tid; idx < 64*WIN; idx += 256){
            int c = idx / WIN, x = idx - c*WIN;
            int gx = tx0 - DIL + x;
            float v = 0.f;
            if (rowOK && (unsigned)gx < LDIM){
                v = in[(c*LDIM + gy)*LDIM + gx];
                if (MODE >= 1) v = leaky(v*sST[c] + sST[64 + c]);
                if (MODE == 2 && r == 1 && x >= DIL && x < DIL + 128)
                    xnew[c*NPIX + gy*LDIM + gx] = v;
            }
            sRaw[c*RAWS + x] = v;
        }

        const float4* asrc = (const float4*)(g_wA + abase + r*ATILE);
        #pragma unroll 1
        for (int tx = 0; tx < 3; tx++){
            __syncthreads();   // raw visible (tx=0); prev mma done (tx>0)
            // stage A: 128 rows x 64 bf16 (8 float4/row)
            {
                int m = tid >> 1, h0 = (tid & 1)*4;
                const float4* sp = asrc + m*24 + tx*8 + h0;
                float4* dp = (float4*)(smem + SM_A + m*ASTR + h0*16);
                #pragma unroll
                for (int i = 0; i < 4; i++) dp[i] = sp[i];
            }
            // build B [k][n]: row k=cin (hi), 64+cin (lo); contiguous along n
            {
                int cin = tid & 63, q4 = tid >> 6;
                const float* rp = sRaw + cin*RAWS + tx*DIL + q4*32;
                uint32_t hiDst = sbase + SM_B + cin*BSTR + q4*64;
                uint32_t loDst = hiDst + 64*BSTR;
                #pragma unroll
                for (int j = 0; j < 32; j += 4){
                    float v0 = rp[j], v1 = rp[j+1], v2 = rp[j+2], v3 = rp[j+3];
                    uint32_t h01 = cvt_bf16x2(v1, v0);
                    uint32_t h23 = cvt_bf16x2(v3, v2);
                    float f0 = __uint_as_float(h01 << 16);
                    float f1 = __uint_as_float(h01 & 0xffff0000u);
                    float f2 = __uint_as_float(h23 << 16);
                    float f3 = __uint_as_float(h23 & 0xffff0000u);
                    uint32_t l01 = cvt_bf16x2(v1 - f1, v0 - f0);
                    uint32_t l23 = cvt_bf16x2(v3 - f3, v2 - f2);
                    asm volatile("st.shared.v2.b32 [%0], {%1, %2};"
                                 :: "r"(hiDst + j*2), "r"(h01), "r"(h23));
                    asm volatile("st.shared.v2.b32 [%0], {%1, %2};"
                                 :: "r"(loDst + j*2), "r"(l01), "r"(l23));
                }
            }
            __syncthreads();

            #pragma unroll
            for (int kb = 0; kb < 4; kb++){
                uint32_t a0[4], a1[4];
                ldm4(a0, aAddr + kb*32);
                ldm4(a1, aAddr + kb*32 + 16*ASTR);
                #pragma unroll
                for (int part = 0; part < 2; part++){
                    uint32_t bb[4][4];
                    uint32_t bbase = bAddr + (part*64 + kb*16)*BSTR;
                    #pragma unroll
                    for (int q = 0; q < 4; q++) ldm4t(bb[q], bbase + q*32);
                    #pragma unroll
                    for (int nf = 0; nf < 8; nf++){
                        uint32_t b0 = bb[nf >> 1][(nf & 1)*2];
                        uint32_t b1 = bb[nf >> 1][(nf & 1)*2 + 1];
                        mma16816(acc[0][nf], a0, b0, b1);
                        mma16816(acc[1][nf], a1, b0, b1);
                    }
                }
            }
        }
    }
    __syncthreads();   // all warps done with mma before overwriting SM_A/B with C

    float* sC = (float*)smem;
    #pragma unroll
    for (int mf = 0; mf < 2; mf++){
        int r0 = wm*32 + mf*16 + (lane >> 2);
        #pragma unroll
        for (int nf = 0; nf < 8; nf++){
            int c0 = wn*64 + nf*8 + (lane & 3)*2;
            *(float2*)&sC[r0*EPI_STRIDE + c0]     = make_float2(acc[mf][nf][0], acc[mf][nf][1]);
            *(float2*)&sC[(r0+8)*EPI_STRIDE + c0] = make_float2(acc[mf][nf][2], acc[mf][nf][3]);
        }
    }
    __syncthreads();

    float* rs = (float*)(smem + SM_RED);
    float* rq = rs + 64;
    if (tid < 64){ rs[tid] = 0.f; rq[tid] = 0.f; }
    __syncthreads();
    int pbase = ty*LDIM + tx0;
    for (int i = 0; i < 32; i++){
        int idx = i*256 + tid;
        int row = idx >> 7, col = idx & 127;
        float v = sC[row*EPI_STRIDE + col] + sC[(row+64)*EPI_STRIDE + col] + sST[128 + row];
        out[row*NPIX + pbase + col] = v;
        float s = v, q = v*v;
        #pragma unroll
        for (int o = 16; o > 0; o >>= 1){
            s += __shfl_down_sync(0xffffffffu, s, o);
            q += __shfl_down_sync(0xffffffffu, q, o);
        }
        if (lane == 0){ atomicAdd(&rs[row], s); atomicAdd(&rq[row], q); }
    }
    __syncthreads();
    if (tid < 64){
        atomicAdd(&g_acc[2*tid],   (double)rs[tid]);
        atomicAdd(&g_acc[2*tid+1], (double)rq[tid]);
    }
}

// ---------------- host ----------------
extern "C" void kernel_launch(void* const* d_in, const int* in_sizes, int n_in,
                              void* d_out, int out_size){
    const float* x1    = (const float*)d_in[0];
    const float* x2    = (const float*)d_in[1];
    const float* W1    = (const float*)d_in[2];
    const float* g1    = (const float*)d_in[3];
    const float* b1    = (const float*)d_in[4];
    const float* W2    = (const float*)d_in[5];
    const float* g2    = (const float*)d_in[6];
    const float* b2    = (const float*)d_in[7];
    const float* W3    = (const float*)d_in[8];
    const float* g3    = (const float*)d_in[9];
    const float* b3    = (const float*)d_in[10];
    const float* rw    = (const float*)d_in[11];
    const float* rb    = (const float*)d_in[12];
    const float* rg    = (const float*)d_in[13];
    const float* rbeta = (const float*)d_in[14];
    float* out = (float*)d_out;

    float *bufA, *bufB, *bufX, *bufY, *s2, *t2, *sP, *tP, *sC, *tC;
    cudaGetSymbolAddress((void**)&bufA, g_bufA);
    cudaGetSymbolAddress((void**)&bufB, g_bufB);
    cudaGetSymbolAddress((void**)&bufX, g_bufX);
    cudaGetSymbolAddress((void**)&bufY, g_bufY);
    cudaGetSymbolAddress((void**)&s2, g_s2);
    cudaGetSymbolAddress((void**)&t2, g_t2);
    cudaGetSymbolAddress((void**)&sP, g_sP);
    cudaGetSymbolAddress((void**)&tP, g_tP);
    cudaGetSymbolAddress((void**)&sC, g_sC);
    cudaGetSymbolAddress((void**)&tC, g_tC);

    cudaFuncSetAttribute(k_conv<1,0>, cudaFuncAttributeMaxDynamicSharedMemorySize, CONV_SMEM);
    cudaFuncSetAttribute(k_conv<1,1>, cudaFuncAttributeMaxDynamicSharedMemorySize, CONV_SMEM);
    cudaFuncSetAttribute(k_conv<1,2>, cudaFuncAttributeMaxDynamicSharedMemorySize, CONV_SMEM);
    cudaFuncSetAttribute(k_conv<2,0>, cudaFuncAttributeMaxDynamicSharedMemorySize, CONV_SMEM);
    cudaFuncSetAttribute(k_conv<2,1>, cudaFuncAttributeMaxDynamicSharedMemorySize, CONV_SMEM);
    cudaFuncSetAttribute(k_conv<4,0>, cudaFuncAttributeMaxDynamicSharedMemorySize, CONV_SMEM);
    cudaFuncSetAttribute(k_conv<4,1>, cudaFuncAttributeMaxDynamicSharedMemorySize, CONV_SMEM);
    cudaFuncSetAttribute(k_combine,   cudaFuncAttributeMaxDynamicSharedMemorySize, 98304);

    const double invN = 1.0 / (double)NPIX;

    k_reset  <<<1, 128>>>();
    k_stats1d<<<D1, 128>>>(x1);
    k_stats2d<<<D2, 256>>>(x2);
    k_aprep  <<<2880, 256>>>(rw);
    k_rowcol <<<CH, LDIM>>>(x1, W1);
    k_pair1  <<<CH, LDIM>>>(g1, b1);
    k_pair2  <<<1152, 256>>>(x2, W2);
    k_finalize<<<1, 64>>>(g2, b2, s2, t2, invN);
    k_combine<<<1152, 256, 98304>>>(W3);
    k_finalize<<<1, 64>>>(g3, b3, sP, tP, invN);

    // layer 0 (d=1): conv1 fuses the pair transform + writes X0 to bufX
    k_conv<1,2><<<1152, 256, CONV_SMEM>>>(bufA, 0*3*ATILE, rb + 0*64, sP, tP, bufX, bufY);
    k_finalize<<<1, 64>>>(rg + 0*64, rbeta + 0*64, sC, tC, invN);
    k_conv<1,1><<<1152, 256, CONV_SMEM>>>(bufY, 1*3*ATILE, rb + 1*64, sC, tC, nullptr, bufB);
    k_finalize<<<1, 64>>>(rg + 1*64, rbeta + 1*64, sC, tC, invN);
    k_ew<<<9216, 256>>>(bufB, sC, tC, bufX, bufX);

    // layers 1..4
    const int dil[5] = {1, 2, 4, 2, 1};
    for (int l = 1; l < 5; l++){
        int d = dil[l];
        int a1b = (l*2)*3*ATILE, a2b = (l*2+1)*3*ATILE;
        if (d == 1){
            k_conv<1,0><<<1152, 256, CONV_SMEM>>>(bufX, a1b, rb + (l*2)*64, nullptr, nullptr, nullptr, bufY);
            k_finalize<<<1, 64>>>(rg + (l*2)*64, rbeta + (l*2)*64, sC, tC, invN);
            k_conv<1,1><<<1152, 256, CONV_SMEM>>>(bufY, a2b, rb + (l*2+1)*64, sC, tC, nullptr, bufB);
        } else if (d == 2){
            k_conv<2,0><<<1152, 256, CONV_SMEM>>>(bufX, a1b, rb + (l*2)*64, nullptr, nullptr, nullptr, bufY);
            k_finalize<<<1, 64>>>(rg + (l*2)*64, rbeta + (l*2)*64, sC, tC, invN);
            k_conv<2,1><<<1152, 256, CONV_SMEM>>>(bufY, a2b, rb + (l*2+1)*64, sC, tC, nullptr, bufB);
        } else {
            k_conv<4,0><<<1152, 256, CONV_SMEM>>>(bufX, a1b, rb + (l*2)*64, nullptr, nullptr, nullptr, bufY);
            k_finalize<<<1, 64>>>(rg + (l*2)*64, rbeta + (l*2)*64, sC, tC, invN);
            k_conv<4,1><<<1152, 256, CONV_SMEM>>>(bufY, a2b, rb + (l*2+1)*64, sC, tC, nullptr, bufB);
        }
        k_finalize<<<1, 64>>>(rg + (l*2+1)*64, rbeta + (l*2+1)*64, sC, tC, invN);
        k_ew<<<9216, 256>>>(bufB, sC, tC, bufX, (l == 4) ? out : bufX);
    }
}

// round 12
// speedup vs baseline: 1.9617x; 1.0084x over previous
#include <cuda_runtime.h>
#include <cuda_bf16.h>
#include <math.h>
#include <stdint.h>

#define LDIM 384
#define NPIX (384*384)
#define CH 64
#define D1 788
#define D2 210

// ---------------- device scratch (static, no allocation) ----------------
__device__ float  g_a1[D1], g_b1[D1];
__device__ float  g_a2[D2], g_b2[D2];
__device__ float  g_row[CH*LDIM], g_col[CH*LDIM];
__device__ float  g_row2[CH*LDIM], g_col2[CH*LDIM];
__device__ float  g_s2[CH], g_t2[CH];
__device__ float  g_sP[CH], g_tP[CH];
__device__ float  g_sC[CH], g_tC[CH];
__device__ double g_acc[2*CH];
__device__ float  g_bufA[CH*NPIX];
__device__ float  g_bufB[CH*NPIX];
__device__ float  g_bufX[CH*NPIX];
__device__ float  g_bufY[CH*NPIX];
// bf16 split weights: [conv(10)][r(3)][m(128: 0-63 hi, 64-127 lo)][k(192 = tx*64+cin)]
#define ATILE 24576
__device__ __nv_bfloat16 g_wA[30*ATILE];

__device__ __forceinline__ float leaky(float v){ return v > 0.f ? v : 0.01f*v; }

__device__ float blockReduceSum(float v, float* sm){
    int tid = threadIdx.x;
    int lane = tid & 31;
    int wid  = tid >> 5;
    #pragma unroll
    for (int o = 16; o > 0; o >>= 1) v += __shfl_down_sync(0xffffffffu, v, o);
    __syncthreads();
    if (lane == 0) sm[wid] = v;
    __syncthreads();
    int nw = (blockDim.x + 31) >> 5;
    v = 0.f;
    if (tid < nw) v = sm[tid];
    if (tid < 32) {
        #pragma unroll
        for (int o = 16; o > 0; o >>= 1) v += __shfl_down_sync(0xffffffffu, v, o);
    }
    return v;
}

// ---------------- mma.sync helpers ----------------
__device__ __forceinline__ uint32_t smem_u32(const void* p){
    uint32_t a;
    asm("{ .reg .u64 t; cvta.to.shared.u64 t, %1; cvt.u32.u64 %0, t; }" : "=r"(a) : "l"(p));
    return a;
}
__device__ __forceinline__ void ldm4(uint32_t r[4], uint32_t addr){
    asm volatile("ldmatrix.sync.aligned.m8n8.x4.shared.b16 {%0,%1,%2,%3}, [%4];"
                 : "=r"(r[0]), "=r"(r[1]), "=r"(r[2]), "=r"(r[3]) : "r"(addr));
}
__device__ __forceinline__ void mma16816(float c[4], const uint32_t a[4], uint32_t b0, uint32_t b1){
    asm volatile("mma.sync.aligned.m16n8k16.row.col.f32.bf16.bf16.f32 "
                 "{%0,%1,%2,%3}, {%4,%5,%6,%7}, {%8,%9}, {%0,%1,%2,%3};"
                 : "+f"(c[0]), "+f"(c[1]), "+f"(c[2]), "+f"(c[3])
                 : "r"(a[0]), "r"(a[1]), "r"(a[2]), "r"(a[3]), "r"(b0), "r"(b1));
}
__device__ __forceinline__ uint32_t cvt_bf16x2(float hi, float lo){
    uint32_t r;
    asm("cvt.rn.bf16x2.f32 %0, %1, %2;" : "=r"(r) : "f"(hi), "f"(lo));
    return r;
}

// ---------------- small kernels ----------------
__global__ void k_reset(){
    if (threadIdx.x < 2*CH) g_acc[threadIdx.x] = 0.0;
}

__global__ void k_stats1d(const float* __restrict__ x){
    __shared__ float sm[32];
    int c = blockIdx.x;
    float s = 0.f, q = 0.f;
    for (int i = threadIdx.x; i < LDIM; i += blockDim.x){
        float v = x[c*LDIM + i]; s += v; q += v*v;
    }
    s = blockReduceSum(s, sm);
    q = blockReduceSum(q, sm);
    if (threadIdx.x == 0){
        float mu = s / LDIM;
        float var = q / LDIM - mu*mu;
        float a = rsqrtf(var + 1e-5f);
        g_a1[c] = a; g_b1[c] = -mu*a;
    }
}

__global__ void k_stats2d(const float* __restrict__ x){
    __shared__ float sm[32];
    int c = blockIdx.x;
    const float* p = x + c*NPIX;
    float s = 0.f, q = 0.f;
    for (int i = threadIdx.x; i < NPIX; i += blockDim.x){
        float v = p[i]; s += v; q += v*v;
    }
    s = blockReduceSum(s, sm);
    q = blockReduceSum(q, sm);
    if (threadIdx.x == 0){
        float mu = s / (float)NPIX;
        float var = q / (float)NPIX - mu*mu;
        float a = rsqrtf(var + 1e-5f);
        g_a2[c] = a; g_b2[c] = -mu*a;
    }
}

// build bf16 hi/lo split weights, linear [lkr][m][k]
__global__ void k_aprep(const float* __restrict__ rw){
    int idx = blockIdx.x*blockDim.x + threadIdx.x;
    if (idx >= 30*128*192) return;
    int lkr = idx / (128*192);
    int rem = idx - lkr*(128*192);
    int m = rem / 192;
    int k = rem - m*192;
    int cout = m & 63, part = m >> 6;
    int cin = k & 63, tx = k >> 6;
    int lk = lkr / 3, r = lkr - lk*3;
    float w = rw[((lk*64 + cout)*64 + cin)*9 + r*3 + tx];
    __nv_bfloat16 hi = __float2bfloat16(w);
    __nv_bfloat16 val = part ? __float2bfloat16(w - __bfloat162float(hi)) : hi;
    g_wA[lkr*ATILE + m*192 + k] = val;
}

__global__ void k_rowcol(const float* __restrict__ x1, const float* __restrict__ W1){
    __shared__ float sa[D1], sb[D1];
    int c = blockIdx.x, i = threadIdx.x;
    for (int d = threadIdx.x; d < D1; d += blockDim.x){ sa[d] = g_a1[d]; sb[d] = g_b1[d]; }
    __syncthreads();
    float r = 0.f, cl = 0.f;
    for (int d = 0; d < D1; d++){
        float v = x1[d*LDIM + i]*sa[d] + sb[d];
        r  += W1[c*(2*D1) + d]      * v;
        cl += W1[c*(2*D1) + D1 + d] * v;
    }
    g_row[c*LDIM + i] = r;
    g_col[c*LDIM + i] = cl;
}

__global__ void k_pair1(const float* __restrict__ g1, const float* __restrict__ b1){
    __shared__ float sm[32];
    __shared__ float sS, sT;
    int c = blockIdx.x, t = threadIdx.x;
    float r  = g_row[c*LDIM + t];
    float co = g_col[c*LDIM + t];
    float sr  = blockReduceSum(r, sm);
    float sr2 = blockReduceSum(r*r, sm);
    float sc  = blockReduceSum(co, sm);
    float sc2 = blockReduceSum(co*co, sm);
    if (t == 0){
        float mr = sr / LDIM, mc = sc / LDIM;
        float var = (sr2/LDIM - mr*mr) + (sc2/LDIM - mc*mc);
        float s = g1[c]*rsqrtf(var + 1e-5f);
        sS = s; sT = b1[c] - (mr + mc)*s;
    }
    __syncthreads();
    g_row2[c*LDIM + t] = r*sS + sT;
    g_col2[c*LDIM + t] = co*sS;
}

__global__ void k_finalize(const float* __restrict__ gamma, const float* __restrict__ beta,
                           float* __restrict__ sOut, float* __restrict__ tOut, double invN){
    int c = threadIdx.x;
    double sum = g_acc[2*c], sq = g_acc[2*c+1];
    double mu  = sum*invN;
    double var = sq*invN - mu*mu;
    float s = gamma[c]*rsqrtf((float)var + 1e-5f);
    float t = beta[c] - (float)mu*s;
    sOut[c] = s; tOut[c] = t;
    g_acc[2*c] = 0.0; g_acc[2*c+1] = 0.0;
}

__global__ void k_ew(const float* __restrict__ in, const float* __restrict__ s,
                     const float* __restrict__ t, const float* __restrict__ res,
                     float* __restrict__ out){
    int idx = blockIdx.x*blockDim.x + threadIdx.x;
    int p = idx*4;
    int c = p / NPIX;
    float4 v = *(const float4*)(in + p);
    float ss = s[c], tt = t[c];
    v.x = leaky(v.x*ss + tt);
    v.y = leaky(v.y*ss + tt);
    v.z = leaky(v.z*ss + tt);
    v.w = leaky(v.w*ss + tt);
    if (res){
        float4 rr = *(const float4*)(res + p);
        v.x += rr.x; v.y += rr.y; v.z += rr.z; v.w += rr.w;
    }
    *(float4*)(out + p) = v;
}

// ---------------- pair2 GEMM (fp32 FFMA; small) ----------------
#define KC 30
__global__ __launch_bounds__(256) void k_pair2(const float* __restrict__ x2,
                                               const float* __restrict__ W2){
    __shared__ float sA[KC*64];
    __shared__ float sB[KC*128];
    __shared__ float rs[64], rq[64];
    int pix0 = blockIdx.x*128;
    int tid = threadIdx.x;
    int tm = tid >> 4, tn = tid & 15;
    float acc[4][8];
    #pragma unroll
    for (int m = 0; m < 4; m++)
        #pragma unroll
        for (int j = 0; j < 8; j++) acc[m][j] = 0.f;

    for (int c0 = 0; c0 < D2; c0 += KC){
        __syncthreads();
        for (int idx = tid; idx < KC*128; idx += 256){
            int k = idx >> 7, n = idx & 127;
            int d = c0 + k;
            sB[idx] = x2[d*NPIX + pix0 + n]*g_a2[d] + g_b2[d];
        }
        for (int idx = tid; idx < KC*64; idx += 256){
            int k = idx >> 6, m = idx & 63;
            sA[idx] = W2[m*D2 + c0 + k];
        }
        __syncthreads();
        #pragma unroll 2
        for (int k = 0; k < KC; k++){
            float4 a = *(const float4*)&sA[k*64 + tm*4];
            float b[8];
            #pragma unroll
            for (int j = 0; j < 8; j++) b[j] = sB[k*128 + tn + j*16];
            #pragma unroll
            for (int j = 0; j < 8; j++){
                acc[0][j] = fmaf(a.x, b[j], acc[0][j]);
                acc[1][j] = fmaf(a.y, b[j], acc[1][j]);
                acc[2][j] = fmaf(a.z, b[j], acc[2][j]);
                acc[3][j] = fmaf(a.w, b[j], acc[3][j]);
            }
        }
    }
    __syncthreads();
    if (tid < 64){ rs[tid] = 0.f; rq[tid] = 0.f; }
    __syncthreads();
    #pragma unroll
    for (int mm = 0; mm < 4; mm++){
        int c = tm*4 + mm;
        float s = 0.f, q = 0.f;
        #pragma unroll
        for (int j = 0; j < 8; j++){
            float v = acc[mm][j];
            g_bufB[c*NPIX + pix0 + tn + j*16] = v;
            s += v; q += v*v;
        }
        atomicAdd(&rs[c], s); atomicAdd(&rq[c], q);
    }
    __syncthreads();
    if (tid < 64){
        atomicAdd(&g_acc[2*tid],   (double)rs[tid]);
        atomicAdd(&g_acc[2*tid+1], (double)rq[tid]);
    }
}

// ---------------- pair combine (fp32 FFMA; small) ----------------
__global__ __launch_bounds__(256) void k_combine(const float* __restrict__ W3){
    extern __shared__ float sm[];
    float* sB1 = sm;
    float* sB2 = sm + 8192;
    float* sA  = sm + 16384;
    int pix0 = blockIdx.x*128;
    int i  = pix0 / LDIM;
    int j0 = pix0 - i*LDIM;
    int tid = threadIdx.x;
    int tm = tid >> 4, tn = tid & 15;

    for (int idx = tid; idx < 8192; idx += 256){
        int e = idx >> 7, n = idx & 127;
        sB1[idx] = leaky(g_row2[e*LDIM + i] + g_col2[e*LDIM + j0 + n]);
        sB2[idx] = leaky(g_bufB[e*NPIX + pix0 + n]*g_s2[e] + g_t2[e]);
    }
    for (int idx = tid; idx < 8192; idx += 256){
        int k = idx >> 6, m = idx & 63;
        sA[idx] = W3[m*128 + k];
    }
    __syncthreads();

    float acc[4][8];
    #pragma unroll
    for (int m = 0; m < 4; m++)
        #pragma unroll
        for (int j = 0; j < 8; j++) acc[m][j] = 0.f;

    #pragma unroll 2
    for (int k = 0; k < 64; k++){
        float4 a = *(const float4*)&sA[k*64 + tm*4];
        float b[8];
        #pragma unroll
        for (int j = 0; j < 8; j++) b[j] = sB1[k*128 + tn + j*16];
        #pragma unroll
        for (int j = 0; j < 8; j++){
            acc[0][j] = fmaf(a.x, b[j], acc[0][j]);
            acc[1][j] = fmaf(a.y, b[j], acc[1][j]);
            acc[2][j] = fmaf(a.z, b[j], acc[2][j]);
            acc[3][j] = fmaf(a.w, b[j], acc[3][j]);
        }
    }
    #pragma unroll 2
    for (int k = 0; k < 64; k++){
        float4 a = *(const float4*)&sA[(64+k)*64 + tm*4];
        float b[8];
        #pragma unroll
        for (int j = 0; j < 8; j++) b[j] = sB2[k*128 + tn + j*16];
        #pragma unroll
        for (int j = 0; j < 8; j++){
            acc[0][j] = fmaf(a.x, b[j], acc[0][j]);
            acc[1][j] = fmaf(a.y, b[j], acc[1][j]);
            acc[2][j] = fmaf(a.z, b[j], acc[2][j]);
            acc[3][j] = fmaf(a.w, b[j], acc[3][j]);
        }
    }
    __syncthreads();
    float* rs = sA; float* rq = sA + 64;
    if (tid < 64){ rs[tid] = 0.f; rq[tid] = 0.f; }
    __syncthreads();
    #pragma unroll
    for (int mm = 0; mm < 4; mm++){
        int c = tm*4 + mm;
        float s = 0.f, q = 0.f;
        #pragma unroll
        for (int j = 0; j < 8; j++){
            float v = acc[mm][j];
            g_bufA[c*NPIX + pix0 + tn + j*16] = v;
            s += v; q += v*v;
        }
        atomicAdd(&rs[c], s); atomicAdd(&rq[c], q);
    }
    __syncthreads();
    if (tid < 64){
        atomicAdd(&g_acc[2*tid],   (double)rs[tid]);
        atomicAdd(&g_acc[2*tid+1], (double)rq[tid]);
    }
}

// ---------------- dilated 3x3 conv via mma.sync bf16-split, 2 CTA/SM ----------------
// B built ONCE per tap-row r as extended [n][k] tile (WIN rows x 64 cin, hi+lo parts);
// the 3 x-tap shifts are row offsets (tx*dil*BSTR). A = full per-r 128x192 panel.
#define ASTR 400
#define BSTR 144
#define SM_A   0
#define SM_BH  51200
#define SM_BL  70784
#define SM_RED 90368
#define SM_ST  90880
#define CONV_SMEM 91648
#define EPI_STRIDE 132

// MODE: 0 = plain load; 1 = leaky(v*s+t); 2 = mode1 + write transformed interior to xnew
template<int DIL, int MODE>
__global__ __launch_bounds__(256, 2)
void k_conv(const float* __restrict__ in, int abase, const float* __restrict__ bias,
            const float* __restrict__ tfs, const float* __restrict__ tft,
            float* __restrict__ xnew, float* __restrict__ out){
    constexpr int WIN = 128 + 2*DIL;
    extern __shared__ char smem[];
    float* sST = (float*)(smem + SM_ST);       // s[64], t[64], bias[64]
    uint32_t sbase = smem_u32(smem);
    int tid = threadIdx.x, wid = tid >> 5, lane = tid & 31;
    int tile = blockIdx.x;
    int ty = tile/3, tx0 = (tile - ty*3)*128;
    int wm = wid & 3, wn = wid >> 2;

    if (tid < 64){
        if (MODE >= 1){ sST[tid] = tfs[tid]; sST[64 + tid] = tft[tid]; }
        sST[128 + tid] = bias[tid];
    }

    uint32_t aAddr = sbase + SM_A + (wm*32 + (lane & 15))*ASTR + ((lane >> 4) << 4);
    uint32_t bAddr = sbase + SM_BH + (wn*64 + (lane & 15))*BSTR + ((lane >> 4) << 4);

    float acc[2][8][4];
    #pragma unroll
    for (int i = 0; i < 2; i++)
        #pragma unroll
        for (int j = 0; j < 8; j++)
            #pragma unroll
            for (int q = 0; q < 4; q++) acc[i][j][q] = 0.f;

    #pragma unroll 1
    for (int r = 0; r < 3; r++){
        int gy = ty + (r-1)*DIL;
        if ((unsigned)gy >= LDIM) continue;        // zero tap row: skip entirely
        __syncthreads();                           // prev mma done; sST visible
        // stage A: full 128 x 192 bf16 panel for this r (rows 400B)
        {
            int m = tid >> 1;
            const float4* sp = (const float4*)(g_wA + abase + r*ATILE) + m*24 + (tid & 1)*12;
            float4* dp = (float4*)(smem + SM_A + m*ASTR + (tid & 1)*192);
            #pragma unroll
            for (int i = 0; i < 12; i++) dp[i] = sp[i];
        }
        // build extended B: rows n in [0,WIN), cols k=cin; hi at SM_BH, lo at SM_BL
        {
            int nlane = tid & 31;
            int c2 = (tid >> 5)*2;
            #pragma unroll
            for (int ci = 0; ci < 4; ci++, c2 += 16){
                const float* p0 = in + (c2*LDIM + gy)*LDIM;
                const float* p1 = p0 + NPIX;
                float s0, t0, s1, t1;
                if (MODE >= 1){
                    s0 = sST[c2]; t0 = sST[64 + c2];
                    s1 = sST[c2 + 1]; t1 = sST[64 + c2 + 1];
                }
                for (int n = nlane; n < WIN; n += 32){
                    int gx = tx0 - DIL + n;
                    float v0 = 0.f, v1 = 0.f;
                    if ((unsigned)gx < LDIM){
                        v0 = p0[gx]; v1 = p1[gx];
                        if (MODE >= 1){
                            v0 = leaky(v0*s0 + t0);
                            v1 = leaky(v1*s1 + t1);
                        }
                        if (MODE == 2 && r == 1 && n >= DIL && n < DIL + 128){
                            xnew[c2*NPIX + gy*LDIM + gx] = v0;
                            xnew[(c2+1)*NPIX + gy*LDIM + gx] = v1;
                        }
                    }
                    uint32_t hi = cvt_bf16x2(v1, v0);
                    float f0 = __uint_as_float(hi << 16);
                    float f1 = __uint_as_float(hi & 0xffff0000u);
                    uint32_t lo = cvt_bf16x2(v1 - f1, v0 - f0);
                    uint32_t ad = sbase + SM_BH + n*BSTR + c2*2;
                    asm volatile("st.shared.b32 [%0], %1;" :: "r"(ad), "r"(hi));
                    asm volatile("st.shared.b32 [%0], %1;" :: "r"(ad + (SM_BL - SM_BH)), "r"(lo));
                }
            }
        }
        __syncthreads();

        #pragma unroll 1
        for (int tx = 0; tx < 3; tx++){
            uint32_t aOff = tx*128;
            uint32_t bOff = tx*DIL*BSTR;
            #pragma unroll
            for (int kb = 0; kb < 4; kb++){
                uint32_t a0[4], a1[4];
                ldm4(a0, aAddr + aOff + kb*32);
                ldm4(a1, aAddr + aOff + kb*32 + 16*ASTR);
                #pragma unroll
                for (int part = 0; part < 2; part++){
                    uint32_t bb[4][4];
                    uint32_t bb0 = bAddr + bOff + kb*32 + part*(SM_BL - SM_BH);
                    #pragma unroll
                    for (int q = 0; q < 4; q++) ldm4(bb[q], bb0 + q*16*BSTR);
                    #pragma unroll
                    for (int nf = 0; nf < 8; nf++){
                        uint32_t b0 = bb[nf >> 1][nf & 1];
                        uint32_t b1 = bb[nf >> 1][(nf & 1) + 2];
                        mma16816(acc[0][nf], a0, b0, b1);
                        mma16816(acc[1][nf], a1, b0, b1);
                    }
                }
            }
        }
    }
    __syncthreads();   // all mma done before overwriting smem with C

    float* sC = (float*)smem;
    #pragma unroll
    for (int mf = 0; mf < 2; mf++){
        int r0 = wm*32 + mf*16 + (lane >> 2);
        #pragma unroll
        for (int nf = 0; nf < 8; nf++){
            int c0 = wn*64 + nf*8 + (lane & 3)*2;
            *(float2*)&sC[r0*EPI_STRIDE + c0]     = make_float2(acc[mf][nf][0], acc[mf][nf][1]);
            *(float2*)&sC[(r0+8)*EPI_STRIDE + c0] = make_float2(acc[mf][nf][2], acc[mf][nf][3]);
        }
    }
    __syncthreads();

    float* rs = (float*)(smem + SM_RED);
    float* rq = rs + 64;
    if (tid < 64){ rs[tid] = 0.f; rq[tid] = 0.f; }
    __syncthreads();
    int pbase = ty*LDIM + tx0;
    for (int i = 0; i < 32; i++){
        int idx = i*256 + tid;
        int row = idx >> 7, col = idx & 127;
        float v = sC[row*EPI_STRIDE + col] + sC[(row+64)*EPI_STRIDE + col] + sST[128 + row];
        out[row*NPIX + pbase + col] = v;
        float s = v, q = v*v;
        #pragma unroll
        for (int o = 16; o > 0; o >>= 1){
            s += __shfl_down_sync(0xffffffffu, s, o);
            q += __shfl_down_sync(0xffffffffu, q, o);
        }
        if (lane == 0){ atomicAdd(&rs[row], s); atomicAdd(&rq[row], q); }
    }
    __syncthreads();
    if (tid < 64){
        atomicAdd(&g_acc[2*tid],   (double)rs[tid]);
        atomicAdd(&g_acc[2*tid+1], (double)rq[tid]);
    }
}

// ---------------- host ----------------
extern "C" void kernel_launch(void* const* d_in, const int* in_sizes, int n_in,
                              void* d_out, int out_size){
    const float* x1    = (const float*)d_in[0];
    const float* x2    = (const float*)d_in[1];
    const float* W1    = (const float*)d_in[2];
    const float* g1    = (const float*)d_in[3];
    const float* b1    = (const float*)d_in[4];
    const float* W2    = (const float*)d_in[5];
    const float* g2    = (const float*)d_in[6];
    const float* b2    = (const float*)d_in[7];
    const float* W3    = (const float*)d_in[8];
    const float* g3    = (const float*)d_in[9];
    const float* b3    = (const float*)d_in[10];
    const float* rw    = (const float*)d_in[11];
    const float* rb    = (const float*)d_in[12];
    const float* rg    = (const float*)d_in[13];
    const float* rbeta = (const float*)d_in[14];
    float* out = (float*)d_out;

    float *bufA, *bufB, *bufX, *bufY, *s2, *t2, *sP, *tP, *sC, *tC;
    cudaGetSymbolAddress((void**)&bufA, g_bufA);
    cudaGetSymbolAddress((void**)&bufB, g_bufB);
    cudaGetSymbolAddress((void**)&bufX, g_bufX);
    cudaGetSymbolAddress((void**)&bufY, g_bufY);
    cudaGetSymbolAddress((void**)&s2, g_s2);
    cudaGetSymbolAddress((void**)&t2, g_t2);
    cudaGetSymbolAddress((void**)&sP, g_sP);
    cudaGetSymbolAddress((void**)&tP, g_tP);
    cudaGetSymbolAddress((void**)&sC, g_sC);
    cudaGetSymbolAddress((void**)&tC, g_tC);

    cudaFuncSetAttribute(k_conv<1,0>, cudaFuncAttributeMaxDynamicSharedMemorySize, CONV_SMEM);
    cudaFuncSetAttribute(k_conv<1,1>, cudaFuncAttributeMaxDynamicSharedMemorySize, CONV_SMEM);
    cudaFuncSetAttribute(k_conv<1,2>, cudaFuncAttributeMaxDynamicSharedMemorySize, CONV_SMEM);
    cudaFuncSetAttribute(k_conv<2,0>, cudaFuncAttributeMaxDynamicSharedMemorySize, CONV_SMEM);
    cudaFuncSetAttribute(k_conv<2,1>, cudaFuncAttributeMaxDynamicSharedMemorySize, CONV_SMEM);
    cudaFuncSetAttribute(k_conv<4,0>, cudaFuncAttributeMaxDynamicSharedMemorySize, CONV_SMEM);
    cudaFuncSetAttribute(k_conv<4,1>, cudaFuncAttributeMaxDynamicSharedMemorySize, CONV_SMEM);
    cudaFuncSetAttribute(k_combine,   cudaFuncAttributeMaxDynamicSharedMemorySize, 98304);

    const double invN = 1.0 / (double)NPIX;

    k_reset  <<<1, 128>>>();
    k_stats1d<<<D1, 128>>>(x1);
    k_stats2d<<<D2, 256>>>(x2);
    k_aprep  <<<2880, 256>>>(rw);
    k_rowcol <<<CH, LDIM>>>(x1, W1);
    k_pair1  <<<CH, LDIM>>>(g1, b1);
    k_pair2  <<<1152, 256>>>(x2, W2);
    k_finalize<<<1, 64>>>(g2, b2, s2, t2, invN);
    k_combine<<<1152, 256, 98304>>>(W3);
    k_finalize<<<1, 64>>>(g3, b3, sP, tP, invN);

    // layer 0 (d=1): conv1 fuses the pair transform + writes X0 to bufX
    k_conv<1,2><<<1152, 256, CONV_SMEM>>>(bufA, 0*3*ATILE, rb + 0*64, sP, tP, bufX, bufY);
    k_finalize<<<1, 64>>>(rg + 0*64, rbeta + 0*64, sC, tC, invN);
    k_conv<1,1><<<1152, 256, CONV_SMEM>>>(bufY, 1*3*ATILE, rb + 1*64, sC, tC, nullptr, bufB);
    k_finalize<<<1, 64>>>(rg + 1*64, rbeta + 1*64, sC, tC, invN);
    k_ew<<<9216, 256>>>(bufB, sC, tC, bufX, bufX);

    // layers 1..4
    const int dil[5] = {1, 2, 4, 2, 1};
    for (int l = 1; l < 5; l++){
        int d = dil[l];
        int a1b = (l*2)*3*ATILE, a2b = (l*2+1)*3*ATILE;
        if (d == 1){
            k_conv<1,0><<<1152, 256, CONV_SMEM>>>(bufX, a1b, rb + (l*2)*64, nullptr, nullptr, nullptr, bufY);
            k_finalize<<<1, 64>>>(rg + (l*2)*64, rbeta + (l*2)*64, sC, tC, invN);
            k_conv<1,1><<<1152, 256, CONV_SMEM>>>(bufY, a2b, rb + (l*2+1)*64, sC, tC, nullptr, bufB);
        } else if (d == 2){
            k_conv<2,0><<<1152, 256, CONV_SMEM>>>(bufX, a1b, rb + (l*2)*64, nullptr, nullptr, nullptr, bufY);
            k_finalize<<<1, 64>>>(rg + (l*2)*64, rbeta + (l*2)*64, sC, tC, invN);
            k_conv<2,1><<<1152, 256, CONV_SMEM>>>(bufY, a2b, rb + (l*2+1)*64, sC, tC, nullptr, bufB);
        } else {
            k_conv<4,0><<<1152, 256, CONV_SMEM>>>(bufX, a1b, rb + (l*2)*64, nullptr, nullptr, nullptr, bufY);
            k_finalize<<<1, 64>>>(rg + (l*2)*64, rbeta + (l*2)*64, sC, tC, invN);
            k_conv<4,1><<<1152, 256, CONV_SMEM>>>(bufY, a2b, rb + (l*2+1)*64, sC, tC, nullptr, bufB);
        }
        k_finalize<<<1, 64>>>(rg + (l*2+1)*64, rbeta + (l*2+1)*64, sC, tC, invN);
        k_ew<<<9216, 256>>>(bufB, sC, tC, bufX, (l == 4) ? out : bufX);
    }
}

// round 14
// speedup vs baseline: 1.9882x; 1.0135x over previous
#include <cuda_runtime.h>
#include <cuda_bf16.h>
#include <math.h>
#include <stdint.h>

#define LDIM 384
#define NPIX (384*384)
#define CH 64
#define D1 788
#define D2 210

// ---------------- device scratch (static, no allocation) ----------------
__device__ float  g_a1[D1], g_b1[D1];
__device__ float  g_a2[D2], g_b2[D2];
__device__ float  g_row[CH*LDIM], g_col[CH*LDIM];
__device__ float  g_row2[CH*LDIM], g_col2[CH*LDIM];
__device__ float  g_s2[CH], g_t2[CH];
__device__ float  g_sP[CH], g_tP[CH];
__device__ float  g_sC[CH], g_tC[CH];
__device__ double g_acc[2*CH];
__device__ float  g_bufA[CH*NPIX];
__device__ float  g_bufB[CH*NPIX];
__device__ float  g_bufX[CH*NPIX];
__device__ float  g_bufY[CH*NPIX];
__device__ float  g_bufZ[CH*NPIX];
// bf16 split weights: [conv(10)][r(3)][m(128: 0-63 hi, 64-127 lo)][k(192 = tx*64+cin)]
#define ATILE 24576
__device__ __nv_bfloat16 g_wA[30*ATILE];
// pair2 weights: [chunk(2)][m(128)][kl(112)]; combine: [m(128)][k(128)]
__device__ __nv_bfloat16 g_wP2[2*128*112];
__device__ __nv_bfloat16 g_wP3[128*128];

__device__ __forceinline__ float leaky(float v){ return v > 0.f ? v : 0.01f*v; }

__device__ float blockReduceSum(float v, float* sm){
    int tid = threadIdx.x;
    int lane = tid & 31;
    int wid  = tid >> 5;
    #pragma unroll
    for (int o = 16; o > 0; o >>= 1) v += __shfl_down_sync(0xffffffffu, v, o);
    __syncthreads();
    if (lane == 0) sm[wid] = v;
    __syncthreads();
    int nw = (blockDim.x + 31) >> 5;
    v = 0.f;
    if (tid < nw) v = sm[tid];
    if (tid < 32) {
        #pragma unroll
        for (int o = 16; o > 0; o >>= 1) v += __shfl_down_sync(0xffffffffu, v, o);
    }
    return v;
}

// ---------------- mma.sync helpers ----------------
__device__ __forceinline__ uint32_t smem_u32(const void* p){
    uint32_t a;
    asm("{ .reg .u64 t; cvta.to.shared.u64 t, %1; cvt.u32.u64 %0, t; }" : "=r"(a) : "l"(p));
    return a;
}
__device__ __forceinline__ void ldm4(uint32_t r[4], uint32_t addr){
    asm volatile("ldmatrix.sync.aligned.m8n8.x4.shared.b16 {%0,%1,%2,%3}, [%4];"
                 : "=r"(r[0]), "=r"(r[1]), "=r"(r[2]), "=r"(r[3]) : "r"(addr));
}
__device__ __forceinline__ void mma16816(float c[4], const uint32_t a[4], uint32_t b0, uint32_t b1){
    asm volatile("mma.sync.aligned.m16n8k16.row.col.f32.bf16.bf16.f32 "
                 "{%0,%1,%2,%3}, {%4,%5,%6,%7}, {%8,%9}, {%0,%1,%2,%3};"
                 : "+f"(c[0]), "+f"(c[1]), "+f"(c[2]), "+f"(c[3])
                 : "r"(a[0]), "r"(a[1]), "r"(a[2]), "r"(a[3]), "r"(b0), "r"(b1));
}
__device__ __forceinline__ uint32_t cvt_bf16x2(float hi, float lo){
    uint32_t r;
    asm("cvt.rn.bf16x2.f32 %0, %1, %2;" : "=r"(r) : "f"(hi), "f"(lo));
    return r;
}

// ---------------- small kernels ----------------
__global__ void k_reset(){
    if (threadIdx.x < 2*CH) g_acc[threadIdx.x] = 0.0;
}

__global__ void k_stats1d(const float* __restrict__ x){
    __shared__ float sm[32];
    int c = blockIdx.x;
    float s = 0.f, q = 0.f;
    for (int i = threadIdx.x; i < LDIM; i += blockDim.x){
        float v = x[c*LDIM + i]; s += v; q += v*v;
    }
    s = blockReduceSum(s, sm);
    q = blockReduceSum(q, sm);
    if (threadIdx.x == 0){
        float mu = s / LDIM;
        float var = q / LDIM - mu*mu;
        float a = rsqrtf(var + 1e-5f);
        g_a1[c] = a; g_b1[c] = -mu*a;
    }
}

__global__ void k_stats2d(const float* __restrict__ x){
    __shared__ float sm[32];
    int c = blockIdx.x;
    const float* p = x + c*NPIX;
    float s = 0.f, q = 0.f;
    for (int i = threadIdx.x; i < NPIX; i += blockDim.x){
        float v = p[i]; s += v; q += v*v;
    }
    s = blockReduceSum(s, sm);
    q = blockReduceSum(q, sm);
    if (threadIdx.x == 0){
        float mu = s / (float)NPIX;
        float var = q / (float)NPIX - mu*mu;
        float a = rsqrtf(var + 1e-5f);
        g_a2[c] = a; g_b2[c] = -mu*a;
    }
}

// build bf16 hi/lo split conv weights, linear [lkr][m][k]
__global__ void k_aprep(const float* __restrict__ rw){
    int idx = blockIdx.x*blockDim.x + threadIdx.x;
    if (idx >= 30*128*192) return;
    int lkr = idx / (128*192);
    int rem = idx - lkr*(128*192);
    int m = rem / 192;
    int k = rem - m*192;
    int cout = m & 63, part = m >> 6;
    int cin = k & 63, tx = k >> 6;
    int lk = lkr / 3, r = lkr - lk*3;
    float w = rw[((lk*64 + cout)*64 + cin)*9 + r*3 + tx];
    __nv_bfloat16 hi = __float2bfloat16(w);
    __nv_bfloat16 val = part ? __float2bfloat16(w - __bfloat162float(hi)) : hi;
    g_wA[lkr*ATILE + m*192 + k] = val;
}

// pair2 weights: [chunk][m][112]
__global__ void k_aprep2(const float* __restrict__ W2){
    int idx = blockIdx.x*blockDim.x + threadIdx.x;
    if (idx >= 2*128*112) return;
    int ch = idx / (128*112);
    int rem = idx - ch*(128*112);
    int m = rem / 112;
    int kl = rem - m*112;
    int cout = m & 63, part = m >> 6;
    int k = ch*112 + kl;
    float w = (k < D2) ? W2[cout*D2 + k] : 0.f;
    __nv_bfloat16 hi = __float2bfloat16(w);
    __nv_bfloat16 val = part ? __float2bfloat16(w - __bfloat162float(hi)) : hi;
    g_wP2[idx] = val;
}

// combine weights: [m][128]  (W3 row already [W3a|W3b])
__global__ void k_aprep3(const float* __restrict__ W3){
    int idx = blockIdx.x*blockDim.x + threadIdx.x;
    if (idx >= 128*128) return;
    int m = idx >> 7, k = idx & 127;
    int cout = m & 63, part = m >> 6;
    float w = W3[cout*128 + k];
    __nv_bfloat16 hi = __float2bfloat16(w);
    __nv_bfloat16 val = part ? __float2bfloat16(w - __bfloat162float(hi)) : hi;
    g_wP3[idx] = val;
}

__global__ void k_rowcol(const float* __restrict__ x1, const float* __restrict__ W1){
    __shared__ float sa[D1], sb[D1];
    int c = blockIdx.x, i = threadIdx.x;
    for (int d = threadIdx.x; d < D1; d += blockDim.x){ sa[d] = g_a1[d]; sb[d] = g_b1[d]; }
    __syncthreads();
    float r = 0.f, cl = 0.f;
    for (int d = 0; d < D1; d++){
        float v = x1[d*LDIM + i]*sa[d] + sb[d];
        r  += W1[c*(2*D1) + d]      * v;
        cl += W1[c*(2*D1) + D1 + d] * v;
    }
    g_row[c*LDIM + i] = r;
    g_col[c*LDIM + i] = cl;
}

__global__ void k_pair1(const float* __restrict__ g1, const float* __restrict__ b1){
    __shared__ float sm[32];
    __shared__ float sS, sT;
    int c = blockIdx.x, t = threadIdx.x;
    float r  = g_row[c*LDIM + t];
    float co = g_col[c*LDIM + t];
    float sr  = blockReduceSum(r, sm);
    float sr2 = blockReduceSum(r*r, sm);
    float sc  = blockReduceSum(co, sm);
    float sc2 = blockReduceSum(co*co, sm);
    if (t == 0){
        float mr = sr / LDIM, mc = sc / LDIM;
        float var = (sr2/LDIM - mr*mr) + (sc2/LDIM - mc*mc);
        float s = g1[c]*rsqrtf(var + 1e-5f);
        sS = s; sT = b1[c] - (mr + mc)*s;
    }
    __syncthreads();
    g_row2[c*LDIM + t] = r*sS + sT;
    g_col2[c*LDIM + t] = co*sS;
}

__global__ void k_finalize(const float* __restrict__ gamma, const float* __restrict__ beta,
                           float* __restrict__ sOut, float* __restrict__ tOut, double invN){
    int c = threadIdx.x;
    double sum = g_acc[2*c], sq = g_acc[2*c+1];
    double mu  = sum*invN;
    double var = sq*invN - mu*mu;
    float s = gamma[c]*rsqrtf((float)var + 1e-5f);
    float t = beta[c] - (float)mu*s;
    sOut[c] = s; tOut[c] = t;
    g_acc[2*c] = 0.0; g_acc[2*c+1] = 0.0;
}

__global__ void k_ew(const float* __restrict__ in, const float* __restrict__ s,
                     const float* __restrict__ t, const float* __restrict__ res,
                     float* __restrict__ out){
    int idx = blockIdx.x*blockDim.x + threadIdx.x;
    int p = idx*4;
    int c = p / NPIX;
    float4 v = *(const float4*)(in + p);
    float ss = s[c], tt = t[c];
    v.x = leaky(v.x*ss + tt);
    v.y = leaky(v.y*ss + tt);
    v.z = leaky(v.z*ss + tt);
    v.w = leaky(v.w*ss + tt);
    if (res){
        float4 rr = *(const float4*)(res + p);
        v.x += rr.x; v.y += rr.y; v.z += rr.z; v.w += rr.w;
    }
    *(float4*)(out + p) = v;
}

// ---------------- unified mma GEMM for pair2 / combine ----------------
// SRC 0: out[64][NPIX] = W2 @ norm(x2), K=210 (2 chunks of 112)
// SRC 1: out = W3a@leaky(pair1) + W3b@leaky(pair2n), K=128 (1 chunk)
#define GSTR 272
#define SMG_A   0
#define SMG_BH  34816
#define SMG_BL  69632
#define SMG_RED 104448
#define SMG_T   104960
#define GEMM_SMEM 105984
#define GEPI 132

template<int SRC>
__global__ __launch_bounds__(256, 2)
void k_gemm(const float* __restrict__ src0, float* __restrict__ outb){
    extern __shared__ char smem[];
    float* sT = (float*)(smem + SMG_T);
    uint32_t sbase = smem_u32(smem);
    int tid = threadIdx.x, wid = tid >> 5, lane = tid & 31;
    int pix0 = blockIdx.x*128;
    int i0 = pix0 / LDIM, j0 = pix0 - i0*LDIM;
    int wm = wid & 3, wn = wid >> 2;
    uint32_t aAddr = sbase + SMG_A + (wm*32 + (lane & 15))*GSTR + ((lane >> 4) << 4);
    uint32_t bAddr = sbase + SMG_BH + (wn*64 + (lane & 15))*GSTR + ((lane >> 4) << 4);

    float acc[2][8][4];
    #pragma unroll
    for (int i = 0; i < 2; i++)
        #pragma unroll
        for (int j = 0; j < 8; j++)
            #pragma unroll
            for (int q = 0; q < 4; q++) acc[i][j][q] = 0.f;

    constexpr int NCH = SRC ? 1 : 2;
    constexpr int KB  = SRC ? 8 : 7;
    #pragma unroll 1
    for (int ch = 0; ch < NCH; ch++){
        __syncthreads();
        if (SRC == 0){
            if (tid < 112){
                int k = ch*112 + tid;
                bool ok = (k < D2);
                sT[tid]       = ok ? g_a2[k] : 0.f;
                sT[128 + tid] = ok ? g_b2[k] : 0.f;
            }
        } else {
            if (tid < 64){
                sT[tid]        = g_s2[tid];
                sT[64 + tid]   = g_t2[tid];
                sT[128 + tid]  = g_row2[tid*LDIM + i0];
            }
        }
        // stage A panel
        {
            constexpr int F4 = SRC ? 16 : 14;
            const __nv_bfloat16* wb = SRC ? g_wP3 : (g_wP2 + ch*128*112);
            int m = tid >> 1, h = tid & 1;
            const float4* sp = (const float4*)wb + m*F4 + h*(F4/2);
            float4* dp = (float4*)(smem + SMG_A + m*GSTR + h*(F4/2)*16);
            #pragma unroll
            for (int q = 0; q < F4/2; q++) dp[q] = sp[q];
        }
        __syncthreads();
        // build B [n][k] hi/lo
        {
            constexpr int PK = SRC ? 8 : 7;  // kl-pairs per warp
            #pragma unroll 1
            for (int p = 0; p < PK; p++){
                int kl0 = wid*2*PK + p*2;
                float v0[4], v1[4];
                if (SRC == 0){
                    int kg = ch*112 + kl0;
                    const float* q0 = src0 + (size_t)kg*NPIX + pix0;
                    const float* q1 = q0 + NPIX;
                    bool ok0 = (kg < D2), ok1 = (kg + 1 < D2);
                    float a0 = sT[kl0], b0v = sT[128 + kl0];
                    float a1 = sT[kl0+1], b1v = sT[128 + kl0 + 1];
                    #pragma unroll
                    for (int q = 0; q < 4; q++){
                        int n = lane + q*32;
                        v0[q] = ok0 ? q0[n]*a0 + b0v : 0.f;
                        v1[q] = ok1 ? q1[n]*a1 + b1v : 0.f;
                    }
                } else if (kl0 < 64){
                    float r0 = sT[128 + kl0], r1 = sT[128 + kl0 + 1];
                    const float* c0p = g_col2 + kl0*LDIM + j0;
                    const float* c1p = c0p + LDIM;
                    #pragma unroll
                    for (int q = 0; q < 4; q++){
                        int n = lane + q*32;
                        v0[q] = leaky(r0 + c0p[n]);
                        v1[q] = leaky(r1 + c1p[n]);
                    }
                } else {
                    int kb2 = kl0 - 64;
                    const float* q0 = src0 + (size_t)kb2*NPIX + pix0;
                    const float* q1 = q0 + NPIX;
                    float s0 = sT[kb2], t0v = sT[64 + kb2];
                    float s1 = sT[kb2+1], t1v = sT[64 + kb2 + 1];
                    #pragma unroll
                    for (int q = 0; q < 4; q++){
                        int n = lane + q*32;
                        v0[q] = leaky(q0[n]*s0 + t0v);
                        v1[q] = leaky(q1[n]*s1 + t1v);
                    }
                }
                #pragma unroll
                for (int q = 0; q < 4; q++){
                    int n = lane + q*32;
                    uint32_t hi = cvt_bf16x2(v1[q], v0[q]);
                    float f0 = __uint_as_float(hi << 16);
                    float f1 = __uint_as_float(hi & 0xffff0000u);
                    uint32_t lo = cvt_bf16x2(v1[q] - f1, v0[q] - f0);
                    uint32_t ad = sbase + SMG_BH + n*GSTR + kl0*2;
                    asm volatile("st.shared.b32 [%0], %1;" :: "r"(ad), "r"(hi));
                    asm volatile("st.shared.b32 [%0], %1;" :: "r"(ad + (SMG_BL - SMG_BH)), "r"(lo));
                }
            }
        }
        __syncthreads();
        #pragma unroll
        for (int kb = 0; kb < KB; kb++){
            uint32_t a0[4], a1[4];
            ldm4(a0, aAddr + kb*32);
            ldm4(a1, aAddr + kb*32 + 16*GSTR);
            #pragma unroll
            for (int part = 0; part < 2; part++){
                if (part == 1 && wm >= 2) break;   // drop Wl@Bl
                uint32_t bb[4][4];
                uint32_t bb0 = bAddr + kb*32 + part*(SMG_BL - SMG_BH);
                #pragma unroll
                for (int q = 0; q < 4; q++) ldm4(bb[q], bb0 + q*16*GSTR);
                #pragma unroll
                for (int nf = 0; nf < 8; nf++){
                    uint32_t b0 = bb[nf >> 1][nf & 1];
                    uint32_t b1 = bb[nf >> 1][(nf & 1) + 2];
                    mma16816(acc[0][nf], a0, b0, b1);
                    mma16816(acc[1][nf], a1, b0, b1);
                }
            }
        }
    }
    __syncthreads();

    float* sC = (float*)smem;
    #pragma unroll
    for (int mf = 0; mf < 2; mf++){
        int r0 = wm*32 + mf*16 + (lane >> 2);
        #pragma unroll
        for (int nf = 0; nf < 8; nf++){
            int c0 = wn*64 + nf*8 + (lane & 3)*2;
            *(float2*)&sC[r0*GEPI + c0]     = make_float2(acc[mf][nf][0], acc[mf][nf][1]);
            *(float2*)&sC[(r0+8)*GEPI + c0] = make_float2(acc[mf][nf][2], acc[mf][nf][3]);
        }
    }
    __syncthreads();
    float* rs = (float*)(smem + SMG_RED);
    float* rq = rs + 64;
    if (tid < 64){ rs[tid] = 0.f; rq[tid] = 0.f; }
    __syncthreads();
    for (int i = 0; i < 32; i++){
        int idx = i*256 + tid;
        int row = idx >> 7, col = idx & 127;
        float v = sC[row*GEPI + col] + sC[(row+64)*GEPI + col];
        outb[row*NPIX + pix0 + col] = v;
        float s = v, q = v*v;
        #pragma unroll
        for (int o = 16; o > 0; o >>= 1){
            s += __shfl_down_sync(0xffffffffu, s, o);
            q += __shfl_down_sync(0xffffffffu, q, o);
        }
        if (lane == 0){ atomicAdd(&rs[row], s); atomicAdd(&rq[row], q); }
    }
    __syncthreads();
    if (tid < 64){
        atomicAdd(&g_acc[2*tid],   (double)rs[tid]);
        atomicAdd(&g_acc[2*tid+1], (double)rq[tid]);
    }
}

// ---------------- dilated 3x3 conv via mma.sync bf16-split, 2 CTA/SM ----------------
#define ASTR 400
#define BSTR 144
#define SM_A   0
#define SM_BH  51200
#define SM_BL  70784
#define SM_RED 90368
#define SM_ST  90880
#define CONV_SMEM 91648
#define EPI_STRIDE 132

// MODE: 0 plain; 1 leaky(v*s+t); 2 = 1 + write X interior; 3 = 1 + res add + write X interior
template<int DIL, int MODE>
__global__ __launch_bounds__(256, 2)
void k_conv(const float* __restrict__ in, int abase, const float* __restrict__ bias,
            const float* __restrict__ tfs, const float* __restrict__ tft,
            const float* __restrict__ res,
            float* __restrict__ xnew, float* __restrict__ out){
    constexpr int WIN = 128 + 2*DIL;
    extern __shared__ char smem[];
    float* sST = (float*)(smem + SM_ST);       // s[64], t[64], bias[64]
    uint32_t sbase = smem_u32(smem);
    int tid = threadIdx.x, wid = tid >> 5, lane = tid & 31;
    int tile = blockIdx.x;
    int ty = tile/3, tx0 = (tile - ty*3)*128;
    int wm = wid & 3, wn = wid >> 2;

    if (tid < 64){
        if (MODE >= 1){ sST[tid] = tfs[tid]; sST[64 + tid] = tft[tid]; }
        sST[128 + tid] = bias[tid];
    }

    uint32_t aAddr = sbase + SM_A + (wm*32 + (lane & 15))*ASTR + ((lane >> 4) << 4);
    uint32_t bAddr = sbase + SM_BH + (wn*64 + (lane & 15))*BSTR + ((lane >> 4) << 4);

    float acc[2][8][4];
    #pragma unroll
    for (int i = 0; i < 2; i++)
        #pragma unroll
        for (int j = 0; j < 8; j++)
            #pragma unroll
            for (int q = 0; q < 4; q++) acc[i][j][q] = 0.f;

    #pragma unroll 1
    for (int r = 0; r < 3; r++){
        int gy = ty + (r-1)*DIL;
        if ((unsigned)gy >= LDIM) continue;
        __syncthreads();
        // stage A: full 128 x 192 bf16 panel for this r
        {
            int m = tid >> 1;
            const float4* sp = (const float4*)(g_wA + abase + r*ATILE) + m*24 + (tid & 1)*12;
            float4* dp = (float4*)(smem + SM_A + m*ASTR + (tid & 1)*192);
            #pragma unroll
            for (int i = 0; i < 12; i++) dp[i] = sp[i];
        }
        // build extended B
        {
            int nlane = tid & 31;
            int c2 = (tid >> 5)*2;
            #pragma unroll
            for (int ci = 0; ci < 4; ci++, c2 += 16){
                const float* p0 = in + (c2*LDIM + gy)*LDIM;
                const float* p1 = p0 + NPIX;
                const float* r0p = (MODE == 3) ? res + (c2*LDIM + gy)*LDIM : nullptr;
                const float* r1p = (MODE == 3) ? r0p + NPIX : nullptr;
                float s0, t0, s1, t1;
                if (MODE >= 1){
                    s0 = sST[c2]; t0 = sST[64 + c2];
                    s1 = sST[c2 + 1]; t1 = sST[64 + c2 + 1];
                }
                for (int n = nlane; n < WIN; n += 32){
                    int gx = tx0 - DIL + n;
                    float v0 = 0.f, v1 = 0.f;
                    if ((unsigned)gx < LDIM){
                        v0 = p0[gx]; v1 = p1[gx];
                        if (MODE >= 1){
                            v0 = leaky(v0*s0 + t0);
                            v1 = leaky(v1*s1 + t1);
                        }
                        if (MODE == 3){ v0 += r0p[gx]; v1 += r1p[gx]; }
                        if (MODE >= 2 && r == 1 && n >= DIL && n < DIL + 128){
                            xnew[c2*NPIX + gy*LDIM + gx] = v0;
                            xnew[(c2+1)*NPIX + gy*LDIM + gx] = v1;
                        }
                    }
                    uint32_t hi = cvt_bf16x2(v1, v0);
                    float f0 = __uint_as_float(hi << 16);
                    float f1 = __uint_as_float(hi & 0xffff0000u);
                    uint32_t lo = cvt_bf16x2(v1 - f1, v0 - f0);
                    uint32_t ad = sbase + SM_BH + n*BSTR + c2*2;
                    asm volatile("st.shared.b32 [%0], %1;" :: "r"(ad), "r"(hi));
                    asm volatile("st.shared.b32 [%0], %1;" :: "r"(ad + (SM_BL - SM_BH)), "r"(lo));
                }
            }
        }
        __syncthreads();

        #pragma unroll 1
        for (int tx = 0; tx < 3; tx++){
            uint32_t aOff = tx*128;
            uint32_t bOff = tx*DIL*BSTR;
            #pragma unroll
            for (int kb = 0; kb < 4; kb++){
                uint32_t a0[4], a1[4];
                ldm4(a0, aAddr + aOff + kb*32);
                ldm4(a1, aAddr + aOff + kb*32 + 16*ASTR);
                #pragma unroll
                for (int part = 0; part < 2; part++){
                    if (part == 1 && wm >= 2) break;   // drop Wl@Bl
                    uint32_t bb[4][4];
                    uint32_t bb0 = bAddr + bOff + kb*32 + part*(SM_BL - SM_BH);
                    #pragma unroll
                    for (int q = 0; q < 4; q++) ldm4(bb[q], bb0 + q*16*BSTR);
                    #pragma unroll
                    for (int nf = 0; nf < 8; nf++){
                        uint32_t b0 = bb[nf >> 1][nf & 1];
                        uint32_t b1 = bb[nf >> 1][(nf & 1) + 2];
                        mma16816(acc[0][nf], a0, b0, b1);
                        mma16816(acc[1][nf], a1, b0, b1);
                    }
                }
            }
        }
    }
    __syncthreads();

    float* sC = (float*)smem;
    #pragma unroll
    for (int mf = 0; mf < 2; mf++){
        int r0 = wm*32 + mf*16 + (lane >> 2);
        #pragma unroll
        for (int nf = 0; nf < 8; nf++){
            int c0 = wn*64 + nf*8 + (lane & 3)*2;
            *(float2*)&sC[r0*EPI_STRIDE + c0]     = make_float2(acc[mf][nf][0], acc[mf][nf][1]);
            *(float2*)&sC[(r0+8)*EPI_STRIDE + c0] = make_float2(acc[mf][nf][2], acc[mf][nf][3]);
        }
    }
    __syncthreads();

    float* rs = (float*)(smem + SM_RED);
    float* rq = rs + 64;
    if (tid < 64){ rs[tid] = 0.f; rq[tid] = 0.f; }
    __syncthreads();
    int pbase = ty*LDIM + tx0;
    for (int i = 0; i < 32; i++){
        int idx = i*256 + tid;
        int row = idx >> 7, col = idx & 127;
        float v = sC[row*EPI_STRIDE + col] + sC[(row+64)*EPI_STRIDE + col] + sST[128 + row];
        out[row*NPIX + pbase + col] = v;
        float s = v, q = v*v;
        #pragma unroll
        for (int o = 16; o > 0; o >>= 1){
            s += __shfl_down_sync(0xffffffffu, s, o);
            q += __shfl_down_sync(0xffffffffu, q, o);
        }
        if (lane == 0){ atomicAdd(&rs[row], s); atomicAdd(&rq[row], q); }
    }
    __syncthreads();
    if (tid < 64){
        atomicAdd(&g_acc[2*tid],   (double)rs[tid]);
        atomicAdd(&g_acc[2*tid+1], (double)rq[tid]);
    }
}

// ---------------- host ----------------
extern "C" void kernel_launch(void* const* d_in, const int* in_sizes, int n_in,
                              void* d_out, int out_size){
    const float* x1    = (const float*)d_in[0];
    const float* x2    = (const float*)d_in[1];
    const float* W1    = (const float*)d_in[2];
    const float* g1    = (const float*)d_in[3];
    const float* b1    = (const float*)d_in[4];
    const float* W2    = (const float*)d_in[5];
    const float* g2    = (const float*)d_in[6];
    const float* b2    = (const float*)d_in[7];
    const float* W3    = (const float*)d_in[8];
    const float* g3    = (const float*)d_in[9];
    const float* b3    = (const float*)d_in[10];
    const float* rw    = (const float*)d_in[11];
    const float* rb    = (const float*)d_in[12];
    const float* rg    = (const float*)d_in[13];
    const float* rbeta = (const float*)d_in[14];
    float* out = (float*)d_out;

    float *bufA, *bufB, *bufX, *bufY, *bufZ, *s2, *t2, *sP, *tP, *sC, *tC;
    cudaGetSymbolAddress((void**)&bufA, g_bufA);
    cudaGetSymbolAddress((void**)&bufB, g_bufB);
    cudaGetSymbolAddress((void**)&bufX, g_bufX);
    cudaGetSymbolAddress((void**)&bufY, g_bufY);
    cudaGetSymbolAddress((void**)&bufZ, g_bufZ);
    cudaGetSymbolAddress((void**)&s2, g_s2);
    cudaGetSymbolAddress((void**)&t2, g_t2);
    cudaGetSymbolAddress((void**)&sP, g_sP);
    cudaGetSymbolAddress((void**)&tP, g_tP);
    cudaGetSymbolAddress((void**)&sC, g_sC);
    cudaGetSymbolAddress((void**)&tC, g_tC);

    cudaFuncSetAttribute(k_conv<1,1>, cudaFuncAttributeMaxDynamicSharedMemorySize, CONV_SMEM);
    cudaFuncSetAttribute(k_conv<1,2>, cudaFuncAttributeMaxDynamicSharedMemorySize, CONV_SMEM);
    cudaFuncSetAttribute(k_conv<1,3>, cudaFuncAttributeMaxDynamicSharedMemorySize, CONV_SMEM);
    cudaFuncSetAttribute(k_conv<2,1>, cudaFuncAttributeMaxDynamicSharedMemorySize, CONV_SMEM);
    cudaFuncSetAttribute(k_conv<2,3>, cudaFuncAttributeMaxDynamicSharedMemorySize, CONV_SMEM);
    cudaFuncSetAttribute(k_conv<4,1>, cudaFuncAttributeMaxDynamicSharedMemorySize, CONV_SMEM);
    cudaFuncSetAttribute(k_conv<4,3>, cudaFuncAttributeMaxDynamicSharedMemorySize, CONV_SMEM);
    cudaFuncSetAttribute(k_gemm<0>,   cudaFuncAttributeMaxDynamicSharedMemorySize, GEMM_SMEM);
    cudaFuncSetAttribute(k_gemm<1>,   cudaFuncAttributeMaxDynamicSharedMemorySize, GEMM_SMEM);

    const double invN = 1.0 / (double)NPIX;

    k_reset  <<<1, 128>>>();
    k_stats1d<<<D1, 128>>>(x1);
    k_stats2d<<<D2, 256>>>(x2);
    k_aprep  <<<2880, 256>>>(rw);
    k_aprep2 <<<112, 256>>>(W2);
    k_aprep3 <<<64, 256>>>(W3);
    k_rowcol <<<CH, LDIM>>>(x1, W1);
    k_pair1  <<<CH, LDIM>>>(g1, b1);
    k_gemm<0><<<1152, 256, GEMM_SMEM>>>(x2, bufB);
    k_finalize<<<1, 64>>>(g2, b2, s2, t2, invN);
    k_gemm<1><<<1152, 256, GEMM_SMEM>>>(bufB, bufA);
    k_finalize<<<1, 64>>>(g3, b3, sP, tP, invN);

    // layer 0 (d=1): conv1 fuses pair transform + writes X0 to bufX
    k_conv<1,2><<<1152, 256, CONV_SMEM>>>(bufA, 0*3*ATILE, rb + 0*64, sP, tP, nullptr, bufX, bufY);
    k_finalize<<<1, 64>>>(rg + 0*64, rbeta + 0*64, sC, tC, invN);
    k_conv<1,1><<<1152, 256, CONV_SMEM>>>(bufY, 1*3*ATILE, rb + 1*64, sC, tC, nullptr, nullptr, bufB);
    k_finalize<<<1, 64>>>(rg + 1*64, rbeta + 1*64, sC, tC, invN);

    // layer 1 (d=2): conv1 fuses layer-0 ew (X1 = leaky(bufB*s+t)+X0 -> bufZ)
    k_conv<2,3><<<1152, 256, CONV_SMEM>>>(bufB, 2*3*ATILE, rb + 2*64, sC, tC, bufX, bufZ, bufY);
    k_finalize<<<1, 64>>>(rg + 2*64, rbeta + 2*64, sC, tC, invN);
    k_conv<2,1><<<1152, 256, CONV_SMEM>>>(bufY, 3*3*ATILE, rb + 3*64, sC, tC, nullptr, nullptr, bufB);
    k_finalize<<<1, 64>>>(rg + 3*64, rbeta + 3*64, sC, tC, invN);

    // layer 2 (d=4): X2 -> bufX
    k_conv<4,3><<<1152, 256, CONV_SMEM>>>(bufB, 4*3*ATILE, rb + 4*64, sC, tC, bufZ, bufX, bufY);
    k_finalize<<<1, 64>>>(rg + 4*64, rbeta + 4*64, sC, tC, invN);
    k_conv<4,1><<<1152, 256, CONV_SMEM>>>(bufY, 5*3*ATILE, rb + 5*64, sC, tC, nullptr, nullptr, bufB);
    k_finalize<<<1, 64>>>(rg + 5*64, rbeta + 5*64, sC, tC, invN);

    // layer 3 (d=2): X3 -> bufZ
    k_conv<2,3><<<1152, 256, CONV_SMEM>>>(bufB, 6*3*ATILE, rb + 6*64, sC, tC, bufX, bufZ, bufY);
    k_finalize<<<1, 64>>>(rg + 6*64, rbeta + 6*64, sC, tC, invN);
    k_conv<2,1><<<1152, 256, CONV_SMEM>>>(bufY, 7*3*ATILE, rb + 7*64, sC, tC, nullptr, nullptr, bufB);
    k_finalize<<<1, 64>>>(rg + 7*64, rbeta + 7*64, sC, tC, invN);

    // layer 4 (d=1): X4 -> bufX
    k_conv<1,3><<<1152, 256, CONV_SMEM>>>(bufB, 8*3*ATILE, rb + 8*64, sC, tC, bufZ, bufX, bufY);
    k_finalize<<<1, 64>>>(rg + 8*64, rbeta + 8*64, sC, tC, invN);
    k_conv<1,1><<<1152, 256, CONV_SMEM>>>(bufY, 9*3*ATILE, rb + 9*64, sC, tC, nullptr, nullptr, bufB);
    k_finalize<<<1, 64>>>(rg + 9*64, rbeta + 9*64, sC, tC, invN);

    k_ew<<<9216, 256>>>(bufB, sC, tC, bufX, out);
}

// round 15
// speedup vs baseline: 2.3389x; 1.1764x over previous
#include <cuda_runtime.h>
#include <cuda_bf16.h>
#include <math.h>
#include <stdint.h>

#define LDIM 384
#define NPIX (384*384)
#define CH 64
#define D1 788
#define D2 210

// ---------------- device scratch (static, no allocation) ----------------
__device__ float  g_a1[D1], g_b1[D1];
__device__ float  g_a2[D2], g_b2[D2];
__device__ float  g_row[CH*LDIM], g_col[CH*LDIM];
__device__ float  g_row2[CH*LDIM], g_col2[CH*LDIM];
__device__ float  g_s2[CH], g_t2[CH];
__device__ float  g_sP[CH], g_tP[CH];
__device__ float  g_sC[CH], g_tC[CH];
__device__ double g_acc[2*CH];
__device__ float  g_bufA[CH*NPIX];
__device__ float  g_bufB[CH*NPIX];
__device__ float  g_bufX[CH*NPIX];
__device__ float  g_bufY[CH*NPIX];
__device__ float  g_bufZ[CH*NPIX];
#define ATILE 24576
__device__ __nv_bfloat16 g_wA[30*ATILE];
__device__ __nv_bfloat16 g_wP2[2*128*112];
__device__ __nv_bfloat16 g_wP3[128*128];

__device__ __forceinline__ float leaky(float v){ return v > 0.f ? v : 0.01f*v; }

__device__ float blockReduceSum(float v, float* sm){
    int tid = threadIdx.x;
    int lane = tid & 31;
    int wid  = tid >> 5;
    #pragma unroll
    for (int o = 16; o > 0; o >>= 1) v += __shfl_down_sync(0xffffffffu, v, o);
    __syncthreads();
    if (lane == 0) sm[wid] = v;
    __syncthreads();
    int nw = (blockDim.x + 31) >> 5;
    v = 0.f;
    if (tid < nw) v = sm[tid];
    if (tid < 32) {
        #pragma unroll
        for (int o = 16; o > 0; o >>= 1) v += __shfl_down_sync(0xffffffffu, v, o);
    }
    return v;
}

// ---------------- mma.sync helpers ----------------
__device__ __forceinline__ uint32_t smem_u32(const void* p){
    uint32_t a;
    asm("{ .reg .u64 t; cvta.to.shared.u64 t, %1; cvt.u32.u64 %0, t; }" : "=r"(a) : "l"(p));
    return a;
}
__device__ __forceinline__ void ldm4(uint32_t r[4], uint32_t addr){
    asm volatile("ldmatrix.sync.aligned.m8n8.x4.shared.b16 {%0,%1,%2,%3}, [%4];"
                 : "=r"(r[0]), "=r"(r[1]), "=r"(r[2]), "=r"(r[3]) : "r"(addr));
}
__device__ __forceinline__ void ldm2(uint32_t r[2], uint32_t addr){
    asm volatile("ldmatrix.sync.aligned.m8n8.x2.shared.b16 {%0,%1}, [%2];"
                 : "=r"(r[0]), "=r"(r[1]) : "r"(addr));
}
__device__ __forceinline__ void mma16816(float c[4], const uint32_t a[4], uint32_t b0, uint32_t b1){
    asm volatile("mma.sync.aligned.m16n8k16.row.col.f32.bf16.bf16.f32 "
                 "{%0,%1,%2,%3}, {%4,%5,%6,%7}, {%8,%9}, {%0,%1,%2,%3};"
                 : "+f"(c[0]), "+f"(c[1]), "+f"(c[2]), "+f"(c[3])
                 : "r"(a[0]), "r"(a[1]), "r"(a[2]), "r"(a[3]), "r"(b0), "r"(b1));
}
__device__ __forceinline__ uint32_t cvt_bf16x2(float hi, float lo){
    uint32_t r;
    asm("cvt.rn.bf16x2.f32 %0, %1, %2;" : "=r"(r) : "f"(hi), "f"(lo));
    return r;
}

// ---------------- small kernels ----------------
__global__ void k_reset(){
    if (threadIdx.x < 2*CH) g_acc[threadIdx.x] = 0.0;
}

__global__ void k_stats1d(const float* __restrict__ x){
    __shared__ float sm[32];
    int c = blockIdx.x;
    float s = 0.f, q = 0.f;
    for (int i = threadIdx.x; i < LDIM; i += blockDim.x){
        float v = x[c*LDIM + i]; s += v; q += v*v;
    }
    s = blockReduceSum(s, sm);
    q = blockReduceSum(q, sm);
    if (threadIdx.x == 0){
        float mu = s / LDIM;
        float var = q / LDIM - mu*mu;
        float a = rsqrtf(var + 1e-5f);
        g_a1[c] = a; g_b1[c] = -mu*a;
    }
}

__global__ void k_stats2d(const float* __restrict__ x){
    __shared__ float sm[32];
    int c = blockIdx.x;
    const float* p = x + c*NPIX;
    float s = 0.f, q = 0.f;
    for (int i = threadIdx.x; i < NPIX; i += blockDim.x){
        float v = p[i]; s += v; q += v*v;
    }
    s = blockReduceSum(s, sm);
    q = blockReduceSum(q, sm);
    if (threadIdx.x == 0){
        float mu = s / (float)NPIX;
        float var = q / (float)NPIX - mu*mu;
        float a = rsqrtf(var + 1e-5f);
        g_a2[c] = a; g_b2[c] = -mu*a;
    }
}

__global__ void k_aprep(const float* __restrict__ rw){
    int idx = blockIdx.x*blockDim.x + threadIdx.x;
    if (idx >= 30*128*192) return;
    int lkr = idx / (128*192);
    int rem = idx - lkr*(128*192);
    int m = rem / 192;
    int k = rem - m*192;
    int cout = m & 63, part = m >> 6;
    int cin = k & 63, tx = k >> 6;
    int lk = lkr / 3, r = lkr - lk*3;
    float w = rw[((lk*64 + cout)*64 + cin)*9 + r*3 + tx];
    __nv_bfloat16 hi = __float2bfloat16(w);
    __nv_bfloat16 val = part ? __float2bfloat16(w - __bfloat162float(hi)) : hi;
    g_wA[lkr*ATILE + m*192 + k] = val;
}

__global__ void k_aprep2(const float* __restrict__ W2){
    int idx = blockIdx.x*blockDim.x + threadIdx.x;
    if (idx >= 2*128*112) return;
    int ch = idx / (128*112);
    int rem = idx - ch*(128*112);
    int m = rem / 112;
    int kl = rem - m*112;
    int cout = m & 63, part = m >> 6;
    int k = ch*112 + kl;
    float w = (k < D2) ? W2[cout*D2 + k] : 0.f;
    __nv_bfloat16 hi = __float2bfloat16(w);
    __nv_bfloat16 val = part ? __float2bfloat16(w - __bfloat162float(hi)) : hi;
    g_wP2[idx] = val;
}

__global__ void k_aprep3(const float* __restrict__ W3){
    int idx = blockIdx.x*blockDim.x + threadIdx.x;
    if (idx >= 128*128) return;
    int m = idx >> 7, k = idx & 127;
    int cout = m & 63, part = m >> 6;
    float w = W3[cout*128 + k];
    __nv_bfloat16 hi = __float2bfloat16(w);
    __nv_bfloat16 val = part ? __float2bfloat16(w - __bfloat162float(hi)) : hi;
    g_wP3[idx] = val;
}

__global__ void k_rowcol(const float* __restrict__ x1, const float* __restrict__ W1){
    __shared__ float sa[D1], sb[D1];
    int c = blockIdx.x, i = threadIdx.x;
    for (int d = threadIdx.x; d < D1; d += blockDim.x){ sa[d] = g_a1[d]; sb[d] = g_b1[d]; }
    __syncthreads();
    float r = 0.f, cl = 0.f;
    for (int d = 0; d < D1; d++){
        float v = x1[d*LDIM + i]*sa[d] + sb[d];
        r  += W1[c*(2*D1) + d]      * v;
        cl += W1[c*(2*D1) + D1 + d] * v;
    }
    g_row[c*LDIM + i] = r;
    g_col[c*LDIM + i] = cl;
}

__global__ void k_pair1(const float* __restrict__ g1, const float* __restrict__ b1){
    __shared__ float sm[32];
    __shared__ float sS, sT;
    int c = blockIdx.x, t = threadIdx.x;
    float r  = g_row[c*LDIM + t];
    float co = g_col[c*LDIM + t];
    float sr  = blockReduceSum(r, sm);
    float sr2 = blockReduceSum(r*r, sm);
    float sc  = blockReduceSum(co, sm);
    float sc2 = blockReduceSum(co*co, sm);
    if (t == 0){
        float mr = sr / LDIM, mc = sc / LDIM;
        float var = (sr2/LDIM - mr*mr) + (sc2/LDIM - mc*mc);
        float s = g1[c]*rsqrtf(var + 1e-5f);
        sS = s; sT = b1[c] - (mr + mc)*s;
    }
    __syncthreads();
    g_row2[c*LDIM + t] = r*sS + sT;
    g_col2[c*LDIM + t] = co*sS;
}

__global__ void k_finalize(const float* __restrict__ gamma, const float* __restrict__ beta,
                           float* __restrict__ sOut, float* __restrict__ tOut, double invN){
    int c = threadIdx.x;
    double sum = g_acc[2*c], sq = g_acc[2*c+1];
    double mu  = sum*invN;
    double var = sq*invN - mu*mu;
    float s = gamma[c]*rsqrtf((float)var + 1e-5f);
    float t = beta[c] - (float)mu*s;
    sOut[c] = s; tOut[c] = t;
    g_acc[2*c] = 0.0; g_acc[2*c+1] = 0.0;
}

__global__ void k_ew(const float* __restrict__ in, const float* __restrict__ s,
                     const float* __restrict__ t, const float* __restrict__ res,
                     float* __restrict__ out){
    int idx = blockIdx.x*blockDim.x + threadIdx.x;
    int p = idx*4;
    int c = p / NPIX;
    float4 v = *(const float4*)(in + p);
    float ss = s[c], tt = t[c];
    v.x = leaky(v.x*ss + tt);
    v.y = leaky(v.y*ss + tt);
    v.z = leaky(v.z*ss + tt);
    v.w = leaky(v.w*ss + tt);
    if (res){
        float4 rr = *(const float4*)(res + p);
        v.x += rr.x; v.y += rr.y; v.z += rr.z; v.w += rr.w;
    }
    *(float4*)(out + p) = v;
}

// ---------------- unified mma GEMM for pair2 / combine ----------------
#define GSTR 272
#define SMG_A   0
#define SMG_BH  34816
#define SMG_BL  69632
#define SMG_RED 104448
#define SMG_T   104960
#define GEMM_SMEM 105984
#define GEPI 132

template<int SRC>
__global__ __launch_bounds__(256, 2)
void k_gemm(const float* __restrict__ src0, float* __restrict__ outb){
    extern __shared__ char smem[];
    float* sT = (float*)(smem + SMG_T);
    uint32_t sbase = smem_u32(smem);
    int tid = threadIdx.x, wid = tid >> 5, lane = tid & 31;
    int pix0 = blockIdx.x*128;
    int i0 = pix0 / LDIM, j0 = pix0 - i0*LDIM;
    int wm = wid & 3, wn = wid >> 2;
    // symmetric M split: each warp owns 16 hi rows (wm*16) + 16 lo rows (64+wm*16)
    uint32_t aAddr0 = sbase + SMG_A + (wm*16 + (lane & 15))*GSTR + ((lane >> 4) << 4);
    uint32_t aAddr1 = aAddr0 + 64*GSTR;
    uint32_t bAddr = sbase + SMG_BH + (wn*64 + (lane & 15))*GSTR + ((lane >> 4) << 4);

    float acc[2][8][4];
    #pragma unroll
    for (int i = 0; i < 2; i++)
        #pragma unroll
        for (int j = 0; j < 8; j++)
            #pragma unroll
            for (int q = 0; q < 4; q++) acc[i][j][q] = 0.f;

    constexpr int NCH = SRC ? 1 : 2;
    constexpr int KB  = SRC ? 8 : 7;
    #pragma unroll 1
    for (int ch = 0; ch < NCH; ch++){
        __syncthreads();
        if (SRC == 0){
            if (tid < 112){
                int k = ch*112 + tid;
                bool ok = (k < D2);
                sT[tid]       = ok ? g_a2[k] : 0.f;
                sT[128 + tid] = ok ? g_b2[k] : 0.f;
            }
        } else {
            if (tid < 64){
                sT[tid]        = g_s2[tid];
                sT[64 + tid]   = g_t2[tid];
                sT[128 + tid]  = g_row2[tid*LDIM + i0];
            }
        }
        {
            constexpr int F4 = SRC ? 16 : 14;
            const __nv_bfloat16* wb = SRC ? g_wP3 : (g_wP2 + ch*128*112);
            int m = tid >> 1, h = tid & 1;
            const float4* sp = (const float4*)wb + m*F4 + h*(F4/2);
            float4* dp = (float4*)(smem + SMG_A + m*GSTR + h*(F4/2)*16);
            #pragma unroll
            for (int q = 0; q < F4/2; q++) dp[q] = sp[q];
        }
        __syncthreads();
        {
            constexpr int PK = SRC ? 8 : 7;
            #pragma unroll 1
            for (int p = 0; p < PK; p++){
                int kl0 = wid*2*PK + p*2;
                float v0[4], v1[4];
                if (SRC == 0){
                    int kg = ch*112 + kl0;
                    const float* q0 = src0 + (size_t)kg*NPIX + pix0;
                    const float* q1 = q0 + NPIX;
                    bool ok0 = (kg < D2), ok1 = (kg + 1 < D2);
                    float a0 = sT[kl0], b0v = sT[128 + kl0];
                    float a1 = sT[kl0+1], b1v = sT[128 + kl0 + 1];
                    #pragma unroll
                    for (int q = 0; q < 4; q++){
                        int n = lane + q*32;
                        v0[q] = ok0 ? q0[n]*a0 + b0v : 0.f;
                        v1[q] = ok1 ? q1[n]*a1 + b1v : 0.f;
                    }
                } else if (kl0 < 64){
                    float r0 = sT[128 + kl0], r1 = sT[128 + kl0 + 1];
                    const float* c0p = g_col2 + kl0*LDIM + j0;
                    const float* c1p = c0p + LDIM;
                    #pragma unroll
                    for (int q = 0; q < 4; q++){
                        int n = lane + q*32;
                        v0[q] = leaky(r0 + c0p[n]);
                        v1[q] = leaky(r1 + c1p[n]);
                    }
                } else {
                    int kb2 = kl0 - 64;
                    const float* q0 = src0 + (size_t)kb2*NPIX + pix0;
                    const float* q1 = q0 + NPIX;
                    float s0 = sT[kb2], t0v = sT[64 + kb2];
                    float s1 = sT[kb2+1], t1v = sT[64 + kb2 + 1];
                    #pragma unroll
                    for (int q = 0; q < 4; q++){
                        int n = lane + q*32;
                        v0[q] = leaky(q0[n]*s0 + t0v);
                        v1[q] = leaky(q1[n]*s1 + t1v);
                    }
                }
                #pragma unroll
                for (int q = 0; q < 4; q++){
                    int n = lane + q*32;
                    uint32_t hi = cvt_bf16x2(v1[q], v0[q]);
                    float f0 = __uint_as_float(hi << 16);
                    float f1 = __uint_as_float(hi & 0xffff0000u);
                    uint32_t lo = cvt_bf16x2(v1[q] - f1, v0[q] - f0);
                    uint32_t ad = sbase + SMG_BH + n*GSTR + kl0*2;
                    asm volatile("st.shared.b32 [%0], %1;" :: "r"(ad), "r"(hi));
                    asm volatile("st.shared.b32 [%0], %1;" :: "r"(ad + (SMG_BL - SMG_BH)), "r"(lo));
                }
            }
        }
        __syncthreads();
        #pragma unroll
        for (int kb = 0; kb < KB; kb++){
            uint32_t a0[4], a1[4];
            ldm4(a0, aAddr0 + kb*32);
            ldm4(a1, aAddr1 + kb*32);
            uint32_t bb[4][4];
            // part 0: B_hi — both hi and lo A rows
            #pragma unroll
            for (int q = 0; q < 4; q++) ldm4(bb[q], bAddr + kb*32 + q*16*GSTR);
            #pragma unroll
            for (int nf = 0; nf < 8; nf++){
                uint32_t b0 = bb[nf >> 1][nf & 1];
                uint32_t b1 = bb[nf >> 1][(nf & 1) + 2];
                mma16816(acc[0][nf], a0, b0, b1);
                mma16816(acc[1][nf], a1, b0, b1);
            }
            // part 1: B_lo — hi A rows only (drop Wl@Bl symmetrically)
            #pragma unroll
            for (int q = 0; q < 4; q++) ldm4(bb[q], bAddr + kb*32 + q*16*GSTR + (SMG_BL - SMG_BH));
            #pragma unroll
            for (int nf = 0; nf < 8; nf++){
                uint32_t b0 = bb[nf >> 1][nf & 1];
                uint32_t b1 = bb[nf >> 1][(nf & 1) + 2];
                mma16816(acc[0][nf], a0, b0, b1);
            }
        }
    }
    __syncthreads();

    float* sC = (float*)smem;
    #pragma unroll
    for (int mf = 0; mf < 2; mf++){
        int r0 = (mf ? 64 : 0) + wm*16 + (lane >> 2);
        #pragma unroll
        for (int nf = 0; nf < 8; nf++){
            int c0 = wn*64 + nf*8 + (lane & 3)*2;
            *(float2*)&sC[r0*GEPI + c0]     = make_float2(acc[mf][nf][0], acc[mf][nf][1]);
            *(float2*)&sC[(r0+8)*GEPI + c0] = make_float2(acc[mf][nf][2], acc[mf][nf][3]);
        }
    }
    __syncthreads();
    float* rs = (float*)(smem + SMG_RED);
    float* rq = rs + 64;
    if (tid < 64){ rs[tid] = 0.f; rq[tid] = 0.f; }
    __syncthreads();
    #pragma unroll
    for (int i = 0; i < 8; i++){
        int idx = i*1024 + tid*4;
        int row = idx >> 7, col = idx & 127;
        float4 t4 = *(const float4*)&sC[row*GEPI + col];
        float4 b4 = *(const float4*)&sC[(row+64)*GEPI + col];
        float4 v;
        v.x = t4.x + b4.x; v.y = t4.y + b4.y; v.z = t4.z + b4.z; v.w = t4.w + b4.w;
        *(float4*)&outb[row*NPIX + pix0 + col] = v;
        float s = v.x + v.y + v.z + v.w;
        float q = v.x*v.x + v.y*v.y + v.z*v.z + v.w*v.w;
        #pragma unroll
        for (int o = 16; o > 0; o >>= 1){
            s += __shfl_down_sync(0xffffffffu, s, o);
            q += __shfl_down_sync(0xffffffffu, q, o);
        }
        if (lane == 0){ atomicAdd(&rs[row], s); atomicAdd(&rq[row], q); }
    }
    __syncthreads();
    if (tid < 64){
        atomicAdd(&g_acc[2*tid],   (double)rs[tid]);
        atomicAdd(&g_acc[2*tid+1], (double)rq[tid]);
    }
}

// ---------------- dilated 3x3 conv via mma.sync bf16-split, 2 CTA/SM ----------------
#define ASTR 400
#define BSTR 144
#define SM_A   0
#define SM_BH  51200
#define SM_BL  70784
#define SM_RED 90368
#define SM_ST  90880
#define CONV_SMEM 91648
#define EPI_STRIDE 132

// MODE: 0 plain; 1 leaky(v*s+t); 2 = 1 + write X interior; 3 = 1 + res add + write X interior
template<int DIL, int MODE>
__global__ __launch_bounds__(256, 2)
void k_conv(const float* __restrict__ in, int abase, const float* __restrict__ bias,
            const float* __restrict__ tfs, const float* __restrict__ tft,
            const float* __restrict__ res,
            float* __restrict__ xnew, float* __restrict__ out){
    constexpr int WIN = 128 + 2*DIL;
    extern __shared__ char smem[];
    float* sST = (float*)(smem + SM_ST);       // s[64], t[64], bias[64]
    uint32_t sbase = smem_u32(smem);
    int tid = threadIdx.x, wid = tid >> 5, lane = tid & 31;
    int tile = blockIdx.x;
    int ty = tile/3, tx0 = (tile - ty*3)*128;
    int wm = wid & 3, wn = wid >> 2;

    if (tid < 64){
        if (MODE >= 1){ sST[tid] = tfs[tid]; sST[64 + tid] = tft[tid]; }
        sST[128 + tid] = bias[tid];
    }

    // symmetric M split: each warp owns 16 hi rows (wm*16) + 16 lo rows (64+wm*16)
    uint32_t aAddr0 = sbase + SM_A + (wm*16 + (lane & 15))*ASTR + ((lane >> 4) << 4);
    uint32_t aAddr1 = aAddr0 + 64*ASTR;
    uint32_t bAddr = sbase + SM_BH + (wn*64 + (lane & 15))*BSTR + ((lane >> 4) << 4);

    float acc[2][8][4];
    #pragma unroll
    for (int i = 0; i < 2; i++)
        #pragma unroll
        for (int j = 0; j < 8; j++)
            #pragma unroll
            for (int q = 0; q < 4; q++) acc[i][j][q] = 0.f;

    #pragma unroll 1
    for (int r = 0; r < 3; r++){
        int gy = ty + (r-1)*DIL;
        if ((unsigned)gy >= LDIM) continue;
        __syncthreads();
        // stage A: full 128 x 192 bf16 panel for this r
        {
            int m = tid >> 1;
            const float4* sp = (const float4*)(g_wA + abase + r*ATILE) + m*24 + (tid & 1)*12;
            float4* dp = (float4*)(smem + SM_A + m*ASTR + (tid & 1)*192);
            #pragma unroll
            for (int i = 0; i < 12; i++) dp[i] = sp[i];
        }
        // build extended B
        {
            int nlane = tid & 31;
            int c2 = (tid >> 5)*2;
            #pragma unroll
            for (int ci = 0; ci < 4; ci++, c2 += 16){
                const float* p0 = in + (c2*LDIM + gy)*LDIM;
                const float* p1 = p0 + NPIX;
                const float* r0p = (MODE == 3) ? res + (c2*LDIM + gy)*LDIM : nullptr;
                const float* r1p = (MODE == 3) ? r0p + NPIX : nullptr;
                float s0, t0, s1, t1;
                if (MODE >= 1){
                    s0 = sST[c2]; t0 = sST[64 + c2];
                    s1 = sST[c2 + 1]; t1 = sST[64 + c2 + 1];
                }
                for (int n = nlane; n < WIN; n += 32){
                    int gx = tx0 - DIL + n;
                    float v0 = 0.f, v1 = 0.f;
                    if ((unsigned)gx < LDIM){
                        v0 = p0[gx]; v1 = p1[gx];
                        if (MODE >= 1){
                            v0 = leaky(v0*s0 + t0);
                            v1 = leaky(v1*s1 + t1);
                        }
                        if (MODE == 3){ v0 += r0p[gx]; v1 += r1p[gx]; }
                        if (MODE >= 2 && r == 1 && n >= DIL && n < DIL + 128){
                            xnew[c2*NPIX + gy*LDIM + gx] = v0;
                            xnew[(c2+1)*NPIX + gy*LDIM + gx] = v1;
                        }
                    }
                    uint32_t hi = cvt_bf16x2(v1, v0);
                    float f0 = __uint_as_float(hi << 16);
                    float f1 = __uint_as_float(hi & 0xffff0000u);
                    uint32_t lo = cvt_bf16x2(v1 - f1, v0 - f0);
                    uint32_t ad = sbase + SM_BH + n*BSTR + c2*2;
                    asm volatile("st.shared.b32 [%0], %1;" :: "r"(ad), "r"(hi));
                    asm volatile("st.shared.b32 [%0], %1;" :: "r"(ad + (SM_BL - SM_BH)), "r"(lo));
                }
            }
        }
        __syncthreads();

        #pragma unroll 1
        for (int tx = 0; tx < 3; tx++){
            uint32_t aOff = tx*128;
            uint32_t bOff = tx*DIL*BSTR;
            #pragma unroll
            for (int kb = 0; kb < 4; kb++){
                uint32_t a0[4], a1[4];
                ldm4(a0, aAddr0 + aOff + kb*32);
                ldm4(a1, aAddr1 + aOff + kb*32);
                uint32_t bb[4][4];
                // part 0: B_hi — both A halves
                #pragma unroll
                for (int q = 0; q < 4; q++) ldm4(bb[q], bAddr + bOff + kb*32 + q*16*BSTR);
                #pragma unroll
                for (int nf = 0; nf < 8; nf++){
                    uint32_t b0 = bb[nf >> 1][nf & 1];
                    uint32_t b1 = bb[nf >> 1][(nf & 1) + 2];
                    mma16816(acc[0][nf], a0, b0, b1);
                    mma16816(acc[1][nf], a1, b0, b1);
                }
                // part 1: B_lo — hi A rows only (symmetric Wl@Bl drop)
                #pragma unroll
                for (int q = 0; q < 4; q++) ldm4(bb[q], bAddr + bOff + kb*32 + q*16*BSTR + (SM_BL - SM_BH));
                #pragma unroll
                for (int nf = 0; nf < 8; nf++){
                    uint32_t b0 = bb[nf >> 1][nf & 1];
                    uint32_t b1 = bb[nf >> 1][(nf & 1) + 2];
                    mma16816(acc[0][nf], a0, b0, b1);
                }
            }
        }
    }
    __syncthreads();

    float* sC = (float*)smem;
    #pragma unroll
    for (int mf = 0; mf < 2; mf++){
        int r0 = (mf ? 64 : 0) + wm*16 + (lane >> 2);
        #pragma unroll
        for (int nf = 0; nf < 8; nf++){
            int c0 = wn*64 + nf*8 + (lane & 3)*2;
            *(float2*)&sC[r0*EPI_STRIDE + c0]     = make_float2(acc[mf][nf][0], acc[mf][nf][1]);
            *(float2*)&sC[(r0+8)*EPI_STRIDE + c0] = make_float2(acc[mf][nf][2], acc[mf][nf][3]);
        }
    }
    __syncthreads();

    float* rs = (float*)(smem + SM_RED);
    float* rq = rs + 64;
    if (tid < 64){ rs[tid] = 0.f; rq[tid] = 0.f; }
    __syncthreads();
    int pbase = ty*LDIM + tx0;
    #pragma unroll
    for (int i = 0; i < 8; i++){
        int idx = i*1024 + tid*4;
        int row = idx >> 7, col = idx & 127;
        float4 t4 = *(const float4*)&sC[row*EPI_STRIDE + col];
        float4 b4 = *(const float4*)&sC[(row+64)*EPI_STRIDE + col];
        float bb = sST[128 + row];
        float4 v;
        v.x = t4.x + b4.x + bb; v.y = t4.y + b4.y + bb;
        v.z = t4.z + b4.z + bb; v.w = t4.w + b4.w + bb;
        *(float4*)&out[row*NPIX + pbase + col] = v;
        float s = v.x + v.y + v.z + v.w;
        float q = v.x*v.x + v.y*v.y + v.z*v.z + v.w*v.w;
        #pragma unroll
        for (int o = 16; o > 0; o >>= 1){
            s += __shfl_down_sync(0xffffffffu, s, o);
            q += __shfl_down_sync(0xffffffffu, q, o);
        }
        if (lane == 0){ atomicAdd(&rs[row], s); atomicAdd(&rq[row], q); }
    }
    __syncthreads();
    if (tid < 64){
        atomicAdd(&g_acc[2*tid],   (double)rs[tid]);
        atomicAdd(&g_acc[2*tid+1], (double)rq[tid]);
    }
}

// ---------------- host ----------------
extern "C" void kernel_launch(void* const* d_in, const int* in_sizes, int n_in,
                              void* d_out, int out_size){
    const float* x1    = (const float*)d_in[0];
    const float* x2    = (const float*)d_in[1];
    const float* W1    = (const float*)d_in[2];
    const float* g1    = (const float*)d_in[3];
    const float* b1    = (const float*)d_in[4];
    const float* W2    = (const float*)d_in[5];
    const float* g2    = (const float*)d_in[6];
    const float* b2    = (const float*)d_in[7];
    const float* W3    = (const float*)d_in[8];
    const float* g3    = (const float*)d_in[9];
    const float* b3    = (const float*)d_in[10];
    const float* rw    = (const float*)d_in[11];
    const float* rb    = (const float*)d_in[12];
    const float* rg    = (const float*)d_in[13];
    const float* rbeta = (const float*)d_in[14];
    float* out = (float*)d_out;

    float *bufA, *bufB, *bufX, *bufY, *bufZ, *s2, *t2, *sP, *tP, *sC, *tC;
    cudaGetSymbolAddress((void**)&bufA, g_bufA);
    cudaGetSymbolAddress((void**)&bufB, g_bufB);
    cudaGetSymbolAddress((void**)&bufX, g_bufX);
    cudaGetSymbolAddress((void**)&bufY, g_bufY);
    cudaGetSymbolAddress((void**)&bufZ, g_bufZ);
    cudaGetSymbolAddress((void**)&s2, g_s2);
    cudaGetSymbolAddress((void**)&t2, g_t2);
    cudaGetSymbolAddress((void**)&sP, g_sP);
    cudaGetSymbolAddress((void**)&tP, g_tP);
    cudaGetSymbolAddress((void**)&sC, g_sC);
    cudaGetSymbolAddress((void**)&tC, g_tC);

    cudaFuncSetAttribute(k_conv<1,1>, cudaFuncAttributeMaxDynamicSharedMemorySize, CONV_SMEM);
    cudaFuncSetAttribute(k_conv<1,2>, cudaFuncAttributeMaxDynamicSharedMemorySize, CONV_SMEM);
    cudaFuncSetAttribute(k_conv<1,3>, cudaFuncAttributeMaxDynamicSharedMemorySize, CONV_SMEM);
    cudaFuncSetAttribute(k_conv<2,1>, cudaFuncAttributeMaxDynamicSharedMemorySize, CONV_SMEM);
    cudaFuncSetAttribute(k_conv<2,3>, cudaFuncAttributeMaxDynamicSharedMemorySize, CONV_SMEM);
    cudaFuncSetAttribute(k_conv<4,1>, cudaFuncAttributeMaxDynamicSharedMemorySize, CONV_SMEM);
    cudaFuncSetAttribute(k_conv<4,3>, cudaFuncAttributeMaxDynamicSharedMemorySize, CONV_SMEM);
    cudaFuncSetAttribute(k_gemm<0>,   cudaFuncAttributeMaxDynamicSharedMemorySize, GEMM_SMEM);
    cudaFuncSetAttribute(k_gemm<1>,   cudaFuncAttributeMaxDynamicSharedMemorySize, GEMM_SMEM);

    const double invN = 1.0 / (double)NPIX;

    k_reset  <<<1, 128>>>();
    k_stats1d<<<D1, 128>>>(x1);
    k_stats2d<<<D2, 256>>>(x2);
    k_aprep  <<<2880, 256>>>(rw);
    k_aprep2 <<<112, 256>>>(W2);
    k_aprep3 <<<64, 256>>>(W3);
    k_rowcol <<<CH, LDIM>>>(x1, W1);
    k_pair1  <<<CH, LDIM>>>(g1, b1);
    k_gemm<0><<<1152, 256, GEMM_SMEM>>>(x2, bufB);
    k_finalize<<<1, 64>>>(g2, b2, s2, t2, invN);
    k_gemm<1><<<1152, 256, GEMM_SMEM>>>(bufB, bufA);
    k_finalize<<<1, 64>>>(g3, b3, sP, tP, invN);

    // layer 0 (d=1): conv1 fuses pair transform + writes X0 to bufX
    k_conv<1,2><<<1152, 256, CONV_SMEM>>>(bufA, 0*3*ATILE, rb + 0*64, sP, tP, nullptr, bufX, bufY);
    k_finalize<<<1, 64>>>(rg + 0*64, rbeta + 0*64, sC, tC, invN);
    k_conv<1,1><<<1152, 256, CONV_SMEM>>>(bufY, 1*3*ATILE, rb + 1*64, sC, tC, nullptr, nullptr, bufB);
    k_finalize<<<1, 64>>>(rg + 1*64, rbeta + 1*64, sC, tC, invN);

    // layer 1 (d=2): conv1 fuses layer-0 ew (X1 = leaky(bufB*s+t)+X0 -> bufZ)
    k_conv<2,3><<<1152, 256, CONV_SMEM>>>(bufB, 2*3*ATILE, rb + 2*64, sC, tC, bufX, bufZ, bufY);
    k_finalize<<<1, 64>>>(rg + 2*64, rbeta + 2*64, sC, tC, invN);
    k_conv<2,1><<<1152, 256, CONV_SMEM>>>(bufY, 3*3*ATILE, rb + 3*64, sC, tC, nullptr, nullptr, bufB);
    k_finalize<<<1, 64>>>(rg + 3*64, rbeta + 3*64, sC, tC, invN);

    // layer 2 (d=4): X2 -> bufX
    k_conv<4,3><<<1152, 256, CONV_SMEM>>>(bufB, 4*3*ATILE, rb + 4*64, sC, tC, bufZ, bufX, bufY);
    k_finalize<<<1, 64>>>(rg + 4*64, rbeta + 4*64, sC, tC, invN);
    k_conv<4,1><<<1152, 256, CONV_SMEM>>>(bufY, 5*3*ATILE, rb + 5*64, sC, tC, nullptr, nullptr, bufB);
    k_finalize<<<1, 64>>>(rg + 5*64, rbeta + 5*64, sC, tC, invN);

    // layer 3 (d=2): X3 -> bufZ
    k_conv<2,3><<<1152, 256, CONV_SMEM>>>(bufB, 6*3*ATILE, rb + 6*64, sC, tC, bufX, bufZ, bufY);
    k_finalize<<<1, 64>>>(rg + 6*64, rbeta + 6*64, sC, tC, invN);
    k_conv<2,1><<<1152, 256, CONV_SMEM>>>(bufY, 7*3*ATILE, rb + 7*64, sC, tC, nullptr, nullptr, bufB);
    k_finalize<<<1, 64>>>(rg + 7*64, rbeta + 7*64, sC, tC, invN);

    // layer 4 (d=1): X4 -> bufX
    k_conv<1,3><<<1152, 256, CONV_SMEM>>>(bufB, 8*3*ATILE, rb + 8*64, sC, tC, bufZ, bufX, bufY);
    k_finalize<<<1, 64>>>(rg + 8*64, rbeta + 8*64, sC, tC, invN);
    k_conv<1,1><<<1152, 256, CONV_SMEM>>>(bufY, 9*3*ATILE, rb + 9*64, sC, tC, nullptr, nullptr, bufB);
    k_finalize<<<1, 64>>>(rg + 9*64, rbeta + 9*64, sC, tC, invN);

    k_ew<<<9216, 256>>>(bufB, sC, tC, bufX, out);
}

// round 16
// speedup vs baseline: 2.4757x; 1.0585x over previous
#include <cuda_runtime.h>
#include <cuda_bf16.h>
#include <math.h>
#include <stdint.h>

#define LDIM 384
#define NPIX (384*384)
#define CH 64
#define D1 788
#define D2 210

// ---------------- device scratch (static, no allocation) ----------------
__device__ float  g_a1[D1], g_b1[D1];
__device__ float  g_a2[D2], g_b2[D2];
__device__ float  g_row[CH*LDIM], g_col[CH*LDIM];
__device__ float  g_row2[CH*LDIM], g_col2[CH*LDIM];
__device__ float  g_s2[CH], g_t2[CH];
__device__ float  g_sP[CH], g_tP[CH];
__device__ float  g_sC[CH], g_tC[CH];
__device__ double g_acc[2*CH];
__device__ float  g_bufA[CH*NPIX];
__device__ float  g_bufB[CH*NPIX];
__device__ float  g_bufX[CH*NPIX];
__device__ float  g_bufY[CH*NPIX];
__device__ float  g_bufZ[CH*NPIX];
#define ATILE 24576
__device__ __nv_bfloat16 g_wA[30*ATILE];
__device__ __nv_bfloat16 g_wP2[2*128*112];
__device__ __nv_bfloat16 g_wP3[128*128];

__device__ __forceinline__ float leaky(float v){ return v > 0.f ? v : 0.01f*v; }

__device__ float blockReduceSum(float v, float* sm){
    int tid = threadIdx.x;
    int lane = tid & 31;
    int wid  = tid >> 5;
    #pragma unroll
    for (int o = 16; o > 0; o >>= 1) v += __shfl_down_sync(0xffffffffu, v, o);
    __syncthreads();
    if (lane == 0) sm[wid] = v;
    __syncthreads();
    int nw = (blockDim.x + 31) >> 5;
    v = 0.f;
    if (tid < nw) v = sm[tid];
    if (tid < 32) {
        #pragma unroll
        for (int o = 16; o > 0; o >>= 1) v += __shfl_down_sync(0xffffffffu, v, o);
    }
    return v;
}

// ---------------- mma.sync / cp.async helpers ----------------
__device__ __forceinline__ uint32_t smem_u32(const void* p){
    uint32_t a;
    asm("{ .reg .u64 t; cvta.to.shared.u64 t, %1; cvt.u32.u64 %0, t; }" : "=r"(a) : "l"(p));
    return a;
}
__device__ __forceinline__ void ldm4(uint32_t r[4], uint32_t addr){
    asm volatile("ldmatrix.sync.aligned.m8n8.x4.shared.b16 {%0,%1,%2,%3}, [%4];"
                 : "=r"(r[0]), "=r"(r[1]), "=r"(r[2]), "=r"(r[3]) : "r"(addr));
}
__device__ __forceinline__ void mma16816(float c[4], const uint32_t a[4], uint32_t b0, uint32_t b1){
    asm volatile("mma.sync.aligned.m16n8k16.row.col.f32.bf16.bf16.f32 "
                 "{%0,%1,%2,%3}, {%4,%5,%6,%7}, {%8,%9}, {%0,%1,%2,%3};"
                 : "+f"(c[0]), "+f"(c[1]), "+f"(c[2]), "+f"(c[3])
                 : "r"(a[0]), "r"(a[1]), "r"(a[2]), "r"(a[3]), "r"(b0), "r"(b1));
}
__device__ __forceinline__ uint32_t cvt_bf16x2(float hi, float lo){
    uint32_t r;
    asm("cvt.rn.bf16x2.f32 %0, %1, %2;" : "=r"(r) : "f"(hi), "f"(lo));
    return r;
}
__device__ __forceinline__ void cpa4(uint32_t saddr, const void* gptr, uint32_t sz){
    asm volatile("cp.async.ca.shared.global [%0], [%1], 4, %2;"
                 :: "r"(saddr), "l"(gptr), "r"(sz));
}
__device__ __forceinline__ void cpa16(uint32_t saddr, const void* gptr){
    asm volatile("cp.async.ca.shared.global [%0], [%1], 16;"
                 :: "r"(saddr), "l"(gptr));
}
__device__ __forceinline__ void cpa_commit(){ asm volatile("cp.async.commit_group;"); }
template<int N>
__device__ __forceinline__ void cpa_wait(){ asm volatile("cp.async.wait_group %0;" :: "n"(N)); }

// ---------------- small kernels ----------------
__global__ void k_reset(){
    if (threadIdx.x < 2*CH) g_acc[threadIdx.x] = 0.0;
}

__global__ void k_stats1d(const float* __restrict__ x){
    __shared__ float sm[32];
    int c = blockIdx.x;
    float s = 0.f, q = 0.f;
    for (int i = threadIdx.x; i < LDIM; i += blockDim.x){
        float v = x[c*LDIM + i]; s += v; q += v*v;
    }
    s = blockReduceSum(s, sm);
    q = blockReduceSum(q, sm);
    if (threadIdx.x == 0){
        float mu = s / LDIM;
        float var = q / LDIM - mu*mu;
        float a = rsqrtf(var + 1e-5f);
        g_a1[c] = a; g_b1[c] = -mu*a;
    }
}

__global__ void k_stats2d(const float* __restrict__ x){
    __shared__ float sm[32];
    int c = blockIdx.x;
    const float* p = x + c*NPIX;
    float s = 0.f, q = 0.f;
    for (int i = threadIdx.x; i < NPIX; i += blockDim.x){
        float v = p[i]; s += v; q += v*v;
    }
    s = blockReduceSum(s, sm);
    q = blockReduceSum(q, sm);
    if (threadIdx.x == 0){
        float mu = s / (float)NPIX;
        float var = q / (float)NPIX - mu*mu;
        float a = rsqrtf(var + 1e-5f);
        g_a2[c] = a; g_b2[c] = -mu*a;
    }
}

__global__ void k_aprep(const float* __restrict__ rw){
    int idx = blockIdx.x*blockDim.x + threadIdx.x;
    if (idx >= 30*128*192) return;
    int lkr = idx / (128*192);
    int rem = idx - lkr*(128*192);
    int m = rem / 192;
    int k = rem - m*192;
    int cout = m & 63, part = m >> 6;
    int cin = k & 63, tx = k >> 6;
    int lk = lkr / 3, r = lkr - lk*3;
    float w = rw[((lk*64 + cout)*64 + cin)*9 + r*3 + tx];
    __nv_bfloat16 hi = __float2bfloat16(w);
    __nv_bfloat16 val = part ? __float2bfloat16(w - __bfloat162float(hi)) : hi;
    g_wA[lkr*ATILE + m*192 + k] = val;
}

__global__ void k_aprep2(const float* __restrict__ W2){
    int idx = blockIdx.x*blockDim.x + threadIdx.x;
    if (idx >= 2*128*112) return;
    int ch = idx / (128*112);
    int rem = idx - ch*(128*112);
    int m = rem / 112;
    int kl = rem - m*112;
    int cout = m & 63, part = m >> 6;
    int k = ch*112 + kl;
    float w = (k < D2) ? W2[cout*D2 + k] : 0.f;
    __nv_bfloat16 hi = __float2bfloat16(w);
    __nv_bfloat16 val = part ? __float2bfloat16(w - __bfloat162float(hi)) : hi;
    g_wP2[idx] = val;
}

__global__ void k_aprep3(const float* __restrict__ W3){
    int idx = blockIdx.x*blockDim.x + threadIdx.x;
    if (idx >= 128*128) return;
    int m = idx >> 7, k = idx & 127;
    int cout = m & 63, part = m >> 6;
    float w = W3[cout*128 + k];
    __nv_bfloat16 hi = __float2bfloat16(w);
    __nv_bfloat16 val = part ? __float2bfloat16(w - __bfloat162float(hi)) : hi;
    g_wP3[idx] = val;
}

__global__ void k_rowcol(const float* __restrict__ x1, const float* __restrict__ W1){
    __shared__ float sa[D1], sb[D1];
    int c = blockIdx.x, i = threadIdx.x;
    for (int d = threadIdx.x; d < D1; d += blockDim.x){ sa[d] = g_a1[d]; sb[d] = g_b1[d]; }
    __syncthreads();
    float r = 0.f, cl = 0.f;
    for (int d = 0; d < D1; d++){
        float v = x1[d*LDIM + i]*sa[d] + sb[d];
        r  += W1[c*(2*D1) + d]      * v;
        cl += W1[c*(2*D1) + D1 + d] * v;
    }
    g_row[c*LDIM + i] = r;
    g_col[c*LDIM + i] = cl;
}

__global__ void k_pair1(const float* __restrict__ g1, const float* __restrict__ b1){
    __shared__ float sm[32];
    __shared__ float sS, sT;
    int c = blockIdx.x, t = threadIdx.x;
    float r  = g_row[c*LDIM + t];
    float co = g_col[c*LDIM + t];
    float sr  = blockReduceSum(r, sm);
    float sr2 = blockReduceSum(r*r, sm);
    float sc  = blockReduceSum(co, sm);
    float sc2 = blockReduceSum(co*co, sm);
    if (t == 0){
        float mr = sr / LDIM, mc = sc / LDIM;
        float var = (sr2/LDIM - mr*mr) + (sc2/LDIM - mc*mc);
        float s = g1[c]*rsqrtf(var + 1e-5f);
        sS = s; sT = b1[c] - (mr + mc)*s;
    }
    __syncthreads();
    g_row2[c*LDIM + t] = r*sS + sT;
    g_col2[c*LDIM + t] = co*sS;
}

__global__ void k_finalize(const float* __restrict__ gamma, const float* __restrict__ beta,
                           float* __restrict__ sOut, float* __restrict__ tOut, double invN){
    int c = threadIdx.x;
    double sum = g_acc[2*c], sq = g_acc[2*c+1];
    double mu  = sum*invN;
    double var = sq*invN - mu*mu;
    float s = gamma[c]*rsqrtf((float)var + 1e-5f);
    float t = beta[c] - (float)mu*s;
    sOut[c] = s; tOut[c] = t;
    g_acc[2*c] = 0.0; g_acc[2*c+1] = 0.0;
}

__global__ void k_ew(const float* __restrict__ in, const float* __restrict__ s,
                     const float* __restrict__ t, const float* __restrict__ res,
                     float* __restrict__ out){
    int idx = blockIdx.x*blockDim.x + threadIdx.x;
    int p = idx*4;
    int c = p / NPIX;
    float4 v = *(const float4*)(in + p);
    float ss = s[c], tt = t[c];
    v.x = leaky(v.x*ss + tt);
    v.y = leaky(v.y*ss + tt);
    v.z = leaky(v.z*ss + tt);
    v.w = leaky(v.w*ss + tt);
    if (res){
        float4 rr = *(const float4*)(res + p);
        v.x += rr.x; v.y += rr.y; v.z += rr.z; v.w += rr.w;
    }
    *(float4*)(out + p) = v;
}

// ---------------- unified mma GEMM for pair2 / combine ----------------
#define GSTR 272
#define SMG_A   0
#define SMG_BH  34816
#define SMG_BL  69632
#define SMG_RED 104448
#define SMG_T   104960
#define GEMM_SMEM 105984
#define GEPI 132

template<int SRC>
__global__ __launch_bounds__(256, 2)
void k_gemm(const float* __restrict__ src0, float* __restrict__ outb){
    extern __shared__ char smem[];
    float* sT = (float*)(smem + SMG_T);
    uint32_t sbase = smem_u32(smem);
    int tid = threadIdx.x, wid = tid >> 5, lane = tid & 31;
    int pix0 = blockIdx.x*128;
    int i0 = pix0 / LDIM, j0 = pix0 - i0*LDIM;
    int wm = wid & 3, wn = wid >> 2;
    uint32_t aAddr0 = sbase + SMG_A + (wm*16 + (lane & 15))*GSTR + ((lane >> 4) << 4);
    uint32_t aAddr1 = aAddr0 + 64*GSTR;
    uint32_t bAddr = sbase + SMG_BH + (wn*64 + (lane & 15))*GSTR + ((lane >> 4) << 4);

    float acc[2][8][4];
    #pragma unroll
    for (int i = 0; i < 2; i++)
        #pragma unroll
        for (int j = 0; j < 8; j++)
            #pragma unroll
            for (int q = 0; q < 4; q++) acc[i][j][q] = 0.f;

    constexpr int NCH = SRC ? 1 : 2;
    constexpr int KB  = SRC ? 8 : 7;
    #pragma unroll 1
    for (int ch = 0; ch < NCH; ch++){
        __syncthreads();
        if (SRC == 0){
            if (tid < 112){
                int k = ch*112 + tid;
                bool ok = (k < D2);
                sT[tid]       = ok ? g_a2[k] : 0.f;
                sT[128 + tid] = ok ? g_b2[k] : 0.f;
            }
        } else {
            if (tid < 64){
                sT[tid]        = g_s2[tid];
                sT[64 + tid]   = g_t2[tid];
                sT[128 + tid]  = g_row2[tid*LDIM + i0];
            }
        }
        {
            constexpr int F4 = SRC ? 16 : 14;
            const __nv_bfloat16* wb = SRC ? g_wP3 : (g_wP2 + ch*128*112);
            int m = tid >> 1, h = tid & 1;
            const float4* sp = (const float4*)wb + m*F4 + h*(F4/2);
            float4* dp = (float4*)(smem + SMG_A + m*GSTR + h*(F4/2)*16);
            #pragma unroll
            for (int q = 0; q < F4/2; q++) dp[q] = sp[q];
        }
        __syncthreads();
        {
            constexpr int PK = SRC ? 8 : 7;
            #pragma unroll 1
            for (int p = 0; p < PK; p++){
                int kl0 = wid*2*PK + p*2;
                float v0[4], v1[4];
                if (SRC == 0){
                    int kg = ch*112 + kl0;
                    const float* q0 = src0 + (size_t)kg*NPIX + pix0;
                    const float* q1 = q0 + NPIX;
                    bool ok0 = (kg < D2), ok1 = (kg + 1 < D2);
                    float a0 = sT[kl0], b0v = sT[128 + kl0];
                    float a1 = sT[kl0+1], b1v = sT[128 + kl0 + 1];
                    #pragma unroll
                    for (int q = 0; q < 4; q++){
                        int n = lane + q*32;
                        v0[q] = ok0 ? q0[n]*a0 + b0v : 0.f;
                        v1[q] = ok1 ? q1[n]*a1 + b1v : 0.f;
                    }
                } else if (kl0 < 64){
                    float r0 = sT[128 + kl0], r1 = sT[128 + kl0 + 1];
                    const float* c0p = g_col2 + kl0*LDIM + j0;
                    const float* c1p = c0p + LDIM;
                    #pragma unroll
                    for (int q = 0; q < 4; q++){
                        int n = lane + q*32;
                        v0[q] = leaky(r0 + c0p[n]);
                        v1[q] = leaky(r1 + c1p[n]);
                    }
                } else {
                    int kb2 = kl0 - 64;
                    const float* q0 = src0 + (size_t)kb2*NPIX + pix0;
                    const float* q1 = q0 + NPIX;
                    float s0 = sT[kb2], t0v = sT[64 + kb2];
                    float s1 = sT[kb2+1], t1v = sT[64 + kb2 + 1];
                    #pragma unroll
                    for (int q = 0; q < 4; q++){
                        int n = lane + q*32;
                        v0[q] = leaky(q0[n]*s0 + t0v);
                        v1[q] = leaky(q1[n]*s1 + t1v);
                    }
                }
                #pragma unroll
                for (int q = 0; q < 4; q++){
                    int n = lane + q*32;
                    uint32_t hi = cvt_bf16x2(v1[q], v0[q]);
                    float f0 = __uint_as_float(hi << 16);
                    float f1 = __uint_as_float(hi & 0xffff0000u);
                    uint32_t lo = cvt_bf16x2(v1[q] - f1, v0[q] - f0);
                    uint32_t ad = sbase + SMG_BH + n*GSTR + kl0*2;
                    asm volatile("st.shared.b32 [%0], %1;" :: "r"(ad), "r"(hi));
                    asm volatile("st.shared.b32 [%0], %1;" :: "r"(ad + (SMG_BL - SMG_BH)), "r"(lo));
                }
            }
        }
        __syncthreads();
        #pragma unroll
        for (int kb = 0; kb < KB; kb++){
            uint32_t a0[4], a1[4];
            ldm4(a0, aAddr0 + kb*32);
            ldm4(a1, aAddr1 + kb*32);
            uint32_t bb[4][4];
            #pragma unroll
            for (int q = 0; q < 4; q++) ldm4(bb[q], bAddr + kb*32 + q*16*GSTR);
            #pragma unroll
            for (int nf = 0; nf < 8; nf++){
                uint32_t b0 = bb[nf >> 1][nf & 1];
                uint32_t b1 = bb[nf >> 1][(nf & 1) + 2];
                mma16816(acc[0][nf], a0, b0, b1);
                mma16816(acc[1][nf], a1, b0, b1);
            }
            #pragma unroll
            for (int q = 0; q < 4; q++) ldm4(bb[q], bAddr + kb*32 + q*16*GSTR + (SMG_BL - SMG_BH));
            #pragma unroll
            for (int nf = 0; nf < 8; nf++){
                uint32_t b0 = bb[nf >> 1][nf & 1];
                uint32_t b1 = bb[nf >> 1][(nf & 1) + 2];
                mma16816(acc[0][nf], a0, b0, b1);
            }
        }
    }
    __syncthreads();

    float* sC = (float*)smem;
    #pragma unroll
    for (int mf = 0; mf < 2; mf++){
        int r0 = (mf ? 64 : 0) + wm*16 + (lane >> 2);
        #pragma unroll
        for (int nf = 0; nf < 8; nf++){
            int c0 = wn*64 + nf*8 + (lane & 3)*2;
            *(float2*)&sC[r0*GEPI + c0]     = make_float2(acc[mf][nf][0], acc[mf][nf][1]);
            *(float2*)&sC[(r0+8)*GEPI + c0] = make_float2(acc[mf][nf][2], acc[mf][nf][3]);
        }
    }
    __syncthreads();
    float* rs = (float*)(smem + SMG_RED);
    float* rq = rs + 64;
    if (tid < 64){ rs[tid] = 0.f; rq[tid] = 0.f; }
    __syncthreads();
    #pragma unroll
    for (int i = 0; i < 8; i++){
        int idx = i*1024 + tid*4;
        int row = idx >> 7, col = idx & 127;
        float4 t4 = *(const float4*)&sC[row*GEPI + col];
        float4 b4 = *(const float4*)&sC[(row+64)*GEPI + col];
        float4 v;
        v.x = t4.x + b4.x; v.y = t4.y + b4.y; v.z = t4.z + b4.z; v.w = t4.w + b4.w;
        *(float4*)&outb[row*NPIX + pix0 + col] = v;
        float s = v.x + v.y + v.z + v.w;
        float q = v.x*v.x + v.y*v.y + v.z*v.z + v.w*v.w;
        #pragma unroll
        for (int o = 16; o > 0; o >>= 1){
            s += __shfl_down_sync(0xffffffffu, s, o);
            q += __shfl_down_sync(0xffffffffu, q, o);
        }
        if (lane == 0){ atomicAdd(&rs[row], s); atomicAdd(&rq[row], q); }
    }
    __syncthreads();
    if (tid < 64){
        atomicAdd(&g_acc[2*tid],   (double)rs[tid]);
        atomicAdd(&g_acc[2*tid+1], (double)rq[tid]);
    }
}

// ---------------- dilated 3x3 conv: cp.async pipelined, mma.sync bf16-split ----------------
// smem: A double-buffered per-(r,tx) panels (128m x 64k), B [n][k] hi/lo, raw f32 band.
#define BSTR 144
#define SM_A0  0
#define SM_A1  18432
#define SM_BH  36864
#define SM_BL  56448
#define SM_RAW 76032
#define SM_RED 110848
#define SM_ST  111360
#define CONV_SMEM 112128
#define EPI_STRIDE 132

// MODE: 0 plain; 1 leaky(v*s+t); 2 = 1 + write X interior; 3 = 1 + res add + write X interior
template<int DIL, int MODE>
__global__ __launch_bounds__(256, 2)
void k_conv(const float* __restrict__ in, int abase, const float* __restrict__ bias,
            const float* __restrict__ tfs, const float* __restrict__ tft,
            const float* __restrict__ res,
            float* __restrict__ xnew, float* __restrict__ out){
    constexpr int WIN = 128 + 2*DIL;
    extern __shared__ char smem[];
    float* sRaw = (float*)(smem + SM_RAW);
    float* sST  = (float*)(smem + SM_ST);       // s[64], t[64], bias[64]
    uint32_t sbase = smem_u32(smem);
    int tid = threadIdx.x, wid = tid >> 5, lane = tid & 31;
    int tile = blockIdx.x;
    int ty = tile/3, tx0 = (tile - ty*3)*128;
    int wm = wid & 3, wn = wid >> 2;

    if (tid < 64){
        if (MODE >= 1){ sST[tid] = tfs[tid]; sST[64 + tid] = tft[tid]; }
        sST[128 + tid] = bias[tid];
    }

    uint32_t aRow = (wm*16 + (lane & 15))*BSTR + ((lane >> 4) << 4);
    uint32_t bAddr = sbase + SM_BH + (wn*64 + (lane & 15))*BSTR + ((lane >> 4) << 4);

    const int rA = (ty >= DIL) ? 0 : 1;
    const int rB = (ty < LDIM - DIL) ? 2 : 1;

    // cp.async issuers
    auto issue_raw = [&](int rr){
        int gy = ty + (rr-1)*DIL;
        const float* base = in + (size_t)gy*LDIM;
        #pragma unroll 4
        for (int idx = tid; idx < 64*WIN; idx += 256){
            int c = idx / WIN, n = idx - c*WIN;
            int gx = tx0 - DIL + n;
            bool ok = ((unsigned)gx < LDIM);
            const float* g = base + (size_t)c*NPIX + (ok ? gx : 0);
            cpa4(sbase + SM_RAW + (uint32_t)idx*4, g, ok ? 4u : 0u);
        }
    };
    auto issue_A = [&](int rr, int tx, int buf){
        const char* src = (const char*)(g_wA + abase + rr*ATILE);
        uint32_t dbase = sbase + (buf ? SM_A1 : SM_A0);
        #pragma unroll
        for (int j = 0; j < 4; j++){
            int cidx = tid*4 + j;
            int m = cidx >> 3, p = cidx & 7;
            cpa16(dbase + m*BSTR + p*16, src + m*384 + tx*128 + p*16);
        }
    };

    float acc[2][8][4];
    #pragma unroll
    for (int i = 0; i < 2; i++)
        #pragma unroll
        for (int j = 0; j < 8; j++)
            #pragma unroll
            for (int q = 0; q < 4; q++) acc[i][j][q] = 0.f;

    // prologue: raw(rA) then A(rA, tx0) as two groups
    issue_raw(rA); cpa_commit();
    issue_A(rA, 0, 0); cpa_commit();
    int abuf = 0;

    #pragma unroll 1
    for (int r = rA; r <= rB; r++){
        cpa_wait<1>();              // raw(r) complete (A tx0 may still fly)
        __syncthreads();
        // build B from sRaw (pure smem->smem + transforms)
        {
            int gy = ty + (r-1)*DIL;
            int nlane = tid & 31;
            int cbase = (tid >> 5)*2;
            #pragma unroll
            for (int ci = 0; ci < 4; ci++){
                int c2 = cbase + ci*16;
                const float* r0p = (MODE == 3) ? res + ((size_t)c2*LDIM + gy)*LDIM : nullptr;
                const float* r1p = (MODE == 3) ? r0p + NPIX : nullptr;
                float s0 = 0.f, t0 = 0.f, s1 = 0.f, t1 = 0.f;
                if (MODE >= 1){
                    s0 = sST[c2]; t0 = sST[64 + c2];
                    s1 = sST[c2 + 1]; t1 = sST[64 + c2 + 1];
                }
                for (int n = nlane; n < WIN; n += 32){
                    int gx = tx0 - DIL + n;
                    bool ok = ((unsigned)gx < LDIM);
                    float v0 = 0.f, v1 = 0.f;
                    if (ok){
                        v0 = sRaw[c2*WIN + n];
                        v1 = sRaw[(c2+1)*WIN + n];
                        if (MODE >= 1){
                            v0 = leaky(v0*s0 + t0);
                            v1 = leaky(v1*s1 + t1);
                        }
                        if (MODE == 3){ v0 += r0p[gx]; v1 += r1p[gx]; }
                        if (MODE >= 2 && r == 1 && n >= DIL && n < DIL + 128){
                            xnew[c2*NPIX + gy*LDIM + gx] = v0;
                            xnew[(c2+1)*NPIX + gy*LDIM + gx] = v1;
                        }
                    }
                    uint32_t hi = cvt_bf16x2(v1, v0);
                    float f0 = __uint_as_float(hi << 16);
                    float f1 = __uint_as_float(hi & 0xffff0000u);
                    uint32_t lo = cvt_bf16x2(v1 - f1, v0 - f0);
                    uint32_t ad = sbase + SM_BH + n*BSTR + c2*2;
                    asm volatile("st.shared.b32 [%0], %1;" :: "r"(ad), "r"(hi));
                    asm volatile("st.shared.b32 [%0], %1;" :: "r"(ad + (SM_BL - SM_BH)), "r"(lo));
                }
            }
        }
        __syncthreads();             // B ready; sRaw free
        if (r < rB) issue_raw(r+1);
        cpa_commit();                // raw(r+1) group (possibly empty)

        #pragma unroll 1
        for (int tx = 0; tx < 3; tx++){
            if (tx == 0) cpa_wait<1>(); else cpa_wait<0>();
            __syncthreads();         // A(r,tx) visible to all warps
            if (tx < 2) issue_A(r, tx+1, abuf^1);
            else if (r < rB) issue_A(r+1, 0, abuf^1);
            cpa_commit();            // next A group (possibly empty)

            uint32_t aA0 = sbase + (abuf ? SM_A1 : SM_A0) + aRow;
            uint32_t aA1 = aA0 + 64*BSTR;
            uint32_t bOff = tx*DIL*BSTR;
            #pragma unroll
            for (int kb = 0; kb < 4; kb++){
                uint32_t a0[4], a1[4];
                ldm4(a0, aA0 + kb*32);
                ldm4(a1, aA1 + kb*32);
                uint32_t bb[4][4];
                // part 0: B_hi — both A halves
                #pragma unroll
                for (int q = 0; q < 4; q++) ldm4(bb[q], bAddr + bOff + kb*32 + q*16*BSTR);
                #pragma unroll
                for (int nf = 0; nf < 8; nf++){
                    uint32_t b0 = bb[nf >> 1][nf & 1];
                    uint32_t b1 = bb[nf >> 1][(nf & 1) + 2];
                    mma16816(acc[0][nf], a0, b0, b1);
                    mma16816(acc[1][nf], a1, b0, b1);
                }
                // part 1: B_lo — hi A rows only (symmetric Wl@Bl drop)
                #pragma unroll
                for (int q = 0; q < 4; q++) ldm4(bb[q], bAddr + bOff + kb*32 + q*16*BSTR + (SM_BL - SM_BH));
                #pragma unroll
                for (int nf = 0; nf < 8; nf++){
                    uint32_t b0 = bb[nf >> 1][nf & 1];
                    uint32_t b1 = bb[nf >> 1][(nf & 1) + 2];
                    mma16816(acc[0][nf], a0, b0, b1);
                }
            }
            abuf ^= 1;
        }
    }
    cpa_wait<0>();
    __syncthreads();   // all mma done before overwriting smem with C

    float* sC = (float*)smem;
    #pragma unroll
    for (int mf = 0; mf < 2; mf++){
        int r0 = (mf ? 64 : 0) + wm*16 + (lane >> 2);
        #pragma unroll
        for (int nf = 0; nf < 8; nf++){
            int c0 = wn*64 + nf*8 + (lane & 3)*2;
            *(float2*)&sC[r0*EPI_STRIDE + c0]     = make_float2(acc[mf][nf][0], acc[mf][nf][1]);
            *(float2*)&sC[(r0+8)*EPI_STRIDE + c0] = make_float2(acc[mf][nf][2], acc[mf][nf][3]);
        }
    }
    __syncthreads();

    float* rs = (float*)(smem + SM_RED);
    float* rq = rs + 64;
    if (tid < 64){ rs[tid] = 0.f; rq[tid] = 0.f; }
    __syncthreads();
    int pbase = ty*LDIM + tx0;
    #pragma unroll
    for (int i = 0; i < 8; i++){
        int idx = i*1024 + tid*4;
        int row = idx >> 7, col = idx & 127;
        float4 t4 = *(const float4*)&sC[row*EPI_STRIDE + col];
        float4 b4 = *(const float4*)&sC[(row+64)*EPI_STRIDE + col];
        float bb = sST[128 + row];
        float4 v;
        v.x = t4.x + b4.x + bb; v.y = t4.y + b4.y + bb;
        v.z = t4.z + b4.z + bb; v.w = t4.w + b4.w + bb;
        *(float4*)&out[row*NPIX + pbase + col] = v;
        float s = v.x + v.y + v.z + v.w;
        float q = v.x*v.x + v.y*v.y + v.z*v.z + v.w*v.w;
        #pragma unroll
        for (int o = 16; o > 0; o >>= 1){
            s += __shfl_down_sync(0xffffffffu, s, o);
            q += __shfl_down_sync(0xffffffffu, q, o);
        }
        if (lane == 0){ atomicAdd(&rs[row], s); atomicAdd(&rq[row], q); }
    }
    __syncthreads();
    if (tid < 64){
        atomicAdd(&g_acc[2*tid],   (double)rs[tid]);
        atomicAdd(&g_acc[2*tid+1], (double)rq[tid]);
    }
}

// ---------------- host ----------------
extern "C" void kernel_launch(void* const* d_in, const int* in_sizes, int n_in,
                              void* d_out, int out_size){
    const float* x1    = (const float*)d_in[0];
    const float* x2    = (const float*)d_in[1];
    const float* W1    = (const float*)d_in[2];
    const float* g1    = (const float*)d_in[3];
    const float* b1    = (const float*)d_in[4];
    const float* W2    = (const float*)d_in[5];
    const float* g2    = (const float*)d_in[6];
    const float* b2    = (const float*)d_in[7];
    const float* W3    = (const float*)d_in[8];
    const float* g3    = (const float*)d_in[9];
    const float* b3    = (const float*)d_in[10];
    const float* rw    = (const float*)d_in[11];
    const float* rb    = (const float*)d_in[12];
    const float* rg    = (const float*)d_in[13];
    const float* rbeta = (const float*)d_in[14];
    float* out = (float*)d_out;

    float *bufA, *bufB, *bufX, *bufY, *bufZ, *s2, *t2, *sP, *tP, *sC, *tC;
    cudaGetSymbolAddress((void**)&bufA, g_bufA);
    cudaGetSymbolAddress((void**)&bufB, g_bufB);
    cudaGetSymbolAddress((void**)&bufX, g_bufX);
    cudaGetSymbolAddress((void**)&bufY, g_bufY);
    cudaGetSymbolAddress((void**)&bufZ, g_bufZ);
    cudaGetSymbolAddress((void**)&s2, g_s2);
    cudaGetSymbolAddress((void**)&t2, g_t2);
    cudaGetSymbolAddress((void**)&sP, g_sP);
    cudaGetSymbolAddress((void**)&tP, g_tP);
    cudaGetSymbolAddress((void**)&sC, g_sC);
    cudaGetSymbolAddress((void**)&tC, g_tC);

    cudaFuncSetAttribute(k_conv<1,1>, cudaFuncAttributeMaxDynamicSharedMemorySize, CONV_SMEM);
    cudaFuncSetAttribute(k_conv<1,2>, cudaFuncAttributeMaxDynamicSharedMemorySize, CONV_SMEM);
    cudaFuncSetAttribute(k_conv<1,3>, cudaFuncAttributeMaxDynamicSharedMemorySize, CONV_SMEM);
    cudaFuncSetAttribute(k_conv<2,1>, cudaFuncAttributeMaxDynamicSharedMemorySize, CONV_SMEM);
    cudaFuncSetAttribute(k_conv<2,3>, cudaFuncAttributeMaxDynamicSharedMemorySize, CONV_SMEM);
    cudaFuncSetAttribute(k_conv<4,1>, cudaFuncAttributeMaxDynamicSharedMemorySize, CONV_SMEM);
    cudaFuncSetAttribute(k_conv<4,3>, cudaFuncAttributeMaxDynamicSharedMemorySize, CONV_SMEM);
    cudaFuncSetAttribute(k_gemm<0>,   cudaFuncAttributeMaxDynamicSharedMemorySize, GEMM_SMEM);
    cudaFuncSetAttribute(k_gemm<1>,   cudaFuncAttributeMaxDynamicSharedMemorySize, GEMM_SMEM);

    const double invN = 1.0 / (double)NPIX;

    k_reset  <<<1, 128>>>();
    k_stats1d<<<D1, 128>>>(x1);
    k_stats2d<<<D2, 256>>>(x2);
    k_aprep  <<<2880, 256>>>(rw);
    k_aprep2 <<<112, 256>>>(W2);
    k_aprep3 <<<64, 256>>>(W3);
    k_rowcol <<<CH, LDIM>>>(x1, W1);
    k_pair1  <<<CH, LDIM>>>(g1, b1);
    k_gemm<0><<<1152, 256, GEMM_SMEM>>>(x2, bufB);
    k_finalize<<<1, 64>>>(g2, b2, s2, t2, invN);
    k_gemm<1><<<1152, 256, GEMM_SMEM>>>(bufB, bufA);
    k_finalize<<<1, 64>>>(g3, b3, sP, tP, invN);

    // layer 0 (d=1): conv1 fuses pair transform + writes X0 to bufX
    k_conv<1,2><<<1152, 256, CONV_SMEM>>>(bufA, 0*3*ATILE, rb + 0*64, sP, tP, nullptr, bufX, bufY);
    k_finalize<<<1, 64>>>(rg + 0*64, rbeta + 0*64, sC, tC, invN);
    k_conv<1,1><<<1152, 256, CONV_SMEM>>>(bufY, 1*3*ATILE, rb + 1*64, sC, tC, nullptr, nullptr, bufB);
    k_finalize<<<1, 64>>>(rg + 1*64, rbeta + 1*64, sC, tC, invN);

    // layer 1 (d=2): conv1 fuses layer-0 ew (X1 = leaky(bufB*s+t)+X0 -> bufZ)
    k_conv<2,3><<<1152, 256, CONV_SMEM>>>(bufB, 2*3*ATILE, rb + 2*64, sC, tC, bufX, bufZ, bufY);
    k_finalize<<<1, 64>>>(rg + 2*64, rbeta + 2*64, sC, tC, invN);
    k_conv<2,1><<<1152, 256, CONV_SMEM>>>(bufY, 3*3*ATILE, rb + 3*64, sC, tC, nullptr, nullptr, bufB);
    k_finalize<<<1, 64>>>(rg + 3*64, rbeta + 3*64, sC, tC, invN);

    // layer 2 (d=4): X2 -> bufX
    k_conv<4,3><<<1152, 256, CONV_SMEM>>>(bufB, 4*3*ATILE, rb + 4*64, sC, tC, bufZ, bufX, bufY);
    k_finalize<<<1, 64>>>(rg + 4*64, rbeta + 4*64, sC, tC, invN);
    k_conv<4,1><<<1152, 256, CONV_SMEM>>>(bufY, 5*3*ATILE, rb + 5*64, sC, tC, nullptr, nullptr, bufB);
    k_finalize<<<1, 64>>>(rg + 5*64, rbeta + 5*64, sC, tC, invN);

    // layer 3 (d=2): X3 -> bufZ
    k_conv<2,3><<<1152, 256, CONV_SMEM>>>(bufB, 6*3*ATILE, rb + 6*64, sC, tC, bufX, bufZ, bufY);
    k_finalize<<<1, 64>>>(rg + 6*64, rbeta + 6*64, sC, tC, invN);
    k_conv<2,1><<<1152, 256, CONV_SMEM>>>(bufY, 7*3*ATILE, rb + 7*64, sC, tC, nullptr, nullptr, bufB);
    k_finalize<<<1, 64>>>(rg + 7*64, rbeta + 7*64, sC, tC, invN);

    // layer 4 (d=1): X4 -> bufX
    k_conv<1,3><<<1152, 256, CONV_SMEM>>>(bufB, 8*3*ATILE, rb + 8*64, sC, tC, bufZ, bufX, bufY);
    k_finalize<<<1, 64>>>(rg + 8*64, rbeta + 8*64, sC, tC, invN);
    k_conv<1,1><<<1152, 256, CONV_SMEM>>>(bufY, 9*3*ATILE, rb + 9*64, sC, tC, nullptr, nullptr, bufB);
    k_finalize<<<1, 64>>>(rg + 9*64, rbeta + 9*64, sC, tC, invN);

    k_ew<<<9216, 256>>>(bufB, sC, tC, bufX, out);
}